// round 2
// baseline (speedup 1.0000x reference)
#include <cuda_runtime.h>

#define B_   32768
#define FEAT 4096
#define XLD  4097
#define HID  2048
#define PROJ 512
#define NOUT 3

#define BM 128
#define BN 128
#define BK 16
#define TILES_M (B_/BM + 2)

// ---------------- scratch (device globals, no allocation) ----------------
__device__ int   g_cnt[2];
__device__ int   g_cnt2[2];
__device__ int   g_base_oth;
__device__ int   g_pos2row[B_ + 256];
__device__ float g_H[(size_t)(B_ + 256) * HID];   // hidden activations (permuted rows)
__device__ float g_Z[(size_t)B_ * PROJ];          // z in ORIGINAL row order

// ---------------- setup kernels: partition rows by flag ----------------
__global__ void k_zero() { g_cnt[0] = 0; g_cnt[1] = 0; }

__global__ void k_count(const float* __restrict__ x) {
    int r = blockIdx.x * blockDim.x + threadIdx.x;
    if (r < B_) {
        int g = (x[(size_t)r * XLD + FEAT] > 0.5f) ? 0 : 1;
        atomicAdd(&g_cnt[g], 1);
    }
}

__global__ void k_mid() {
    g_base_oth = ((g_cnt[0] + BM - 1) / BM) * BM;
    g_cnt2[0] = 0; g_cnt2[1] = 0;
}

__global__ void k_assign(const float* __restrict__ x) {
    int r = blockIdx.x * blockDim.x + threadIdx.x;
    if (r < B_) {
        int g = (x[(size_t)r * XLD + FEAT] > 0.5f) ? 0 : 1;
        int idx = atomicAdd(&g_cnt2[g], 1);
        int pos = g ? (g_base_oth + idx) : idx;
        g_pos2row[pos] = r;
    }
}

// ---------------- GEMM1: H = relu(gather(feat) @ W1_sel + b1_sel) ----------------
// A: x rows gathered by permutation (stride 4097, scalar loads — odd stride breaks float4)
// C: g_H, permuted-position indexed
__global__ __launch_bounds__(256) void gemm1_kernel(
    const float* __restrict__ x,
    const float* __restrict__ W1n, const float* __restrict__ b1n,
    const float* __restrict__ W1o, const float* __restrict__ b1o)
{
    __shared__ float As[2][BK][BM];
    __shared__ float Bs[2][BK][BN];

    const int n_nat = g_cnt[0];
    const int n_oth = g_cnt[1];
    const int nat_tiles = (n_nat + BM - 1) / BM;
    const int bm = blockIdx.x;
    const int bn = blockIdx.y;

    int grp, prow0, nrows;
    if (bm < nat_tiles) {
        grp = 0; prow0 = bm * BM; nrows = min(BM, n_nat - prow0);
    } else {
        int bm2 = bm - nat_tiles;
        if (bm2 * BM >= n_oth) return;
        grp = 1; prow0 = nat_tiles * BM + bm2 * BM;
        nrows = min(BM, n_oth - bm2 * BM);
    }
    const float* __restrict__ W    = grp ? W1o : W1n;
    const float* __restrict__ bias = grp ? b1o : b1n;

    const int t    = threadIdx.x;
    const int arow = t >> 1;
    const int ak0  = (t & 1) * 8;
    const float* aptr = nullptr;
    if (arow < nrows) {
        int orig = g_pos2row[prow0 + arow];
        aptr = x + (size_t)orig * XLD;
    }
    const int bk_a = t >> 5;            // 0..7
    const int bn4  = (t & 31) * 4;      // 0..124
    const float* __restrict__ Wb = W + bn * BN + bn4;

    const int tm = (t >> 4) * 8;
    const int tn = (t & 15) * 8;

    float acc[8][8];
    #pragma unroll
    for (int i = 0; i < 8; i++)
        #pragma unroll
        for (int j = 0; j < 8; j++) acc[i][j] = 0.f;

    // prologue: tile kt=0 -> buf 0
    {
        #pragma unroll
        for (int j = 0; j < 8; j++)
            As[0][ak0 + j][arow] = aptr ? aptr[ak0 + j] : 0.f;
        float4 v0 = *(const float4*)(Wb + (size_t)bk_a * HID);
        float4 v1 = *(const float4*)(Wb + (size_t)(bk_a + 8) * HID);
        *(float4*)&Bs[0][bk_a][bn4]     = v0;
        *(float4*)&Bs[0][bk_a + 8][bn4] = v1;
    }
    __syncthreads();

    for (int kt = 0; kt < FEAT; kt += BK) {
        const int buf = (kt / BK) & 1;
        const bool more = (kt + BK < FEAT);

        // prefetch next tile into registers (hide LDG behind compute)
        float  ra[8];
        float4 rb0, rb1;
        if (more) {
            const int k2 = kt + BK;
            #pragma unroll
            for (int j = 0; j < 8; j++)
                ra[j] = aptr ? aptr[k2 + ak0 + j] : 0.f;
            rb0 = *(const float4*)(Wb + (size_t)(k2 + bk_a) * HID);
            rb1 = *(const float4*)(Wb + (size_t)(k2 + bk_a + 8) * HID);
        }

        #pragma unroll
        for (int kk = 0; kk < BK; kk++) {
            float4 a0 = *(const float4*)&As[buf][kk][tm];
            float4 a1 = *(const float4*)&As[buf][kk][tm + 4];
            float4 b0 = *(const float4*)&Bs[buf][kk][tn];
            float4 b1 = *(const float4*)&Bs[buf][kk][tn + 4];
            float a[8] = {a0.x,a0.y,a0.z,a0.w,a1.x,a1.y,a1.z,a1.w};
            float b[8] = {b0.x,b0.y,b0.z,b0.w,b1.x,b1.y,b1.z,b1.w};
            #pragma unroll
            for (int i = 0; i < 8; i++)
                #pragma unroll
                for (int j = 0; j < 8; j++)
                    acc[i][j] = fmaf(a[i], b[j], acc[i][j]);
        }

        if (more) {
            const int nb = buf ^ 1;
            #pragma unroll
            for (int j = 0; j < 8; j++)
                As[nb][ak0 + j][arow] = ra[j];
            *(float4*)&Bs[nb][bk_a][bn4]     = rb0;
            *(float4*)&Bs[nb][bk_a + 8][bn4] = rb1;
        }
        __syncthreads();
    }

    // epilogue: bias + relu -> g_H (permuted position)
    #pragma unroll
    for (int i = 0; i < 8; i++) {
        const int pr = tm + i;
        if (pr < nrows) {
            float* hrow = g_H + (size_t)(prow0 + pr) * HID + bn * BN + tn;
            #pragma unroll
            for (int j = 0; j < 8; j++) {
                float v = acc[i][j] + bias[bn * BN + tn + j];
                hrow[j] = fmaxf(v, 0.f);
            }
        }
    }
}

// ---------------- GEMM2: Z = H @ W2_sel + b2_sel (scatter to original rows) ----------------
__global__ __launch_bounds__(256) void gemm2_kernel(
    const float* __restrict__ W2n, const float* __restrict__ b2n,
    const float* __restrict__ W2o, const float* __restrict__ b2o)
{
    __shared__ float As[2][BK][BM];
    __shared__ float Bs[2][BK][BN];

    const int n_nat = g_cnt[0];
    const int n_oth = g_cnt[1];
    const int nat_tiles = (n_nat + BM - 1) / BM;
    const int bm = blockIdx.x;
    const int bn = blockIdx.y;

    int grp, prow0, nrows;
    if (bm < nat_tiles) {
        grp = 0; prow0 = bm * BM; nrows = min(BM, n_nat - prow0);
    } else {
        int bm2 = bm - nat_tiles;
        if (bm2 * BM >= n_oth) return;
        grp = 1; prow0 = nat_tiles * BM + bm2 * BM;
        nrows = min(BM, n_oth - bm2 * BM);
    }
    const float* __restrict__ W    = grp ? W2o : W2n;
    const float* __restrict__ bias = grp ? b2o : b2n;

    const int t    = threadIdx.x;
    const int arow = t >> 1;
    const int ak0  = (t & 1) * 8;
    const float* aptr = (arow < nrows) ? (g_H + (size_t)(prow0 + arow) * HID) : nullptr;

    const int bk_a = t >> 5;
    const int bn4  = (t & 31) * 4;
    const float* __restrict__ Wb = W + bn * BN + bn4;

    const int tm = (t >> 4) * 8;
    const int tn = (t & 15) * 8;

    float acc[8][8];
    #pragma unroll
    for (int i = 0; i < 8; i++)
        #pragma unroll
        for (int j = 0; j < 8; j++) acc[i][j] = 0.f;

    {
        float4 a0 = aptr ? *(const float4*)(aptr + ak0)     : make_float4(0,0,0,0);
        float4 a1 = aptr ? *(const float4*)(aptr + ak0 + 4) : make_float4(0,0,0,0);
        As[0][ak0+0][arow]=a0.x; As[0][ak0+1][arow]=a0.y; As[0][ak0+2][arow]=a0.z; As[0][ak0+3][arow]=a0.w;
        As[0][ak0+4][arow]=a1.x; As[0][ak0+5][arow]=a1.y; As[0][ak0+6][arow]=a1.z; As[0][ak0+7][arow]=a1.w;
        float4 v0 = *(const float4*)(Wb + (size_t)bk_a * PROJ);
        float4 v1 = *(const float4*)(Wb + (size_t)(bk_a + 8) * PROJ);
        *(float4*)&Bs[0][bk_a][bn4]     = v0;
        *(float4*)&Bs[0][bk_a + 8][bn4] = v1;
    }
    __syncthreads();

    for (int kt = 0; kt < HID; kt += BK) {
        const int buf = (kt / BK) & 1;
        const bool more = (kt + BK < HID);

        float4 pa0, pa1, rb0, rb1;
        if (more) {
            const int k2 = kt + BK;
            pa0 = aptr ? *(const float4*)(aptr + k2 + ak0)     : make_float4(0,0,0,0);
            pa1 = aptr ? *(const float4*)(aptr + k2 + ak0 + 4) : make_float4(0,0,0,0);
            rb0 = *(const float4*)(Wb + (size_t)(k2 + bk_a) * PROJ);
            rb1 = *(const float4*)(Wb + (size_t)(k2 + bk_a + 8) * PROJ);
        }

        #pragma unroll
        for (int kk = 0; kk < BK; kk++) {
            float4 a0 = *(const float4*)&As[buf][kk][tm];
            float4 a1 = *(const float4*)&As[buf][kk][tm + 4];
            float4 b0 = *(const float4*)&Bs[buf][kk][tn];
            float4 b1 = *(const float4*)&Bs[buf][kk][tn + 4];
            float a[8] = {a0.x,a0.y,a0.z,a0.w,a1.x,a1.y,a1.z,a1.w};
            float b[8] = {b0.x,b0.y,b0.z,b0.w,b1.x,b1.y,b1.z,b1.w};
            #pragma unroll
            for (int i = 0; i < 8; i++)
                #pragma unroll
                for (int j = 0; j < 8; j++)
                    acc[i][j] = fmaf(a[i], b[j], acc[i][j]);
        }

        if (more) {
            const int nb = buf ^ 1;
            As[nb][ak0+0][arow]=pa0.x; As[nb][ak0+1][arow]=pa0.y; As[nb][ak0+2][arow]=pa0.z; As[nb][ak0+3][arow]=pa0.w;
            As[nb][ak0+4][arow]=pa1.x; As[nb][ak0+5][arow]=pa1.y; As[nb][ak0+6][arow]=pa1.z; As[nb][ak0+7][arow]=pa1.w;
            *(float4*)&Bs[nb][bk_a][bn4]     = rb0;
            *(float4*)&Bs[nb][bk_a + 8][bn4] = rb1;
        }
        __syncthreads();
    }

    // epilogue: + bias, scatter to original row order (no relu; z is raw)
    #pragma unroll
    for (int i = 0; i < 8; i++) {
        const int pr = tm + i;
        if (pr < nrows) {
            const int orig = g_pos2row[prow0 + pr];
            float* zrow = g_Z + (size_t)orig * PROJ + bn * BN + tn;
            #pragma unroll
            for (int j = 0; j < 8; j++)
                zrow[j] = acc[i][j] + bias[bn * BN + tn + j];
        }
    }
}

// ---------------- finalize: norm, z_normalized, logits ----------------
__global__ __launch_bounds__(128) void k_final(
    const float* __restrict__ x,
    const float* __restrict__ Wcn, const float* __restrict__ bcn,
    const float* __restrict__ Wco, const float* __restrict__ bco,
    float* __restrict__ out)
{
    const int row = blockIdx.x;
    const bool nat = x[(size_t)row * XLD + FEAT] > 0.5f;
    const float* __restrict__ Wc = nat ? Wcn : Wco;
    const float* __restrict__ bc = nat ? bcn : bco;

    const int t = threadIdx.x;
    const float* zr = g_Z + (size_t)row * PROJ;

    float zv[4];
    float ss = 0.f, l0 = 0.f, l1 = 0.f, l2 = 0.f;
    #pragma unroll
    for (int i = 0; i < 4; i++) {
        const int k = t + i * 128;
        const float z = zr[k];
        zv[i] = z;
        ss = fmaf(z, z, ss);
        const float rz = fmaxf(z, 0.f);
        l0 = fmaf(rz, Wc[k * 3 + 0], l0);
        l1 = fmaf(rz, Wc[k * 3 + 1], l1);
        l2 = fmaf(rz, Wc[k * 3 + 2], l2);
    }
    #pragma unroll
    for (int o = 16; o > 0; o >>= 1) {
        ss += __shfl_down_sync(0xFFFFFFFFu, ss, o);
        l0 += __shfl_down_sync(0xFFFFFFFFu, l0, o);
        l1 += __shfl_down_sync(0xFFFFFFFFu, l1, o);
        l2 += __shfl_down_sync(0xFFFFFFFFu, l2, o);
    }
    __shared__ float red[4][4];
    __shared__ float inv_s;
    const int w = t >> 5, lane = t & 31;
    if (lane == 0) { red[w][0] = ss; red[w][1] = l0; red[w][2] = l1; red[w][3] = l2; }
    __syncthreads();
    if (t == 0) {
        float S  = red[0][0] + red[1][0] + red[2][0] + red[3][0];
        float L0 = red[0][1] + red[1][1] + red[2][1] + red[3][1];
        float L1 = red[0][2] + red[1][2] + red[2][2] + red[3][2];
        float L2 = red[0][3] + red[1][3] + red[2][3] + red[3][3];
        float norm = sqrtf(S);
        inv_s = 1.f / fmaxf(norm, 1e-12f);
        float* lg = out + (size_t)B_ * PROJ + (size_t)row * NOUT;
        lg[0] = L0 + bc[0];
        lg[1] = L1 + bc[1];
        lg[2] = L2 + bc[2];
    }
    __syncthreads();
    const float inv = inv_s;
    #pragma unroll
    for (int i = 0; i < 4; i++)
        out[(size_t)row * PROJ + t + i * 128] = zv[i] * inv;
}

// ---------------- launcher ----------------
extern "C" void kernel_launch(void* const* d_in, const int* in_sizes, int n_in,
                              void* d_out, int out_size) {
    const float* x   = (const float*)d_in[0];
    const float* W1n = (const float*)d_in[1];
    const float* b1n = (const float*)d_in[2];
    const float* W2n = (const float*)d_in[3];
    const float* b2n = (const float*)d_in[4];
    const float* Wcn = (const float*)d_in[5];
    const float* bcn = (const float*)d_in[6];
    const float* W1o = (const float*)d_in[7];
    const float* b1o = (const float*)d_in[8];
    const float* W2o = (const float*)d_in[9];
    const float* b2o = (const float*)d_in[10];
    const float* Wco = (const float*)d_in[11];
    const float* bco = (const float*)d_in[12];
    float* out = (float*)d_out;

    k_zero<<<1, 1>>>();
    k_count<<<B_ / 256, 256>>>(x);
    k_mid<<<1, 1>>>();
    k_assign<<<B_ / 256, 256>>>(x);

    dim3 g1(TILES_M, HID / BN);
    gemm1_kernel<<<g1, 256>>>(x, W1n, b1n, W1o, b1o);

    dim3 g2(TILES_M, PROJ / BN);
    gemm2_kernel<<<g2, 256>>>(W2n, b2n, W2o, b2o);

    k_final<<<B_, 128>>>(x, Wcn, bcn, Wco, bco, out);
}

// round 4
// speedup vs baseline: 3.4282x; 3.4282x over previous
#include <cuda_runtime.h>
#include <cuda_bf16.h>
#include <cstdint>

#define B_   32768
#define FEAT 4096
#define XLD  4097
#define HID  2048
#define PROJ 512
#define NOUT 3
#define APAD (B_ + 256)
#define TILES_M 258
#define STG 98304           // per-stage: Ah 16K + Al 16K + Wh 32K + Wl 32K

// ---------- device scratch ----------
__device__ int g_cnt[2];
__device__ int g_cnt2[2];
__device__ int g_pos2row[APAD];
__device__ float g_Z[(size_t)B_ * PROJ];
__device__ __nv_bfloat16 g_Ah[(size_t)APAD * FEAT];
__device__ __nv_bfloat16 g_Al[(size_t)APAD * FEAT];
__device__ __nv_bfloat16 g_Hh[(size_t)APAD * HID];
__device__ __nv_bfloat16 g_Hl[(size_t)APAD * HID];
__device__ __nv_bfloat16 g_W1h[(size_t)2 * 16 * 64 * 8192];
__device__ __nv_bfloat16 g_W1l[(size_t)2 * 16 * 64 * 8192];
__device__ __nv_bfloat16 g_W2h[(size_t)2 * 4 * 32 * 8192];
__device__ __nv_bfloat16 g_W2l[(size_t)2 * 4 * 32 * 8192];

// ---------- helpers ----------
__device__ __forceinline__ uint32_t smem_u32(const void* p) {
    uint32_t a;
    asm("{ .reg .u64 t; cvta.to.shared.u64 t, %1; cvt.u32.u64 %0, t; }" : "=r"(a) : "l"(p));
    return a;
}
__device__ __forceinline__ void split2(float v0, float v1, uint32_t& hi, uint32_t& lo) {
    __nv_bfloat16 h0 = __float2bfloat16_rn(v0);
    __nv_bfloat16 h1 = __float2bfloat16_rn(v1);
    __nv_bfloat16 l0 = __float2bfloat16_rn(v0 - __bfloat162float(h0));
    __nv_bfloat16 l1 = __float2bfloat16_rn(v1 - __bfloat162float(h1));
    __nv_bfloat162 hp = __halves2bfloat162(h0, h1);
    __nv_bfloat162 lp = __halves2bfloat162(l0, l1);
    hi = *reinterpret_cast<uint32_t*>(&hp);
    lo = *reinterpret_cast<uint32_t*>(&lp);
}
__device__ __forceinline__ void cpa16(uint32_t d, const void* s) {
    asm volatile("cp.async.cg.shared.global [%0], [%1], 16;" :: "r"(d), "l"(s));
}
#define CPCOMMIT() asm volatile("cp.async.commit_group;" ::: "memory")
#define CPWAIT0()  asm volatile("cp.async.wait_group 0;" ::: "memory")
#define CPWAIT1()  asm volatile("cp.async.wait_group 1;" ::: "memory")
__device__ __forceinline__ void ldsm4(uint32_t* r, uint32_t a) {
    asm volatile("ldmatrix.sync.aligned.m8n8.x4.shared.b16 {%0,%1,%2,%3}, [%4];"
                 : "=r"(r[0]), "=r"(r[1]), "=r"(r[2]), "=r"(r[3]) : "r"(a));
}
__device__ __forceinline__ void mma16816(float* c, const uint32_t* a, const uint32_t* b) {
    asm volatile("mma.sync.aligned.m16n8k16.row.col.f32.bf16.bf16.f32 "
                 "{%0,%1,%2,%3}, {%4,%5,%6,%7}, {%8,%9}, {%0,%1,%2,%3};"
                 : "+f"(c[0]), "+f"(c[1]), "+f"(c[2]), "+f"(c[3])
                 : "r"(a[0]), "r"(a[1]), "r"(a[2]), "r"(a[3]), "r"(b[0]), "r"(b[1]));
}

// ---------- partition ----------
__global__ void k_zero() { g_cnt[0]=0; g_cnt[1]=0; g_cnt2[0]=0; g_cnt2[1]=0; }
__global__ void k_count(const float* __restrict__ x) {
    int r = blockIdx.x * blockDim.x + threadIdx.x;
    if (r < B_) atomicAdd(&g_cnt[(x[(size_t)r*XLD+FEAT] > 0.5f) ? 0 : 1], 1);
}
__global__ void k_assign(const float* __restrict__ x) {
    int r = blockIdx.x * blockDim.x + threadIdx.x;
    if (r < B_) {
        int g = (x[(size_t)r*XLD+FEAT] > 0.5f) ? 0 : 1;
        int idx = atomicAdd(&g_cnt2[g], 1);
        int base_oth = ((g_cnt[0] + 127) >> 7) << 7;
        g_pos2row[g ? (base_oth + idx) : idx] = r;
    }
}

// ---------- A pre-split: gather + fp32 -> bf16 hi/lo, permuted row order ----------
__global__ __launch_bounds__(256) void k_splitA(const float* __restrict__ x) {
    int pos = blockIdx.x;
    int natPad = ((g_cnt[0] + 127) & ~127);
    bool valid = (pos < natPad) ? (pos < g_cnt[0]) : ((pos - natPad) < g_cnt[1]);
    int t = threadIdx.x;
    size_t db = ((size_t)pos * FEAT + t * 16) * 2;   // byte offset
    uint4 h[2] = {{0,0,0,0},{0,0,0,0}}, l[2] = {{0,0,0,0},{0,0,0,0}};
    if (valid) {
        int orig = g_pos2row[pos];
        const float* src = x + (size_t)orig * XLD + t * 16;
        #pragma unroll
        for (int q = 0; q < 2; q++) {
            uint32_t* hp = (uint32_t*)&h[q];
            uint32_t* lp = (uint32_t*)&l[q];
            #pragma unroll
            for (int e = 0; e < 4; e++)
                split2(__ldg(src + q*8 + 2*e), __ldg(src + q*8 + 2*e + 1), hp[e], lp[e]);
        }
    }
    *(uint4*)((char*)g_Ah + db)      = h[0];
    *(uint4*)((char*)g_Ah + db + 16) = h[1];
    *(uint4*)((char*)g_Al + db)      = l[0];
    *(uint4*)((char*)g_Al + db + 16) = l[1];
}

// ---------- weight prepack: fp32 [K][N] -> bf16 hi/lo, [N][K] tile-linear SW128 ----------
__global__ __launch_bounds__(256) void prep_w1(const float* __restrict__ Wn, const float* __restrict__ Wo) {
    int tid = blockIdx.x * 256 + threadIdx.x;      // 2*512*2048
    int n = tid & 2047, rest = tid >> 11;
    int ko = rest & 511, g = rest >> 9;
    const float* src = g ? Wo : Wn;
    uint4 hv, lv;
    uint32_t* hp = (uint32_t*)&hv; uint32_t* lp = (uint32_t*)&lv;
    #pragma unroll
    for (int e = 0; e < 4; e++)
        split2(__ldg(src + (size_t)(ko*8 + 2*e) * HID + n),
               __ldg(src + (size_t)(ko*8 + 2*e + 1) * HID + n), hp[e], lp[e]);
    int nt = n >> 7, rIn = n & 127, kt = ko >> 3, cb = ko & 7;
    size_t tb = ((size_t)(((g << 4) + nt) * 64 + kt)) << 14;
    uint32_t sw = (uint32_t)(rIn * 128 + (cb << 4)) ^ ((uint32_t)(rIn & 7) << 4);
    *(uint4*)((char*)g_W1h + tb + sw) = hv;
    *(uint4*)((char*)g_W1l + tb + sw) = lv;
}
__global__ __launch_bounds__(256) void prep_w2(const float* __restrict__ Wn, const float* __restrict__ Wo) {
    int tid = blockIdx.x * 256 + threadIdx.x;      // 2*256*512
    int n = tid & 511, rest = tid >> 9;
    int ko = rest & 255, g = rest >> 8;
    const float* src = g ? Wo : Wn;
    uint4 hv, lv;
    uint32_t* hp = (uint32_t*)&hv; uint32_t* lp = (uint32_t*)&lv;
    #pragma unroll
    for (int e = 0; e < 4; e++)
        split2(__ldg(src + (size_t)(ko*8 + 2*e) * PROJ + n),
               __ldg(src + (size_t)(ko*8 + 2*e + 1) * PROJ + n), hp[e], lp[e]);
    int nt = n >> 7, rIn = n & 127, kt = ko >> 3, cb = ko & 7;
    size_t tb = ((size_t)(((g << 2) + nt) * 32 + kt)) << 14;
    uint32_t sw = (uint32_t)(rIn * 128 + (cb << 4)) ^ ((uint32_t)(rIn & 7) << 4);
    *(uint4*)((char*)g_W2h + tb + sw) = hv;
    *(uint4*)((char*)g_W2l + tb + sw) = lv;
}

// ---------- GEMM via mma.sync: M128 x N256 CTA, K-step 64, bf16 3-term split ----------
template <int IS_G1>
__global__ __launch_bounds__(256, 1) void gemm_mma(
    const float* __restrict__ bn_, const float* __restrict__ bo_)
{
    extern __shared__ char smc[];
    __shared__ float biasS[256];
    __shared__ int rowS[128];

    const int NTB = IS_G1 ? 16 : 4;
    const int KTB = IS_G1 ? 64 : 32;
    const int NIT = IS_G1 ? (FEAT/64) : (HID/64);
    const int n_nat = g_cnt[0], n_oth = g_cnt[1];
    const int nat_tiles = (n_nat + 127) >> 7;
    const int bm = blockIdx.y, bnb = blockIdx.x;
    int grp, prow0, nrows;
    if (bm < nat_tiles) { grp = 0; prow0 = bm << 7; nrows = min(128, n_nat - prow0); }
    else {
        int bm2 = bm - nat_tiles;
        if ((bm2 << 7) >= n_oth) return;
        grp = 1; prow0 = (nat_tiles + bm2) << 7; nrows = min(128, n_oth - (bm2 << 7));
    }
    const int t = threadIdx.x;
    biasS[t] = (grp ? bo_ : bn_)[(bnb << 8) + t];
    if (t < 128) rowS[t] = (t < nrows) ? g_pos2row[prow0 + t] : -1;
    __syncthreads();

    const uint32_t sb = smem_u32(smc);
    const char* Asrc_h = (const char*)(IS_G1 ? g_Ah : g_Hh);
    const char* Asrc_l = (const char*)(IS_G1 ? g_Al : g_Hl);
    const size_t rowE  = IS_G1 ? FEAT : HID;
    const char* Wsrc_h = (const char*)(IS_G1 ? g_W1h : g_W2h);
    const char* Wsrc_l = (const char*)(IS_G1 ? g_W1l : g_W2l);

    auto issue = [&](int s, int it) {
        uint32_t base = sb + s * STG;
        #pragma unroll
        for (int i = 0; i < 4; i++) {
            int cid = i * 256 + t;
            int r = cid >> 3, c = cid & 7;
            uint32_t off = (uint32_t)((r * 128 + c * 16) ^ ((r & 7) << 4));
            size_t so = ((size_t)(prow0 + r) * rowE + it * 64 + c * 8) * 2;
            cpa16(base + off,         Asrc_h + so);
            cpa16(base + 16384 + off, Asrc_l + so);
        }
        size_t tb0 = ((size_t)((grp * NTB + bnb * 2 + 0) * KTB + it)) << 14;
        size_t tb1 = ((size_t)((grp * NTB + bnb * 2 + 1) * KTB + it)) << 14;
        #pragma unroll
        for (int i = 0; i < 16; i++) {
            int cid = i * 256 + t;
            int ti = cid >> 10, j = cid & 1023;
            const char* sp = (ti >= 2 ? Wsrc_l : Wsrc_h) + ((ti & 1) ? tb1 : tb0) + (size_t)j * 16;
            cpa16(base + 32768 + ti * 16384 + j * 16, sp);
        }
    };

    // frag addressing
    const int w = t >> 5, lane = t & 31;
    const int wm = w >> 2, wn = w & 3;
    const int lr = lane & 7, gq = lane >> 3;
    int preA[4], rxA[4], preB[4], rxB[4];
    #pragma unroll
    for (int mf = 0; mf < 4; mf++) {
        int row = wm * 64 + mf * 16 + (gq & 1) * 8 + lr;
        preA[mf] = row * 128 + (gq >> 1) * 16;
        rxA[mf]  = (row & 7) << 4;
    }
    #pragma unroll
    for (int p = 0; p < 4; p++) {
        int n = wn * 64 + p * 16 + (gq >> 1) * 8 + lr;
        preB[p] = ((n >> 7) << 14) + (n & 127) * 128 + (gq & 1) * 16;
        rxB[p]  = (n & 7) << 4;
    }

    float acc[4][8][4];
    #pragma unroll
    for (int i = 0; i < 4; i++)
        #pragma unroll
        for (int j = 0; j < 8; j++)
            #pragma unroll
            for (int e = 0; e < 4; e++) acc[i][j][e] = 0.f;

    issue(0, 0); CPCOMMIT();
    for (int it = 0; it < NIT; it++) {
        int b = it & 1;
        if (it + 1 < NIT) { issue(b ^ 1, it + 1); CPCOMMIT(); CPWAIT1(); }
        else              { CPWAIT0(); }
        __syncthreads();
        uint32_t sAh = sb + b * STG, sAl = sAh + 16384, sWh = sAh + 32768, sWl = sAh + 65536;
        #pragma unroll
        for (int k16 = 0; k16 < 4; k16++) {
            int kb = k16 * 32;
            uint32_t a[4][4], a2[4][4], bb[8][2];
            #pragma unroll
            for (int mf = 0; mf < 4; mf++) ldsm4(a[mf], sAh + (uint32_t)((preA[mf] + kb) ^ rxA[mf]));
            #pragma unroll
            for (int p = 0; p < 4; p++) {
                uint32_t r[4];
                ldsm4(r, sWh + (uint32_t)((preB[p] + kb) ^ rxB[p]));
                bb[2*p][0]=r[0]; bb[2*p][1]=r[1]; bb[2*p+1][0]=r[2]; bb[2*p+1][1]=r[3];
            }
            #pragma unroll
            for (int mf = 0; mf < 4; mf++)
                #pragma unroll
                for (int nf = 0; nf < 8; nf++) mma16816(acc[mf][nf], a[mf], bb[nf]);
            #pragma unroll
            for (int mf = 0; mf < 4; mf++) ldsm4(a2[mf], sAl + (uint32_t)((preA[mf] + kb) ^ rxA[mf]));
            #pragma unroll
            for (int mf = 0; mf < 4; mf++)
                #pragma unroll
                for (int nf = 0; nf < 8; nf++) mma16816(acc[mf][nf], a2[mf], bb[nf]);
            #pragma unroll
            for (int p = 0; p < 4; p++) {
                uint32_t r[4];
                ldsm4(r, sWl + (uint32_t)((preB[p] + kb) ^ rxB[p]));
                bb[2*p][0]=r[0]; bb[2*p][1]=r[1]; bb[2*p+1][0]=r[2]; bb[2*p+1][1]=r[3];
            }
            #pragma unroll
            for (int mf = 0; mf < 4; mf++)
                #pragma unroll
                for (int nf = 0; nf < 8; nf++) mma16816(acc[mf][nf], a[mf], bb[nf]);
        }
        __syncthreads();
    }

    // epilogue
    #pragma unroll
    for (int mf = 0; mf < 4; mf++) {
        #pragma unroll
        for (int half = 0; half < 2; half++) {
            int row = wm * 64 + mf * 16 + (lane >> 2) + half * 8;
            if (IS_G1) {
                size_t base = (size_t)(prow0 + row) * HID + (bnb << 8);
                #pragma unroll
                for (int nf = 0; nf < 8; nf++) {
                    int n = wn * 64 + nf * 8 + (lane & 3) * 2;
                    float v0 = fmaxf(acc[mf][nf][half*2+0] + biasS[n],     0.f);
                    float v1 = fmaxf(acc[mf][nf][half*2+1] + biasS[n + 1], 0.f);
                    uint32_t uh, ul;
                    split2(v0, v1, uh, ul);
                    *(uint32_t*)((char*)g_Hh + (base + n) * 2) = uh;
                    *(uint32_t*)((char*)g_Hl + (base + n) * 2) = ul;
                }
            } else {
                int orig = rowS[row];
                if (orig >= 0) {
                    float* zp = g_Z + (size_t)orig * PROJ + (bnb << 8);
                    #pragma unroll
                    for (int nf = 0; nf < 8; nf++) {
                        int n = wn * 64 + nf * 8 + (lane & 3) * 2;
                        float2 v;
                        v.x = acc[mf][nf][half*2+0] + biasS[n];
                        v.y = acc[mf][nf][half*2+1] + biasS[n + 1];
                        *(float2*)(zp + n) = v;
                    }
                }
            }
        }
    }
}

// ---------- finalize: norm, z_normalized, logits ----------
__global__ __launch_bounds__(128) void k_final(
    const float* __restrict__ x,
    const float* __restrict__ Wcn, const float* __restrict__ bcn,
    const float* __restrict__ Wco, const float* __restrict__ bco,
    float* __restrict__ out)
{
    const int row = blockIdx.x;
    const bool nat = x[(size_t)row * XLD + FEAT] > 0.5f;
    const float* __restrict__ Wc = nat ? Wcn : Wco;
    const float* __restrict__ bc = nat ? bcn : bco;
    const int t = threadIdx.x;
    const float* zr = g_Z + (size_t)row * PROJ;

    float zv[4];
    float ss = 0.f, l0 = 0.f, l1 = 0.f, l2 = 0.f;
    #pragma unroll
    for (int i = 0; i < 4; i++) {
        const int k = t + i * 128;
        const float z = zr[k];
        zv[i] = z;
        ss = fmaf(z, z, ss);
        const float rz = fmaxf(z, 0.f);
        l0 = fmaf(rz, Wc[k*3+0], l0);
        l1 = fmaf(rz, Wc[k*3+1], l1);
        l2 = fmaf(rz, Wc[k*3+2], l2);
    }
    #pragma unroll
    for (int o = 16; o > 0; o >>= 1) {
        ss += __shfl_down_sync(0xFFFFFFFFu, ss, o);
        l0 += __shfl_down_sync(0xFFFFFFFFu, l0, o);
        l1 += __shfl_down_sync(0xFFFFFFFFu, l1, o);
        l2 += __shfl_down_sync(0xFFFFFFFFu, l2, o);
    }
    __shared__ float red[4][4];
    __shared__ float inv_s;
    const int w = t >> 5, lane = t & 31;
    if (lane == 0) { red[w][0]=ss; red[w][1]=l0; red[w][2]=l1; red[w][3]=l2; }
    __syncthreads();
    if (t == 0) {
        float S  = red[0][0]+red[1][0]+red[2][0]+red[3][0];
        float L0 = red[0][1]+red[1][1]+red[2][1]+red[3][1];
        float L1 = red[0][2]+red[1][2]+red[2][2]+red[3][2];
        float L2 = red[0][3]+red[1][3]+red[2][3]+red[3][3];
        inv_s = 1.f / fmaxf(sqrtf(S), 1e-12f);
        float* lg = out + (size_t)B_ * PROJ + (size_t)row * NOUT;
        lg[0] = L0 + bc[0]; lg[1] = L1 + bc[1]; lg[2] = L2 + bc[2];
    }
    __syncthreads();
    const float inv = inv_s;
    #pragma unroll
    for (int i = 0; i < 4; i++)
        out[(size_t)row * PROJ + t + i * 128] = zv[i] * inv;
}

// ---------- launcher ----------
extern "C" void kernel_launch(void* const* d_in, const int* in_sizes, int n_in,
                              void* d_out, int out_size) {
    const float* x   = (const float*)d_in[0];
    const float* W1n = (const float*)d_in[1];
    const float* b1n = (const float*)d_in[2];
    const float* W2n = (const float*)d_in[3];
    const float* b2n = (const float*)d_in[4];
    const float* Wcn = (const float*)d_in[5];
    const float* bcn = (const float*)d_in[6];
    const float* W1o = (const float*)d_in[7];
    const float* b1o = (const float*)d_in[8];
    const float* W2o = (const float*)d_in[9];
    const float* b2o = (const float*)d_in[10];
    const float* Wco = (const float*)d_in[11];
    const float* bco = (const float*)d_in[12];
    float* out = (float*)d_out;

    cudaFuncSetAttribute(gemm_mma<1>, cudaFuncAttributeMaxDynamicSharedMemorySize, 2*STG);
    cudaFuncSetAttribute(gemm_mma<0>, cudaFuncAttributeMaxDynamicSharedMemorySize, 2*STG);

    k_zero<<<1, 1>>>();
    k_count<<<B_ / 256, 256>>>(x);
    k_assign<<<B_ / 256, 256>>>(x);
    k_splitA<<<APAD, 256>>>(x);
    prep_w1<<<8192, 256>>>(W1n, W1o);
    prep_w2<<<1024, 256>>>(W2n, W2o);

    gemm_mma<1><<<dim3(8, TILES_M), 256, 2*STG>>>(b1n, b1o);
    gemm_mma<0><<<dim3(2, TILES_M), 256, 2*STG>>>(b2n, b2o);

    k_final<<<B_, 128>>>(x, Wcn, bcn, Wco, bco, out);
}

// round 5
// speedup vs baseline: 4.7090x; 1.3736x over previous
#include <cuda_runtime.h>
#include <cuda_bf16.h>
#include <cuda_fp16.h>
#include <cstdint>

#define B_   32768
#define FEAT 4096
#define XLD  4097
#define HID  2048
#define PROJ 512
#define NOUT 3
#define APAD (B_ + 256)
#define TILES_M 258

// ---------- device scratch ----------
__device__ int g_cnt[2];
__device__ int g_cnt2[2];
__device__ int g_pos2row[APAD];
__device__ float g_Z[(size_t)B_ * PROJ];
__device__ __half g_Ah[(size_t)APAD * FEAT];           // fp16 hi limb of x features
__device__ __half g_Al[(size_t)APAD * FEAT];           // fp16 lo limb
__device__ __nv_bfloat16 g_Hh[(size_t)APAD * HID];     // H bf16 hi/lo (for 3-term GEMM2)
__device__ __nv_bfloat16 g_Hl[(size_t)APAD * HID];
__device__ __half        g_W1h[(size_t)2 * 16 * 64 * 8192];   // fp16 single limb
__device__ __nv_bfloat16 g_W2h[(size_t)2 * 4 * 32 * 8192];
__device__ __nv_bfloat16 g_W2l[(size_t)2 * 4 * 32 * 8192];

// ---------- helpers ----------
__device__ __forceinline__ uint32_t smem_u32(const void* p) {
    uint32_t a;
    asm("{ .reg .u64 t; cvta.to.shared.u64 t, %1; cvt.u32.u64 %0, t; }" : "=r"(a) : "l"(p));
    return a;
}
__device__ __forceinline__ void split2b(float v0, float v1, uint32_t& hi, uint32_t& lo) {
    __nv_bfloat16 h0 = __float2bfloat16_rn(v0);
    __nv_bfloat16 h1 = __float2bfloat16_rn(v1);
    __nv_bfloat16 l0 = __float2bfloat16_rn(v0 - __bfloat162float(h0));
    __nv_bfloat16 l1 = __float2bfloat16_rn(v1 - __bfloat162float(h1));
    __nv_bfloat162 hp = __halves2bfloat162(h0, h1);
    __nv_bfloat162 lp = __halves2bfloat162(l0, l1);
    hi = *reinterpret_cast<uint32_t*>(&hp);
    lo = *reinterpret_cast<uint32_t*>(&lp);
}
__device__ __forceinline__ void split2h(float v0, float v1, uint32_t& hi, uint32_t& lo) {
    __half h0 = __float2half_rn(v0);
    __half h1 = __float2half_rn(v1);
    __half l0 = __float2half_rn(v0 - __half2float(h0));
    __half l1 = __float2half_rn(v1 - __half2float(h1));
    __half2 hp = __halves2half2(h0, h1);
    __half2 lp = __halves2half2(l0, l1);
    hi = *reinterpret_cast<uint32_t*>(&hp);
    lo = *reinterpret_cast<uint32_t*>(&lp);
}
__device__ __forceinline__ void cpa16(uint32_t d, const void* s) {
    asm volatile("cp.async.cg.shared.global [%0], [%1], 16;" :: "r"(d), "l"(s));
}
#define CPCOMMIT() asm volatile("cp.async.commit_group;" ::: "memory")
#define CPWAIT0()  asm volatile("cp.async.wait_group 0;" ::: "memory")
#define CPWAIT1()  asm volatile("cp.async.wait_group 1;" ::: "memory")
__device__ __forceinline__ void ldsm4(uint32_t* r, uint32_t a) {
    asm volatile("ldmatrix.sync.aligned.m8n8.x4.shared.b16 {%0,%1,%2,%3}, [%4];"
                 : "=r"(r[0]), "=r"(r[1]), "=r"(r[2]), "=r"(r[3]) : "r"(a));
}
__device__ __forceinline__ void mma_bf(float* c, const uint32_t* a, const uint32_t* b) {
    asm volatile("mma.sync.aligned.m16n8k16.row.col.f32.bf16.bf16.f32 "
                 "{%0,%1,%2,%3}, {%4,%5,%6,%7}, {%8,%9}, {%0,%1,%2,%3};"
                 : "+f"(c[0]), "+f"(c[1]), "+f"(c[2]), "+f"(c[3])
                 : "r"(a[0]), "r"(a[1]), "r"(a[2]), "r"(a[3]), "r"(b[0]), "r"(b[1]));
}
__device__ __forceinline__ void mma_h(float* c, const uint32_t* a, const uint32_t* b) {
    asm volatile("mma.sync.aligned.m16n8k16.row.col.f32.f16.f16.f32 "
                 "{%0,%1,%2,%3}, {%4,%5,%6,%7}, {%8,%9}, {%0,%1,%2,%3};"
                 : "+f"(c[0]), "+f"(c[1]), "+f"(c[2]), "+f"(c[3])
                 : "r"(a[0]), "r"(a[1]), "r"(a[2]), "r"(a[3]), "r"(b[0]), "r"(b[1]));
}

// ---------- partition ----------
__global__ void k_zero() { g_cnt[0]=0; g_cnt[1]=0; g_cnt2[0]=0; g_cnt2[1]=0; }
__global__ void k_count(const float* __restrict__ x) {
    int r = blockIdx.x * blockDim.x + threadIdx.x;
    if (r < B_) atomicAdd(&g_cnt[(x[(size_t)r*XLD+FEAT] > 0.5f) ? 0 : 1], 1);
}
__global__ void k_assign(const float* __restrict__ x) {
    int r = blockIdx.x * blockDim.x + threadIdx.x;
    if (r < B_) {
        int g = (x[(size_t)r*XLD+FEAT] > 0.5f) ? 0 : 1;
        int idx = atomicAdd(&g_cnt2[g], 1);
        int base_oth = ((g_cnt[0] + 127) >> 7) << 7;
        g_pos2row[g ? (base_oth + idx) : idx] = r;
    }
}

// ---------- A pre-split: gather + fp32 -> fp16 hi/lo, permuted row order ----------
__global__ __launch_bounds__(256) void k_splitA(const float* __restrict__ x) {
    int pos = blockIdx.x;
    int natPad = ((g_cnt[0] + 127) & ~127);
    bool valid = (pos < natPad) ? (pos < g_cnt[0]) : ((pos - natPad) < g_cnt[1]);
    int t = threadIdx.x;
    size_t db = ((size_t)pos * FEAT + t * 16) * 2;
    uint4 h = {0,0,0,0}, l = {0,0,0,0};
    float v[16];
    if (valid) {
        int orig = g_pos2row[pos];
        const float* src = x + (size_t)orig * XLD + t * 16;
        if (!(orig & 1)) {
            #pragma unroll
            for (int q = 0; q < 8; q++) {
                float2 f = __ldg((const float2*)(src + q * 2));
                v[q*2] = f.x; v[q*2+1] = f.y;
            }
        } else {
            #pragma unroll
            for (int q = 0; q < 16; q++) v[q] = __ldg(src + q);
        }
        uint32_t* hp = (uint32_t*)&h;
        uint32_t* lp = (uint32_t*)&l;
        #pragma unroll
        for (int e = 0; e < 8; e++) {
            uint32_t uh, ul;
            split2h(v[2*e], v[2*e+1], uh, ul);
            if (e < 4) { hp[e] = uh; lp[e] = ul; }
            else {
                if (e == 4) { *(uint4*)((char*)g_Ah + db) = h; *(uint4*)((char*)g_Al + db) = l; }
                hp[e-4] = uh; lp[e-4] = ul;
            }
        }
        *(uint4*)((char*)g_Ah + db + 16) = h;
        *(uint4*)((char*)g_Al + db + 16) = l;
    } else {
        *(uint4*)((char*)g_Ah + db) = h;  *(uint4*)((char*)g_Ah + db + 16) = h;
        *(uint4*)((char*)g_Al + db) = l;  *(uint4*)((char*)g_Al + db + 16) = l;
    }
}

// ---------- W1 prepack: fp32 [K][N] -> single fp16, [N][K] tile-linear SW128 ----------
__global__ __launch_bounds__(256) void prep_w1(const float* __restrict__ Wn, const float* __restrict__ Wo) {
    int tid = blockIdx.x * 256 + threadIdx.x;      // 2*512*2048
    int n = tid & 2047, rest = tid >> 11;
    int ko = rest & 511, g = rest >> 9;
    const float* src = g ? Wo : Wn;
    uint4 hv;
    uint32_t* hp = (uint32_t*)&hv;
    #pragma unroll
    for (int e = 0; e < 4; e++) {
        __half2 p = __floats2half2_rn(__ldg(src + (size_t)(ko*8 + 2*e) * HID + n),
                                      __ldg(src + (size_t)(ko*8 + 2*e + 1) * HID + n));
        hp[e] = *reinterpret_cast<uint32_t*>(&p);
    }
    int nt = n >> 7, rIn = n & 127, kt = ko >> 3, cb = ko & 7;
    size_t tb = ((size_t)(((g << 4) + nt) * 64 + kt)) << 14;
    uint32_t sw = (uint32_t)(rIn * 128 + (cb << 4)) ^ ((uint32_t)(rIn & 7) << 4);
    *(uint4*)((char*)g_W1h + tb + sw) = hv;
}

// ---------- W2 prepack: fp32 [K][N] -> bf16 hi/lo (3-term for GEMM2) ----------
__global__ __launch_bounds__(256) void prep_w2(const float* __restrict__ Wn, const float* __restrict__ Wo) {
    int tid = blockIdx.x * 256 + threadIdx.x;      // 2*256*512
    int n = tid & 511, rest = tid >> 9;
    int ko = rest & 255, g = rest >> 8;
    const float* src = g ? Wo : Wn;
    uint4 hv, lv;
    uint32_t* hp = (uint32_t*)&hv; uint32_t* lp = (uint32_t*)&lv;
    #pragma unroll
    for (int e = 0; e < 4; e++)
        split2b(__ldg(src + (size_t)(ko*8 + 2*e) * PROJ + n),
                __ldg(src + (size_t)(ko*8 + 2*e + 1) * PROJ + n), hp[e], lp[e]);
    int nt = n >> 7, rIn = n & 127, kt = ko >> 3, cb = ko & 7;
    size_t tb = ((size_t)(((g << 2) + nt) * 32 + kt)) << 14;
    uint32_t sw = (uint32_t)(rIn * 128 + (cb << 4)) ^ ((uint32_t)(rIn & 7) << 4);
    *(uint4*)((char*)g_W2h + tb + sw) = hv;
    *(uint4*)((char*)g_W2l + tb + sw) = lv;
}

// ---------- GEMM: M128 x N256 CTA, K-step 64 ----------
// IS_G1=1: fp16 2-term (Ah·W + Al·W), stage 64KB.  IS_G1=0: bf16 3-term, stage 96KB.
template <int IS_G1>
__global__ __launch_bounds__(256, 1) void gemm_mma(
    const float* __restrict__ bn_, const float* __restrict__ bo_)
{
    extern __shared__ char smc[];
    __shared__ float biasS[256];
    __shared__ int rowS[128];

    constexpr int STG = IS_G1 ? 65536 : 98304;
    constexpr int NTB = IS_G1 ? 16 : 4;
    constexpr int KTB = IS_G1 ? 64 : 32;
    constexpr int NIT = IS_G1 ? (FEAT/64) : (HID/64);
    const int n_nat = g_cnt[0], n_oth = g_cnt[1];
    const int nat_tiles = (n_nat + 127) >> 7;
    const int bm = blockIdx.y, bnb = blockIdx.x;
    int grp, prow0, nrows;
    if (bm < nat_tiles) { grp = 0; prow0 = bm << 7; nrows = min(128, n_nat - prow0); }
    else {
        int bm2 = bm - nat_tiles;
        if ((bm2 << 7) >= n_oth) return;
        grp = 1; prow0 = (nat_tiles + bm2) << 7; nrows = min(128, n_oth - (bm2 << 7));
    }
    const int t = threadIdx.x;
    biasS[t] = (grp ? bo_ : bn_)[(bnb << 8) + t];
    if (t < 128) rowS[t] = (t < nrows) ? g_pos2row[prow0 + t] : -1;
    __syncthreads();

    const uint32_t sb = smem_u32(smc);
    const char* Asrc_h = IS_G1 ? (const char*)g_Ah : (const char*)g_Hh;
    const char* Asrc_l = IS_G1 ? (const char*)g_Al : (const char*)g_Hl;
    const size_t rowE  = IS_G1 ? FEAT : HID;
    const char* Wsrc_h = IS_G1 ? (const char*)g_W1h : (const char*)g_W2h;
    const char* Wsrc_l = (const char*)g_W2l;

    auto issue = [&](int s, int it) {
        uint32_t base = sb + s * STG;
        #pragma unroll
        for (int i = 0; i < 4; i++) {
            int cid = i * 256 + t;
            int r = cid >> 3, c = cid & 7;
            uint32_t off = (uint32_t)((r * 128 + c * 16) ^ ((r & 7) << 4));
            size_t so = ((size_t)(prow0 + r) * rowE + it * 64 + c * 8) * 2;
            cpa16(base + off,         Asrc_h + so);
            cpa16(base + 16384 + off, Asrc_l + so);
        }
        size_t tb0 = ((size_t)((grp * NTB + bnb * 2 + 0) * KTB + it)) << 14;
        size_t tb1 = ((size_t)((grp * NTB + bnb * 2 + 1) * KTB + it)) << 14;
        if (IS_G1) {
            #pragma unroll
            for (int i = 0; i < 8; i++) {
                int cid = i * 256 + t;
                int ti = cid >> 10, j = cid & 1023;
                const char* sp = Wsrc_h + (ti ? tb1 : tb0) + (size_t)j * 16;
                cpa16(base + 32768 + ti * 16384 + j * 16, sp);
            }
        } else {
            #pragma unroll
            for (int i = 0; i < 16; i++) {
                int cid = i * 256 + t;
                int ti = cid >> 10, j = cid & 1023;
                const char* sp = (ti >= 2 ? Wsrc_l : Wsrc_h) + ((ti & 1) ? tb1 : tb0) + (size_t)j * 16;
                cpa16(base + 32768 + ti * 16384 + j * 16, sp);
            }
        }
    };

    const int w = t >> 5, lane = t & 31;
    const int wm = w >> 2, wn = w & 3;
    const int lr = lane & 7, gq = lane >> 3;
    int preA[4], rxA[4], preB[4], rxB[4];
    #pragma unroll
    for (int mf = 0; mf < 4; mf++) {
        int row = wm * 64 + mf * 16 + (gq & 1) * 8 + lr;
        preA[mf] = row * 128 + (gq >> 1) * 16;
        rxA[mf]  = (row & 7) << 4;
    }
    #pragma unroll
    for (int p = 0; p < 4; p++) {
        int n = wn * 64 + p * 16 + (gq >> 1) * 8 + lr;
        preB[p] = ((n >> 7) << 14) + (n & 127) * 128 + (gq & 1) * 16;
        rxB[p]  = (n & 7) << 4;
    }

    float acc[4][8][4];
    #pragma unroll
    for (int i = 0; i < 4; i++)
        #pragma unroll
        for (int j = 0; j < 8; j++)
            #pragma unroll
            for (int e = 0; e < 4; e++) acc[i][j][e] = 0.f;

    issue(0, 0); CPCOMMIT();
    for (int it = 0; it < NIT; it++) {
        int b = it & 1;
        if (it + 1 < NIT) { issue(b ^ 1, it + 1); CPCOMMIT(); CPWAIT1(); }
        else              { CPWAIT0(); }
        __syncthreads();
        uint32_t sAh = sb + b * STG, sAl = sAh + 16384, sWh = sAh + 32768, sWl = sAh + 65536;
        #pragma unroll
        for (int k16 = 0; k16 < 4; k16++) {
            int kb = k16 * 32;
            uint32_t a[4][4], a2[4][4], bb[8][2];
            #pragma unroll
            for (int mf = 0; mf < 4; mf++) ldsm4(a[mf], sAh + (uint32_t)((preA[mf] + kb) ^ rxA[mf]));
            #pragma unroll
            for (int p = 0; p < 4; p++) {
                uint32_t r[4];
                ldsm4(r, sWh + (uint32_t)((preB[p] + kb) ^ rxB[p]));
                bb[2*p][0]=r[0]; bb[2*p][1]=r[1]; bb[2*p+1][0]=r[2]; bb[2*p+1][1]=r[3];
            }
            if (IS_G1) {
                #pragma unroll
                for (int mf = 0; mf < 4; mf++)
                    #pragma unroll
                    for (int nf = 0; nf < 8; nf++) mma_h(acc[mf][nf], a[mf], bb[nf]);
                #pragma unroll
                for (int mf = 0; mf < 4; mf++) ldsm4(a2[mf], sAl + (uint32_t)((preA[mf] + kb) ^ rxA[mf]));
                #pragma unroll
                for (int mf = 0; mf < 4; mf++)
                    #pragma unroll
                    for (int nf = 0; nf < 8; nf++) mma_h(acc[mf][nf], a2[mf], bb[nf]);
            } else {
                #pragma unroll
                for (int mf = 0; mf < 4; mf++)
                    #pragma unroll
                    for (int nf = 0; nf < 8; nf++) mma_bf(acc[mf][nf], a[mf], bb[nf]);
                #pragma unroll
                for (int mf = 0; mf < 4; mf++) ldsm4(a2[mf], sAl + (uint32_t)((preA[mf] + kb) ^ rxA[mf]));
                #pragma unroll
                for (int mf = 0; mf < 4; mf++)
                    #pragma unroll
                    for (int nf = 0; nf < 8; nf++) mma_bf(acc[mf][nf], a2[mf], bb[nf]);
                #pragma unroll
                for (int p = 0; p < 4; p++) {
                    uint32_t r[4];
                    ldsm4(r, sWl + (uint32_t)((preB[p] + kb) ^ rxB[p]));
                    bb[2*p][0]=r[0]; bb[2*p][1]=r[1]; bb[2*p+1][0]=r[2]; bb[2*p+1][1]=r[3];
                }
                #pragma unroll
                for (int mf = 0; mf < 4; mf++)
                    #pragma unroll
                    for (int nf = 0; nf < 8; nf++) mma_bf(acc[mf][nf], a[mf], bb[nf]);
            }
        }
        __syncthreads();
    }

    // epilogue
    #pragma unroll
    for (int mf = 0; mf < 4; mf++) {
        #pragma unroll
        for (int half = 0; half < 2; half++) {
            int row = wm * 64 + mf * 16 + (lane >> 2) + half * 8;
            if (IS_G1) {
                size_t base = (size_t)(prow0 + row) * HID + (bnb << 8);
                #pragma unroll
                for (int nf = 0; nf < 8; nf++) {
                    int n = wn * 64 + nf * 8 + (lane & 3) * 2;
                    float v0 = fmaxf(acc[mf][nf][half*2+0] + biasS[n],     0.f);
                    float v1 = fmaxf(acc[mf][nf][half*2+1] + biasS[n + 1], 0.f);
                    uint32_t uh, ul;
                    split2b(v0, v1, uh, ul);
                    *(uint32_t*)((char*)g_Hh + (base + n) * 2) = uh;
                    *(uint32_t*)((char*)g_Hl + (base + n) * 2) = ul;
                }
            } else {
                int orig = rowS[row];
                if (orig >= 0) {
                    float* zp = g_Z + (size_t)orig * PROJ + (bnb << 8);
                    #pragma unroll
                    for (int nf = 0; nf < 8; nf++) {
                        int n = wn * 64 + nf * 8 + (lane & 3) * 2;
                        float2 v;
                        v.x = acc[mf][nf][half*2+0] + biasS[n];
                        v.y = acc[mf][nf][half*2+1] + biasS[n + 1];
                        *(float2*)(zp + n) = v;
                    }
                }
            }
        }
    }
}

// ---------- finalize: norm, z_normalized, logits ----------
__global__ __launch_bounds__(128) void k_final(
    const float* __restrict__ x,
    const float* __restrict__ Wcn, const float* __restrict__ bcn,
    const float* __restrict__ Wco, const float* __restrict__ bco,
    float* __restrict__ out)
{
    const int row = blockIdx.x;
    const bool nat = x[(size_t)row * XLD + FEAT] > 0.5f;
    const float* __restrict__ Wc = nat ? Wcn : Wco;
    const float* __restrict__ bc = nat ? bcn : bco;
    const int t = threadIdx.x;
    const float* zr = g_Z + (size_t)row * PROJ;

    float zv[4];
    float ss = 0.f, l0 = 0.f, l1 = 0.f, l2 = 0.f;
    #pragma unroll
    for (int i = 0; i < 4; i++) {
        const int k = t + i * 128;
        const float z = zr[k];
        zv[i] = z;
        ss = fmaf(z, z, ss);
        const float rz = fmaxf(z, 0.f);
        l0 = fmaf(rz, Wc[k*3+0], l0);
        l1 = fmaf(rz, Wc[k*3+1], l1);
        l2 = fmaf(rz, Wc[k*3+2], l2);
    }
    #pragma unroll
    for (int o = 16; o > 0; o >>= 1) {
        ss += __shfl_down_sync(0xFFFFFFFFu, ss, o);
        l0 += __shfl_down_sync(0xFFFFFFFFu, l0, o);
        l1 += __shfl_down_sync(0xFFFFFFFFu, l1, o);
        l2 += __shfl_down_sync(0xFFFFFFFFu, l2, o);
    }
    __shared__ float red[4][4];
    __shared__ float inv_s;
    const int w = t >> 5, lane = t & 31;
    if (lane == 0) { red[w][0]=ss; red[w][1]=l0; red[w][2]=l1; red[w][3]=l2; }
    __syncthreads();
    if (t == 0) {
        float S  = red[0][0]+red[1][0]+red[2][0]+red[3][0];
        float L0 = red[0][1]+red[1][1]+red[2][1]+red[3][1];
        float L1 = red[0][2]+red[1][2]+red[2][2]+red[3][2];
        float L2 = red[0][3]+red[1][3]+red[2][3]+red[3][3];
        inv_s = 1.f / fmaxf(sqrtf(S), 1e-12f);
        float* lg = out + (size_t)B_ * PROJ + (size_t)row * NOUT;
        lg[0] = L0 + bc[0]; lg[1] = L1 + bc[1]; lg[2] = L2 + bc[2];
    }
    __syncthreads();
    const float inv = inv_s;
    #pragma unroll
    for (int i = 0; i < 4; i++)
        out[(size_t)row * PROJ + t + i * 128] = zv[i] * inv;
}

// ---------- launcher ----------
extern "C" void kernel_launch(void* const* d_in, const int* in_sizes, int n_in,
                              void* d_out, int out_size) {
    const float* x   = (const float*)d_in[0];
    const float* W1n = (const float*)d_in[1];
    const float* b1n = (const float*)d_in[2];
    const float* W2n = (const float*)d_in[3];
    const float* b2n = (const float*)d_in[4];
    const float* Wcn = (const float*)d_in[5];
    const float* bcn = (const float*)d_in[6];
    const float* W1o = (const float*)d_in[7];
    const float* b1o = (const float*)d_in[8];
    const float* W2o = (const float*)d_in[9];
    const float* b2o = (const float*)d_in[10];
    const float* Wco = (const float*)d_in[11];
    const float* bco = (const float*)d_in[12];
    float* out = (float*)d_out;

    cudaFuncSetAttribute(gemm_mma<1>, cudaFuncAttributeMaxDynamicSharedMemorySize, 2*65536);
    cudaFuncSetAttribute(gemm_mma<0>, cudaFuncAttributeMaxDynamicSharedMemorySize, 2*98304);

    k_zero<<<1, 1>>>();
    k_count<<<B_ / 256, 256>>>(x);
    k_assign<<<B_ / 256, 256>>>(x);
    k_splitA<<<APAD, 256>>>(x);
    prep_w1<<<8192, 256>>>(W1n, W1o);
    prep_w2<<<1024, 256>>>(W2n, W2o);

    gemm_mma<1><<<dim3(8, TILES_M), 256, 2*65536>>>(b1n, b1o);
    gemm_mma<0><<<dim3(2, TILES_M), 256, 2*98304>>>(b2n, b2o);

    k_final<<<B_, 128>>>(x, Wcn, bcn, Wco, bco, out);
}

// round 6
// speedup vs baseline: 5.2451x; 1.1138x over previous
#include <cuda_runtime.h>
#include <cuda_bf16.h>
#include <cuda_fp16.h>
#include <cstdint>

#define B_   32768
#define FEAT 4096
#define XLD  4097
#define HID  2048
#define PROJ 512
#define NOUT 3
#define APAD (B_ + 256)
#define TILES_M 258

// ---------- device scratch ----------
__device__ int g_cnt[2];
__device__ int g_cnt2[2];
__device__ int g_pos2row[APAD];
__device__ float g_Z[(size_t)B_ * PROJ];
__device__ __half g_Ah[(size_t)APAD * FEAT];     // fp16 hi limb of x features
__device__ __half g_Al[(size_t)APAD * FEAT];     // fp16 lo limb
__device__ __half g_H [(size_t)APAD * HID];      // H single fp16 (GEMM2 is 1-term)
__device__ __half g_W1h[(size_t)2 * 16 * 64 * 8192];  // fp16, [N][K] tile-linear SW128
__device__ __half g_W2h[(size_t)2 * 4 * 32 * 8192];

// ---------- helpers ----------
__device__ __forceinline__ uint32_t smem_u32(const void* p) {
    uint32_t a;
    asm("{ .reg .u64 t; cvta.to.shared.u64 t, %1; cvt.u32.u64 %0, t; }" : "=r"(a) : "l"(p));
    return a;
}
__device__ __forceinline__ void split2h(float v0, float v1, uint32_t& hi, uint32_t& lo) {
    __half h0 = __float2half_rn(v0);
    __half h1 = __float2half_rn(v1);
    __half l0 = __float2half_rn(v0 - __half2float(h0));
    __half l1 = __float2half_rn(v1 - __half2float(h1));
    __half2 hp = __halves2half2(h0, h1);
    __half2 lp = __halves2half2(l0, l1);
    hi = *reinterpret_cast<uint32_t*>(&hp);
    lo = *reinterpret_cast<uint32_t*>(&lp);
}
__device__ __forceinline__ void cpa16(uint32_t d, const void* s) {
    asm volatile("cp.async.cg.shared.global [%0], [%1], 16;" :: "r"(d), "l"(s));
}
#define CPCOMMIT() asm volatile("cp.async.commit_group;" ::: "memory")
#define CPWAIT0()  asm volatile("cp.async.wait_group 0;" ::: "memory")
#define CPWAIT1()  asm volatile("cp.async.wait_group 1;" ::: "memory")
__device__ __forceinline__ void ldsm4(uint32_t* r, uint32_t a) {
    asm volatile("ldmatrix.sync.aligned.m8n8.x4.shared.b16 {%0,%1,%2,%3}, [%4];"
                 : "=r"(r[0]), "=r"(r[1]), "=r"(r[2]), "=r"(r[3]) : "r"(a));
}
__device__ __forceinline__ void mma_h(float* c, const uint32_t* a, const uint32_t* b) {
    asm volatile("mma.sync.aligned.m16n8k16.row.col.f32.f16.f16.f32 "
                 "{%0,%1,%2,%3}, {%4,%5,%6,%7}, {%8,%9}, {%0,%1,%2,%3};"
                 : "+f"(c[0]), "+f"(c[1]), "+f"(c[2]), "+f"(c[3])
                 : "r"(a[0]), "r"(a[1]), "r"(a[2]), "r"(a[3]), "r"(b[0]), "r"(b[1]));
}

// ---------- partition ----------
__global__ void k_zero() { g_cnt[0]=0; g_cnt[1]=0; g_cnt2[0]=0; g_cnt2[1]=0; }
__global__ void k_count(const float* __restrict__ x) {
    int r = blockIdx.x * blockDim.x + threadIdx.x;
    if (r < B_) atomicAdd(&g_cnt[(x[(size_t)r*XLD+FEAT] > 0.5f) ? 0 : 1], 1);
}
__global__ void k_assign(const float* __restrict__ x) {
    int r = blockIdx.x * blockDim.x + threadIdx.x;
    if (r < B_) {
        int g = (x[(size_t)r*XLD+FEAT] > 0.5f) ? 0 : 1;
        int idx = atomicAdd(&g_cnt2[g], 1);
        int base_oth = ((g_cnt[0] + 127) >> 7) << 7;
        g_pos2row[g ? (base_oth + idx) : idx] = r;
    }
}

// ---------- A pre-split: gather + fp32 -> fp16 hi/lo, permuted row order ----------
__global__ __launch_bounds__(256) void k_splitA(const float* __restrict__ x) {
    int pos = blockIdx.x;
    int natPad = ((g_cnt[0] + 127) & ~127);
    bool valid = (pos < natPad) ? (pos < g_cnt[0]) : ((pos - natPad) < g_cnt[1]);
    int t = threadIdx.x;
    size_t db = ((size_t)pos * FEAT + t * 16) * 2;
    uint4 h = {0,0,0,0}, l = {0,0,0,0};
    float v[16];
    if (valid) {
        int orig = g_pos2row[pos];
        const float* src = x + (size_t)orig * XLD + t * 16;
        if (!(orig & 1)) {
            #pragma unroll
            for (int q = 0; q < 8; q++) {
                float2 f = __ldg((const float2*)(src + q * 2));
                v[q*2] = f.x; v[q*2+1] = f.y;
            }
        } else {
            #pragma unroll
            for (int q = 0; q < 16; q++) v[q] = __ldg(src + q);
        }
        uint32_t* hp = (uint32_t*)&h;
        uint32_t* lp = (uint32_t*)&l;
        #pragma unroll
        for (int e = 0; e < 8; e++) {
            uint32_t uh, ul;
            split2h(v[2*e], v[2*e+1], uh, ul);
            if (e < 4) { hp[e] = uh; lp[e] = ul; }
            else {
                if (e == 4) { *(uint4*)((char*)g_Ah + db) = h; *(uint4*)((char*)g_Al + db) = l; }
                hp[e-4] = uh; lp[e-4] = ul;
            }
        }
        *(uint4*)((char*)g_Ah + db + 16) = h;
        *(uint4*)((char*)g_Al + db + 16) = l;
    } else {
        *(uint4*)((char*)g_Ah + db) = h;  *(uint4*)((char*)g_Ah + db + 16) = h;
        *(uint4*)((char*)g_Al + db) = l;  *(uint4*)((char*)g_Al + db + 16) = l;
    }
}

// ---------- W1 prepack: fp32 [K][N] -> fp16, [N][K] tile-linear SW128 ----------
__global__ __launch_bounds__(256) void prep_w1(const float* __restrict__ Wn, const float* __restrict__ Wo) {
    int tid = blockIdx.x * 256 + threadIdx.x;      // 2*512*2048
    int n = tid & 2047, rest = tid >> 11;
    int ko = rest & 511, g = rest >> 9;
    const float* src = g ? Wo : Wn;
    uint4 hv;
    uint32_t* hp = (uint32_t*)&hv;
    #pragma unroll
    for (int e = 0; e < 4; e++) {
        __half2 p = __floats2half2_rn(__ldg(src + (size_t)(ko*8 + 2*e) * HID + n),
                                      __ldg(src + (size_t)(ko*8 + 2*e + 1) * HID + n));
        hp[e] = *reinterpret_cast<uint32_t*>(&p);
    }
    int nt = n >> 7, rIn = n & 127, kt = ko >> 3, cb = ko & 7;
    size_t tb = ((size_t)(((g << 4) + nt) * 64 + kt)) << 14;
    uint32_t sw = (uint32_t)(rIn * 128 + (cb << 4)) ^ ((uint32_t)(rIn & 7) << 4);
    *(uint4*)((char*)g_W1h + tb + sw) = hv;
}

// ---------- W2 prepack: fp32 [K][N] -> fp16, [N][K] tile-linear SW128 ----------
__global__ __launch_bounds__(256) void prep_w2(const float* __restrict__ Wn, const float* __restrict__ Wo) {
    int tid = blockIdx.x * 256 + threadIdx.x;      // 2*256*512
    int n = tid & 511, rest = tid >> 9;
    int ko = rest & 255, g = rest >> 8;
    const float* src = g ? Wo : Wn;
    uint4 hv;
    uint32_t* hp = (uint32_t*)&hv;
    #pragma unroll
    for (int e = 0; e < 4; e++) {
        __half2 p = __floats2half2_rn(__ldg(src + (size_t)(ko*8 + 2*e) * PROJ + n),
                                      __ldg(src + (size_t)(ko*8 + 2*e + 1) * PROJ + n));
        hp[e] = *reinterpret_cast<uint32_t*>(&p);
    }
    int nt = n >> 7, rIn = n & 127, kt = ko >> 3, cb = ko & 7;
    size_t tb = ((size_t)(((g << 2) + nt) * 32 + kt)) << 14;
    uint32_t sw = (uint32_t)(rIn * 128 + (cb << 4)) ^ ((uint32_t)(rIn & 7) << 4);
    *(uint4*)((char*)g_W2h + tb + sw) = hv;
}

// ---------- GEMM: M128 x N256 CTA, K-step 64, fp16 mma ----------
// IS_G1=1: 2-term (Ah·W + Al·W), stage 64KB.  IS_G1=0: 1-term (H·W), stage 48KB.
template <int IS_G1>
__global__ __launch_bounds__(256, 1) void gemm_mma(
    const float* __restrict__ bn_, const float* __restrict__ bo_)
{
    extern __shared__ char smc[];
    __shared__ float biasS[256];
    __shared__ int rowS[128];

    constexpr int STG  = IS_G1 ? 65536 : 49152;
    constexpr int WOFF = IS_G1 ? 32768 : 16384;
    constexpr int NTB  = IS_G1 ? 16 : 4;
    constexpr int KTB  = IS_G1 ? 64 : 32;
    constexpr int NIT  = IS_G1 ? (FEAT/64) : (HID/64);
    const int n_nat = g_cnt[0], n_oth = g_cnt[1];
    const int nat_tiles = (n_nat + 127) >> 7;
    const int bm = blockIdx.y, bnb = blockIdx.x;
    int grp, prow0, nrows;
    if (bm < nat_tiles) { grp = 0; prow0 = bm << 7; nrows = min(128, n_nat - prow0); }
    else {
        int bm2 = bm - nat_tiles;
        if ((bm2 << 7) >= n_oth) return;
        grp = 1; prow0 = (nat_tiles + bm2) << 7; nrows = min(128, n_oth - (bm2 << 7));
    }
    const int t = threadIdx.x;
    biasS[t] = (grp ? bo_ : bn_)[(bnb << 8) + t];
    if (t < 128) rowS[t] = (t < nrows) ? g_pos2row[prow0 + t] : -1;
    __syncthreads();

    const uint32_t sb = smem_u32(smc);
    const char* Asrc_h = IS_G1 ? (const char*)g_Ah : (const char*)g_H;
    const char* Asrc_l = (const char*)g_Al;
    const size_t rowE  = IS_G1 ? FEAT : HID;
    const char* Wsrc   = IS_G1 ? (const char*)g_W1h : (const char*)g_W2h;

    auto issue = [&](int s, int it) {
        uint32_t base = sb + s * STG;
        #pragma unroll
        for (int i = 0; i < 4; i++) {
            int cid = i * 256 + t;
            int r = cid >> 3, c = cid & 7;
            uint32_t off = (uint32_t)((r * 128 + c * 16) ^ ((r & 7) << 4));
            size_t so = ((size_t)(prow0 + r) * rowE + it * 64 + c * 8) * 2;
            cpa16(base + off, Asrc_h + so);
            if (IS_G1) cpa16(base + 16384 + off, Asrc_l + so);
        }
        size_t tb0 = ((size_t)((grp * NTB + bnb * 2 + 0) * KTB + it)) << 14;
        size_t tb1 = ((size_t)((grp * NTB + bnb * 2 + 1) * KTB + it)) << 14;
        #pragma unroll
        for (int i = 0; i < 8; i++) {
            int cid = i * 256 + t;
            int ti = cid >> 10, j = cid & 1023;
            const char* sp = Wsrc + (ti ? tb1 : tb0) + (size_t)j * 16;
            cpa16(base + WOFF + ti * 16384 + j * 16, sp);
        }
    };

    const int w = t >> 5, lane = t & 31;
    const int wm = w >> 2, wn = w & 3;
    const int lr = lane & 7, gq = lane >> 3;
    int preA[4], rxA[4], preB[4], rxB[4];
    #pragma unroll
    for (int mf = 0; mf < 4; mf++) {
        int row = wm * 64 + mf * 16 + (gq & 1) * 8 + lr;
        preA[mf] = row * 128 + (gq >> 1) * 16;
        rxA[mf]  = (row & 7) << 4;
    }
    #pragma unroll
    for (int p = 0; p < 4; p++) {
        int n = wn * 64 + p * 16 + (gq >> 1) * 8 + lr;
        preB[p] = ((n >> 7) << 14) + (n & 127) * 128 + (gq & 1) * 16;
        rxB[p]  = (n & 7) << 4;
    }

    float acc[4][8][4];
    #pragma unroll
    for (int i = 0; i < 4; i++)
        #pragma unroll
        for (int j = 0; j < 8; j++)
            #pragma unroll
            for (int e = 0; e < 4; e++) acc[i][j][e] = 0.f;

    issue(0, 0); CPCOMMIT();
    for (int it = 0; it < NIT; it++) {
        int b = it & 1;
        if (it + 1 < NIT) { issue(b ^ 1, it + 1); CPCOMMIT(); CPWAIT1(); }
        else              { CPWAIT0(); }
        __syncthreads();
        uint32_t sAh = sb + b * STG, sAl = sAh + 16384, sWh = sAh + WOFF;
        #pragma unroll
        for (int k16 = 0; k16 < 4; k16++) {
            int kb = k16 * 32;
            uint32_t a[4][4], a2[4][4], bb[8][2];
            #pragma unroll
            for (int mf = 0; mf < 4; mf++) ldsm4(a[mf], sAh + (uint32_t)((preA[mf] + kb) ^ rxA[mf]));
            #pragma unroll
            for (int p = 0; p < 4; p++) {
                uint32_t r[4];
                ldsm4(r, sWh + (uint32_t)((preB[p] + kb) ^ rxB[p]));
                bb[2*p][0]=r[0]; bb[2*p][1]=r[1]; bb[2*p+1][0]=r[2]; bb[2*p+1][1]=r[3];
            }
            #pragma unroll
            for (int mf = 0; mf < 4; mf++)
                #pragma unroll
                for (int nf = 0; nf < 8; nf++) mma_h(acc[mf][nf], a[mf], bb[nf]);
            if (IS_G1) {
                #pragma unroll
                for (int mf = 0; mf < 4; mf++) ldsm4(a2[mf], sAl + (uint32_t)((preA[mf] + kb) ^ rxA[mf]));
                #pragma unroll
                for (int mf = 0; mf < 4; mf++)
                    #pragma unroll
                    for (int nf = 0; nf < 8; nf++) mma_h(acc[mf][nf], a2[mf], bb[nf]);
            }
        }
        __syncthreads();
    }

    // epilogue
    #pragma unroll
    for (int mf = 0; mf < 4; mf++) {
        #pragma unroll
        for (int half = 0; half < 2; half++) {
            int row = wm * 64 + mf * 16 + (lane >> 2) + half * 8;
            if (IS_G1) {
                size_t base = (size_t)(prow0 + row) * HID + (bnb << 8);
                #pragma unroll
                for (int nf = 0; nf < 8; nf++) {
                    int n = wn * 64 + nf * 8 + (lane & 3) * 2;
                    float v0 = fmaxf(acc[mf][nf][half*2+0] + biasS[n],     0.f);
                    float v1 = fmaxf(acc[mf][nf][half*2+1] + biasS[n + 1], 0.f);
                    __half2 p = __floats2half2_rn(v0, v1);
                    *(uint32_t*)((char*)g_H + (base + n) * 2) = *reinterpret_cast<uint32_t*>(&p);
                }
            } else {
                int orig = rowS[row];
                if (orig >= 0) {
                    float* zp = g_Z + (size_t)orig * PROJ + (bnb << 8);
                    #pragma unroll
                    for (int nf = 0; nf < 8; nf++) {
                        int n = wn * 64 + nf * 8 + (lane & 3) * 2;
                        float2 v;
                        v.x = acc[mf][nf][half*2+0] + biasS[n];
                        v.y = acc[mf][nf][half*2+1] + biasS[n + 1];
                        *(float2*)(zp + n) = v;
                    }
                }
            }
        }
    }
}

// ---------- finalize: norm, z_normalized, logits ----------
__global__ __launch_bounds__(128) void k_final(
    const float* __restrict__ x,
    const float* __restrict__ Wcn, const float* __restrict__ bcn,
    const float* __restrict__ Wco, const float* __restrict__ bco,
    float* __restrict__ out)
{
    const int row = blockIdx.x;
    const bool nat = x[(size_t)row * XLD + FEAT] > 0.5f;
    const float* __restrict__ Wc = nat ? Wcn : Wco;
    const float* __restrict__ bc = nat ? bcn : bco;
    const int t = threadIdx.x;
    const float* zr = g_Z + (size_t)row * PROJ;

    float zv[4];
    float ss = 0.f, l0 = 0.f, l1 = 0.f, l2 = 0.f;
    #pragma unroll
    for (int i = 0; i < 4; i++) {
        const int k = t + i * 128;
        const float z = zr[k];
        zv[i] = z;
        ss = fmaf(z, z, ss);
        const float rz = fmaxf(z, 0.f);
        l0 = fmaf(rz, Wc[k*3+0], l0);
        l1 = fmaf(rz, Wc[k*3+1], l1);
        l2 = fmaf(rz, Wc[k*3+2], l2);
    }
    #pragma unroll
    for (int o = 16; o > 0; o >>= 1) {
        ss += __shfl_down_sync(0xFFFFFFFFu, ss, o);
        l0 += __shfl_down_sync(0xFFFFFFFFu, l0, o);
        l1 += __shfl_down_sync(0xFFFFFFFFu, l1, o);
        l2 += __shfl_down_sync(0xFFFFFFFFu, l2, o);
    }
    __shared__ float red[4][4];
    __shared__ float inv_s;
    const int w = t >> 5, lane = t & 31;
    if (lane == 0) { red[w][0]=ss; red[w][1]=l0; red[w][2]=l1; red[w][3]=l2; }
    __syncthreads();
    if (t == 0) {
        float S  = red[0][0]+red[1][0]+red[2][0]+red[3][0];
        float L0 = red[0][1]+red[1][1]+red[2][1]+red[3][1];
        float L1 = red[0][2]+red[1][2]+red[2][2]+red[3][2];
        float L2 = red[0][3]+red[1][3]+red[2][3]+red[3][3];
        inv_s = 1.f / fmaxf(sqrtf(S), 1e-12f);
        float* lg = out + (size_t)B_ * PROJ + (size_t)row * NOUT;
        lg[0] = L0 + bc[0]; lg[1] = L1 + bc[1]; lg[2] = L2 + bc[2];
    }
    __syncthreads();
    const float inv = inv_s;
    #pragma unroll
    for (int i = 0; i < 4; i++)
        out[(size_t)row * PROJ + t + i * 128] = zv[i] * inv;
}

// ---------- launcher ----------
extern "C" void kernel_launch(void* const* d_in, const int* in_sizes, int n_in,
                              void* d_out, int out_size) {
    const float* x   = (const float*)d_in[0];
    const float* W1n = (const float*)d_in[1];
    const float* b1n = (const float*)d_in[2];
    const float* W2n = (const float*)d_in[3];
    const float* b2n = (const float*)d_in[4];
    const float* Wcn = (const float*)d_in[5];
    const float* bcn = (const float*)d_in[6];
    const float* W1o = (const float*)d_in[7];
    const float* b1o = (const float*)d_in[8];
    const float* W2o = (const float*)d_in[9];
    const float* b2o = (const float*)d_in[10];
    const float* Wco = (const float*)d_in[11];
    const float* bco = (const float*)d_in[12];
    float* out = (float*)d_out;

    cudaFuncSetAttribute(gemm_mma<1>, cudaFuncAttributeMaxDynamicSharedMemorySize, 2*65536);
    cudaFuncSetAttribute(gemm_mma<0>, cudaFuncAttributeMaxDynamicSharedMemorySize, 2*49152);

    k_zero<<<1, 1>>>();
    k_count<<<B_ / 256, 256>>>(x);
    k_assign<<<B_ / 256, 256>>>(x);
    k_splitA<<<APAD, 256>>>(x);
    prep_w1<<<8192, 256>>>(W1n, W1o);
    prep_w2<<<1024, 256>>>(W2n, W2o);

    gemm_mma<1><<<dim3(8, TILES_M), 256, 2*65536>>>(b1n, b1o);
    gemm_mma<0><<<dim3(2, TILES_M), 256, 2*49152>>>(b2n, b2o);

    k_final<<<B_, 128>>>(x, Wcn, bcn, Wco, bco, out);
}

// round 7
// speedup vs baseline: 8.3523x; 1.5924x over previous
#include <cuda_runtime.h>
#include <cuda_fp16.h>
#include <cstdint>

#define B_   32768
#define FEAT 4096
#define XLD  4097
#define HID  2048
#define PROJ 512
#define NOUT 3
#define APAD (B_ + 256)
#define TILES_M 258

// ---------- device scratch ----------
__device__ int g_cnt[2];
__device__ int g_cnt2[2];
__device__ int g_pos2row[APAD];
__device__ float g_Z[(size_t)B_ * PROJ];
__device__ __half g_A[(size_t)APAD * FEAT];      // fp16 x features, permuted rows
__device__ __half g_H[(size_t)APAD * HID];       // fp16 hidden
__device__ __half g_W1[(size_t)2 * 16 * 64 * 8192];   // fp16, [N][K] tile-linear SW128
__device__ __half g_W2[(size_t)2 * 4 * 32 * 8192];

// ---------- helpers ----------
__device__ __forceinline__ uint32_t smem_u32(const void* p) {
    uint32_t a;
    asm("{ .reg .u64 t; cvta.to.shared.u64 t, %1; cvt.u32.u64 %0, t; }" : "=r"(a) : "l"(p));
    return a;
}
__device__ __forceinline__ void cpa16(uint32_t d, const void* s) {
    asm volatile("cp.async.cg.shared.global [%0], [%1], 16;" :: "r"(d), "l"(s));
}
#define CPCOMMIT() asm volatile("cp.async.commit_group;" ::: "memory")
#define CPWAIT0()  asm volatile("cp.async.wait_group 0;" ::: "memory")
#define CPWAIT1()  asm volatile("cp.async.wait_group 1;" ::: "memory")
__device__ __forceinline__ void ldsm4(uint32_t* r, uint32_t a) {
    asm volatile("ldmatrix.sync.aligned.m8n8.x4.shared.b16 {%0,%1,%2,%3}, [%4];"
                 : "=r"(r[0]), "=r"(r[1]), "=r"(r[2]), "=r"(r[3]) : "r"(a));
}
__device__ __forceinline__ void mma_h(float* c, const uint32_t* a, const uint32_t* b) {
    asm volatile("mma.sync.aligned.m16n8k16.row.col.f32.f16.f16.f32 "
                 "{%0,%1,%2,%3}, {%4,%5,%6,%7}, {%8,%9}, {%0,%1,%2,%3};"
                 : "+f"(c[0]), "+f"(c[1]), "+f"(c[2]), "+f"(c[3])
                 : "r"(a[0]), "r"(a[1]), "r"(a[2]), "r"(a[3]), "r"(b[0]), "r"(b[1]));
}

// ---------- partition ----------
__global__ void k_zero() { g_cnt[0]=0; g_cnt[1]=0; g_cnt2[0]=0; g_cnt2[1]=0; }
__global__ void k_count(const float* __restrict__ x) {
    int r = blockIdx.x * blockDim.x + threadIdx.x;
    if (r < B_) atomicAdd(&g_cnt[(x[(size_t)r*XLD+FEAT] > 0.5f) ? 0 : 1], 1);
}
__global__ void k_assign(const float* __restrict__ x) {
    int r = blockIdx.x * blockDim.x + threadIdx.x;
    if (r < B_) {
        int g = (x[(size_t)r*XLD+FEAT] > 0.5f) ? 0 : 1;
        int idx = atomicAdd(&g_cnt2[g], 1);
        int base_oth = ((g_cnt[0] + 127) >> 7) << 7;
        g_pos2row[g ? (base_oth + idx) : idx] = r;
    }
}

// ---------- A convert: gather + fp32 -> fp16, permuted row order ----------
__global__ __launch_bounds__(256) void k_convA(const float* __restrict__ x) {
    int pos = blockIdx.x;
    int natPad = ((g_cnt[0] + 127) & ~127);
    bool valid = (pos < natPad) ? (pos < g_cnt[0]) : ((pos - natPad) < g_cnt[1]);
    int t = threadIdx.x;
    size_t db = ((size_t)pos * FEAT + t * 16) * 2;   // byte offset (fp16)
    uint4 h0 = {0,0,0,0}, h1 = {0,0,0,0};
    if (valid) {
        int orig = g_pos2row[pos];
        const float* src = x + (size_t)orig * XLD + t * 16;
        float v[16];
        if (!(orig & 1)) {
            #pragma unroll
            for (int q = 0; q < 8; q++) {
                float2 f = __ldg((const float2*)(src + q * 2));
                v[q*2] = f.x; v[q*2+1] = f.y;
            }
        } else {
            #pragma unroll
            for (int q = 0; q < 16; q++) v[q] = __ldg(src + q);
        }
        uint32_t* p0 = (uint32_t*)&h0;
        uint32_t* p1 = (uint32_t*)&h1;
        #pragma unroll
        for (int e = 0; e < 4; e++) {
            __half2 a = __floats2half2_rn(v[2*e],     v[2*e+1]);
            __half2 b = __floats2half2_rn(v[8+2*e],   v[8+2*e+1]);
            p0[e] = *reinterpret_cast<uint32_t*>(&a);
            p1[e] = *reinterpret_cast<uint32_t*>(&b);
        }
    }
    *(uint4*)((char*)g_A + db)      = h0;
    *(uint4*)((char*)g_A + db + 16) = h1;
}

// ---------- W prepack: fp32 [K][N] -> fp16, [N][K] tile-linear SW128 ----------
__global__ __launch_bounds__(256) void prep_w1(const float* __restrict__ Wn, const float* __restrict__ Wo) {
    int tid = blockIdx.x * 256 + threadIdx.x;      // 2*512*2048
    int n = tid & 2047, rest = tid >> 11;
    int ko = rest & 511, g = rest >> 9;
    const float* src = g ? Wo : Wn;
    uint4 hv;
    uint32_t* hp = (uint32_t*)&hv;
    #pragma unroll
    for (int e = 0; e < 4; e++) {
        __half2 p = __floats2half2_rn(__ldg(src + (size_t)(ko*8 + 2*e) * HID + n),
                                      __ldg(src + (size_t)(ko*8 + 2*e + 1) * HID + n));
        hp[e] = *reinterpret_cast<uint32_t*>(&p);
    }
    int nt = n >> 7, rIn = n & 127, kt = ko >> 3, cb = ko & 7;
    size_t tb = ((size_t)(((g << 4) + nt) * 64 + kt)) << 14;
    uint32_t sw = (uint32_t)(rIn * 128 + (cb << 4)) ^ ((uint32_t)(rIn & 7) << 4);
    *(uint4*)((char*)g_W1 + tb + sw) = hv;
}
__global__ __launch_bounds__(256) void prep_w2(const float* __restrict__ Wn, const float* __restrict__ Wo) {
    int tid = blockIdx.x * 256 + threadIdx.x;      // 2*256*512
    int n = tid & 511, rest = tid >> 9;
    int ko = rest & 255, g = rest >> 8;
    const float* src = g ? Wo : Wn;
    uint4 hv;
    uint32_t* hp = (uint32_t*)&hv;
    #pragma unroll
    for (int e = 0; e < 4; e++) {
        __half2 p = __floats2half2_rn(__ldg(src + (size_t)(ko*8 + 2*e) * PROJ + n),
                                      __ldg(src + (size_t)(ko*8 + 2*e + 1) * PROJ + n));
        hp[e] = *reinterpret_cast<uint32_t*>(&p);
    }
    int nt = n >> 7, rIn = n & 127, kt = ko >> 3, cb = ko & 7;
    size_t tb = ((size_t)(((g << 2) + nt) * 32 + kt)) << 14;
    uint32_t sw = (uint32_t)(rIn * 128 + (cb << 4)) ^ ((uint32_t)(rIn & 7) << 4);
    *(uint4*)((char*)g_W2 + tb + sw) = hv;
}

// ---------- GEMM: M128 x N256 CTA, K-step 64, single fp16 mma ----------
// Stage 48KB: A 16K + W 32K. Double-buffered cp.async.
template <int IS_G1>
__global__ __launch_bounds__(256, 1) void gemm_mma(
    const float* __restrict__ bn_, const float* __restrict__ bo_)
{
    extern __shared__ char smc[];
    __shared__ float biasS[256];
    __shared__ int rowS[128];

    constexpr int STG  = 49152;
    constexpr int NTB  = IS_G1 ? 16 : 4;
    constexpr int KTB  = IS_G1 ? 64 : 32;
    constexpr int NIT  = IS_G1 ? (FEAT/64) : (HID/64);
    const int n_nat = g_cnt[0], n_oth = g_cnt[1];
    const int nat_tiles = (n_nat + 127) >> 7;
    const int bm = blockIdx.y, bnb = blockIdx.x;
    int grp, prow0, nrows;
    if (bm < nat_tiles) { grp = 0; prow0 = bm << 7; nrows = min(128, n_nat - prow0); }
    else {
        int bm2 = bm - nat_tiles;
        if ((bm2 << 7) >= n_oth) return;
        grp = 1; prow0 = (nat_tiles + bm2) << 7; nrows = min(128, n_oth - (bm2 << 7));
    }
    const int t = threadIdx.x;
    biasS[t] = (grp ? bo_ : bn_)[(bnb << 8) + t];
    if (t < 128) rowS[t] = (t < nrows) ? g_pos2row[prow0 + t] : -1;
    __syncthreads();

    const uint32_t sb = smem_u32(smc);
    const char* Asrc = IS_G1 ? (const char*)g_A : (const char*)g_H;
    const size_t rowE = IS_G1 ? FEAT : HID;
    const char* Wsrc = IS_G1 ? (const char*)g_W1 : (const char*)g_W2;

    auto issue = [&](int s, int it) {
        uint32_t base = sb + s * STG;
        #pragma unroll
        for (int i = 0; i < 4; i++) {
            int cid = i * 256 + t;
            int r = cid >> 3, c = cid & 7;
            uint32_t off = (uint32_t)((r * 128 + c * 16) ^ ((r & 7) << 4));
            size_t so = ((size_t)(prow0 + r) * rowE + it * 64 + c * 8) * 2;
            cpa16(base + off, Asrc + so);
        }
        size_t tb0 = ((size_t)((grp * NTB + bnb * 2 + 0) * KTB + it)) << 14;
        size_t tb1 = ((size_t)((grp * NTB + bnb * 2 + 1) * KTB + it)) << 14;
        #pragma unroll
        for (int i = 0; i < 8; i++) {
            int cid = i * 256 + t;
            int ti = cid >> 10, j = cid & 1023;
            const char* sp = Wsrc + (ti ? tb1 : tb0) + (size_t)j * 16;
            cpa16(base + 16384 + ti * 16384 + j * 16, sp);
        }
    };

    const int w = t >> 5, lane = t & 31;
    const int wm = w >> 2, wn = w & 3;
    const int lr = lane & 7, gq = lane >> 3;
    int preA[4], rxA[4], preB[4], rxB[4];
    #pragma unroll
    for (int mf = 0; mf < 4; mf++) {
        int row = wm * 64 + mf * 16 + (gq & 1) * 8 + lr;
        preA[mf] = row * 128 + (gq >> 1) * 16;
        rxA[mf]  = (row & 7) << 4;
    }
    #pragma unroll
    for (int p = 0; p < 4; p++) {
        int n = wn * 64 + p * 16 + (gq >> 1) * 8 + lr;
        preB[p] = ((n >> 7) << 14) + (n & 127) * 128 + (gq & 1) * 16;
        rxB[p]  = (n & 7) << 4;
    }

    float acc[4][8][4];
    #pragma unroll
    for (int i = 0; i < 4; i++)
        #pragma unroll
        for (int j = 0; j < 8; j++)
            #pragma unroll
            for (int e = 0; e < 4; e++) acc[i][j][e] = 0.f;

    issue(0, 0); CPCOMMIT();
    for (int it = 0; it < NIT; it++) {
        int b = it & 1;
        if (it + 1 < NIT) { issue(b ^ 1, it + 1); CPCOMMIT(); CPWAIT1(); }
        else              { CPWAIT0(); }
        __syncthreads();
        uint32_t sA = sb + b * STG, sW = sA + 16384;
        #pragma unroll
        for (int k16 = 0; k16 < 4; k16++) {
            int kb = k16 * 32;
            uint32_t a[4][4], bb[8][2];
            #pragma unroll
            for (int mf = 0; mf < 4; mf++) ldsm4(a[mf], sA + (uint32_t)((preA[mf] + kb) ^ rxA[mf]));
            #pragma unroll
            for (int p = 0; p < 4; p++) {
                uint32_t r[4];
                ldsm4(r, sW + (uint32_t)((preB[p] + kb) ^ rxB[p]));
                bb[2*p][0]=r[0]; bb[2*p][1]=r[1]; bb[2*p+1][0]=r[2]; bb[2*p+1][1]=r[3];
            }
            #pragma unroll
            for (int mf = 0; mf < 4; mf++)
                #pragma unroll
                for (int nf = 0; nf < 8; nf++) mma_h(acc[mf][nf], a[mf], bb[nf]);
        }
        __syncthreads();
    }

    // epilogue
    #pragma unroll
    for (int mf = 0; mf < 4; mf++) {
        #pragma unroll
        for (int half = 0; half < 2; half++) {
            int row = wm * 64 + mf * 16 + (lane >> 2) + half * 8;
            if (IS_G1) {
                size_t base = (size_t)(prow0 + row) * HID + (bnb << 8);
                #pragma unroll
                for (int nf = 0; nf < 8; nf++) {
                    int n = wn * 64 + nf * 8 + (lane & 3) * 2;
                    float v0 = fmaxf(acc[mf][nf][half*2+0] + biasS[n],     0.f);
                    float v1 = fmaxf(acc[mf][nf][half*2+1] + biasS[n + 1], 0.f);
                    __half2 p = __floats2half2_rn(v0, v1);
                    *(uint32_t*)((char*)g_H + (base + n) * 2) = *reinterpret_cast<uint32_t*>(&p);
                }
            } else {
                int orig = rowS[row];
                if (orig >= 0) {
                    float* zp = g_Z + (size_t)orig * PROJ + (bnb << 8);
                    #pragma unroll
                    for (int nf = 0; nf < 8; nf++) {
                        int n = wn * 64 + nf * 8 + (lane & 3) * 2;
                        float2 v;
                        v.x = acc[mf][nf][half*2+0] + biasS[n];
                        v.y = acc[mf][nf][half*2+1] + biasS[n + 1];
                        *(float2*)(zp + n) = v;
                    }
                }
            }
        }
    }
}

// ---------- finalize: norm, z_normalized, logits ----------
__global__ __launch_bounds__(128) void k_final(
    const float* __restrict__ x,
    const float* __restrict__ Wcn, const float* __restrict__ bcn,
    const float* __restrict__ Wco, const float* __restrict__ bco,
    float* __restrict__ out)
{
    const int row = blockIdx.x;
    const bool nat = x[(size_t)row * XLD + FEAT] > 0.5f;
    const float* __restrict__ Wc = nat ? Wcn : Wco;
    const float* __restrict__ bc = nat ? bcn : bco;
    const int t = threadIdx.x;
    const float* zr = g_Z + (size_t)row * PROJ;

    float zv[4];
    float ss = 0.f, l0 = 0.f, l1 = 0.f, l2 = 0.f;
    #pragma unroll
    for (int i = 0; i < 4; i++) {
        const int k = t + i * 128;
        const float z = zr[k];
        zv[i] = z;
        ss = fmaf(z, z, ss);
        const float rz = fmaxf(z, 0.f);
        l0 = fmaf(rz, Wc[k*3+0], l0);
        l1 = fmaf(rz, Wc[k*3+1], l1);
        l2 = fmaf(rz, Wc[k*3+2], l2);
    }
    #pragma unroll
    for (int o = 16; o > 0; o >>= 1) {
        ss += __shfl_down_sync(0xFFFFFFFFu, ss, o);
        l0 += __shfl_down_sync(0xFFFFFFFFu, l0, o);
        l1 += __shfl_down_sync(0xFFFFFFFFu, l1, o);
        l2 += __shfl_down_sync(0xFFFFFFFFu, l2, o);
    }
    __shared__ float red[4][4];
    __shared__ float inv_s;
    const int w = t >> 5, lane = t & 31;
    if (lane == 0) { red[w][0]=ss; red[w][1]=l0; red[w][2]=l1; red[w][3]=l2; }
    __syncthreads();
    if (t == 0) {
        float S  = red[0][0]+red[1][0]+red[2][0]+red[3][0];
        float L0 = red[0][1]+red[1][1]+red[2][1]+red[3][1];
        float L1 = red[0][2]+red[1][2]+red[2][2]+red[3][2];
        float L2 = red[0][3]+red[1][3]+red[2][3]+red[3][3];
        inv_s = 1.f / fmaxf(sqrtf(S), 1e-12f);
        float* lg = out + (size_t)B_ * PROJ + (size_t)row * NOUT;
        lg[0] = L0 + bc[0]; lg[1] = L1 + bc[1]; lg[2] = L2 + bc[2];
    }
    __syncthreads();
    const float inv = inv_s;
    #pragma unroll
    for (int i = 0; i < 4; i++)
        out[(size_t)row * PROJ + t + i * 128] = zv[i] * inv;
}

// ---------- launcher ----------
extern "C" void kernel_launch(void* const* d_in, const int* in_sizes, int n_in,
                              void* d_out, int out_size) {
    const float* x   = (const float*)d_in[0];
    const float* W1n = (const float*)d_in[1];
    const float* b1n = (const float*)d_in[2];
    const float* W2n = (const float*)d_in[3];
    const float* b2n = (const float*)d_in[4];
    const float* Wcn = (const float*)d_in[5];
    const float* bcn = (const float*)d_in[6];
    const float* W1o = (const float*)d_in[7];
    const float* b1o = (const float*)d_in[8];
    const float* W2o = (const float*)d_in[9];
    const float* b2o = (const float*)d_in[10];
    const float* Wco = (const float*)d_in[11];
    const float* bco = (const float*)d_in[12];
    float* out = (float*)d_out;

    cudaFuncSetAttribute(gemm_mma<1>, cudaFuncAttributeMaxDynamicSharedMemorySize, 2*49152);
    cudaFuncSetAttribute(gemm_mma<0>, cudaFuncAttributeMaxDynamicSharedMemorySize, 2*49152);

    k_zero<<<1, 1>>>();
    k_count<<<B_ / 256, 256>>>(x);
    k_assign<<<B_ / 256, 256>>>(x);
    k_convA<<<APAD, 256>>>(x);
    prep_w1<<<8192, 256>>>(W1n, W1o);
    prep_w2<<<1024, 256>>>(W2n, W2o);

    gemm_mma<1><<<dim3(8, TILES_M), 256, 2*49152>>>(b1n, b1o);
    gemm_mma<0><<<dim3(2, TILES_M), 256, 2*49152>>>(b2n, b2o);

    k_final<<<B_, 128>>>(x, Wcn, bcn, Wco, bco, out);
}

// round 8
// speedup vs baseline: 8.4697x; 1.0141x over previous
#include <cuda_runtime.h>
#include <cuda_fp16.h>
#include <cstdint>

#define B_   32768
#define FEAT 4096
#define XLD  4097
#define HID  2048
#define PROJ 512
#define NOUT 3
#define APAD (B_ + 256)
#define TILES_M 258

// ---------- device scratch ----------
__device__ int g_cnt[2];
__device__ int g_cnt2[2];
__device__ int g_pos2row[APAD];
__device__ float g_Z[(size_t)B_ * PROJ];
__device__ __half g_A[(size_t)APAD * FEAT];      // fp16 x features, permuted rows
__device__ __half g_H[(size_t)APAD * HID];       // fp16 hidden
__device__ __half g_W1[(size_t)2 * 16 * 64 * 8192];   // fp16, [N][K] tile-linear SW128
__device__ __half g_W2[(size_t)2 * 4 * 32 * 8192];

// ---------- helpers ----------
__device__ __forceinline__ uint32_t smem_u32(const void* p) {
    uint32_t a;
    asm("{ .reg .u64 t; cvta.to.shared.u64 t, %1; cvt.u32.u64 %0, t; }" : "=r"(a) : "l"(p));
    return a;
}
__device__ __forceinline__ void cpa16(uint32_t d, const void* s) {
    asm volatile("cp.async.cg.shared.global [%0], [%1], 16;" :: "r"(d), "l"(s));
}
#define CPCOMMIT() asm volatile("cp.async.commit_group;" ::: "memory")
#define CPWAIT0()  asm volatile("cp.async.wait_group 0;" ::: "memory")
#define CPWAIT1()  asm volatile("cp.async.wait_group 1;" ::: "memory")
__device__ __forceinline__ void ldsm4(uint32_t* r, uint32_t a) {
    asm volatile("ldmatrix.sync.aligned.m8n8.x4.shared.b16 {%0,%1,%2,%3}, [%4];"
                 : "=r"(r[0]), "=r"(r[1]), "=r"(r[2]), "=r"(r[3]) : "r"(a));
}
__device__ __forceinline__ void mma_h(float* c, const uint32_t* a, const uint32_t* b) {
    asm volatile("mma.sync.aligned.m16n8k16.row.col.f32.f16.f16.f32 "
                 "{%0,%1,%2,%3}, {%4,%5,%6,%7}, {%8,%9}, {%0,%1,%2,%3};"
                 : "+f"(c[0]), "+f"(c[1]), "+f"(c[2]), "+f"(c[3])
                 : "r"(a[0]), "r"(a[1]), "r"(a[2]), "r"(a[3]), "r"(b[0]), "r"(b[1]));
}

// ---------- partition ----------
__global__ void k_zero() { g_cnt[0]=0; g_cnt[1]=0; g_cnt2[0]=0; g_cnt2[1]=0; }
__global__ void k_count(const float* __restrict__ x) {
    int r = blockIdx.x * blockDim.x + threadIdx.x;
    if (r < B_) atomicAdd(&g_cnt[(x[(size_t)r*XLD+FEAT] > 0.5f) ? 0 : 1], 1);
}
__global__ void k_assign(const float* __restrict__ x) {
    int r = blockIdx.x * blockDim.x + threadIdx.x;
    if (r < B_) {
        int g = (x[(size_t)r*XLD+FEAT] > 0.5f) ? 0 : 1;
        int idx = atomicAdd(&g_cnt2[g], 1);
        int base_oth = ((g_cnt[0] + 127) >> 7) << 7;
        g_pos2row[g ? (base_oth + idx) : idx] = r;
    }
}

// ---------- A convert: gather + fp32 -> fp16, permuted rows, alignment-adaptive ----------
__global__ __launch_bounds__(256) void k_convA(const float* __restrict__ x) {
    int pos = blockIdx.x;
    int natPad = ((g_cnt[0] + 127) & ~127);
    bool valid = (pos < natPad) ? (pos < g_cnt[0]) : ((pos - natPad) < g_cnt[1]);
    int t = threadIdx.x;
    size_t db = ((size_t)pos * FEAT + t * 16) * 2;   // byte offset (fp16)
    uint4 h0 = {0,0,0,0}, h1 = {0,0,0,0};
    if (valid) {
        int orig = g_pos2row[pos];
        const float* src = x + (size_t)orig * XLD + t * 16;
        float v[16];
        if (!(orig & 3)) {                 // 16B-aligned rows: uint4
            #pragma unroll
            for (int q = 0; q < 4; q++) {
                float4 f = __ldg((const float4*)(src + q * 4));
                v[q*4] = f.x; v[q*4+1] = f.y; v[q*4+2] = f.z; v[q*4+3] = f.w;
            }
        } else if (!(orig & 1)) {          // 8B-aligned: float2
            #pragma unroll
            for (int q = 0; q < 8; q++) {
                float2 f = __ldg((const float2*)(src + q * 2));
                v[q*2] = f.x; v[q*2+1] = f.y;
            }
        } else {                           // scalar
            #pragma unroll
            for (int q = 0; q < 16; q++) v[q] = __ldg(src + q);
        }
        uint32_t* p0 = (uint32_t*)&h0;
        uint32_t* p1 = (uint32_t*)&h1;
        #pragma unroll
        for (int e = 0; e < 4; e++) {
            __half2 a = __floats2half2_rn(v[2*e],     v[2*e+1]);
            __half2 b = __floats2half2_rn(v[8+2*e],   v[8+2*e+1]);
            p0[e] = *reinterpret_cast<uint32_t*>(&a);
            p1[e] = *reinterpret_cast<uint32_t*>(&b);
        }
    }
    *(uint4*)((char*)g_A + db)      = h0;
    *(uint4*)((char*)g_A + db + 16) = h1;
}

// ---------- W prepack: fp32 [K][N] -> fp16, [N][K] tile-linear SW128 ----------
__global__ __launch_bounds__(256) void prep_w1(const float* __restrict__ Wn, const float* __restrict__ Wo) {
    int tid = blockIdx.x * 256 + threadIdx.x;      // 2*512*2048
    int n = tid & 2047, rest = tid >> 11;
    int ko = rest & 511, g = rest >> 9;
    const float* src = g ? Wo : Wn;
    uint4 hv;
    uint32_t* hp = (uint32_t*)&hv;
    #pragma unroll
    for (int e = 0; e < 4; e++) {
        __half2 p = __floats2half2_rn(__ldg(src + (size_t)(ko*8 + 2*e) * HID + n),
                                      __ldg(src + (size_t)(ko*8 + 2*e + 1) * HID + n));
        hp[e] = *reinterpret_cast<uint32_t*>(&p);
    }
    int nt = n >> 7, rIn = n & 127, kt = ko >> 3, cb = ko & 7;
    size_t tb = ((size_t)(((g << 4) + nt) * 64 + kt)) << 14;
    uint32_t sw = (uint32_t)(rIn * 128 + (cb << 4)) ^ ((uint32_t)(rIn & 7) << 4);
    *(uint4*)((char*)g_W1 + tb + sw) = hv;
}
__global__ __launch_bounds__(256) void prep_w2(const float* __restrict__ Wn, const float* __restrict__ Wo) {
    int tid = blockIdx.x * 256 + threadIdx.x;      // 2*256*512
    int n = tid & 511, rest = tid >> 9;
    int ko = rest & 255, g = rest >> 8;
    const float* src = g ? Wo : Wn;
    uint4 hv;
    uint32_t* hp = (uint32_t*)&hv;
    #pragma unroll
    for (int e = 0; e < 4; e++) {
        __half2 p = __floats2half2_rn(__ldg(src + (size_t)(ko*8 + 2*e) * PROJ + n),
                                      __ldg(src + (size_t)(ko*8 + 2*e + 1) * PROJ + n));
        hp[e] = *reinterpret_cast<uint32_t*>(&p);
    }
    int nt = n >> 7, rIn = n & 127, kt = ko >> 3, cb = ko & 7;
    size_t tb = ((size_t)(((g << 2) + nt) * 32 + kt)) << 14;
    uint32_t sw = (uint32_t)(rIn * 128 + (cb << 4)) ^ ((uint32_t)(rIn & 7) << 4);
    *(uint4*)((char*)g_W2 + tb + sw) = hv;
}

// ---------- GEMM: M128 x N256 CTA, K-step 64, single fp16 mma ----------
template <int IS_G1>
__global__ __launch_bounds__(256, 1) void gemm_mma(
    const float* __restrict__ bn_, const float* __restrict__ bo_)
{
    extern __shared__ char smc[];
    __shared__ float biasS[256];
    __shared__ int rowS[128];

    constexpr int STG  = 49152;
    constexpr int NTB  = IS_G1 ? 16 : 4;
    constexpr int KTB  = IS_G1 ? 64 : 32;
    constexpr int NIT  = IS_G1 ? (FEAT/64) : (HID/64);
    const int n_nat = g_cnt[0], n_oth = g_cnt[1];
    const int nat_tiles = (n_nat + 127) >> 7;
    const int bm = blockIdx.y, bnb = blockIdx.x;
    int grp, prow0, nrows;
    if (bm < nat_tiles) { grp = 0; prow0 = bm << 7; nrows = min(128, n_nat - prow0); }
    else {
        int bm2 = bm - nat_tiles;
        if ((bm2 << 7) >= n_oth) return;
        grp = 1; prow0 = (nat_tiles + bm2) << 7; nrows = min(128, n_oth - (bm2 << 7));
    }
    const int t = threadIdx.x;
    biasS[t] = (grp ? bo_ : bn_)[(bnb << 8) + t];
    if (t < 128) rowS[t] = (t < nrows) ? g_pos2row[prow0 + t] : -1;
    __syncthreads();

    const uint32_t sb = smem_u32(smc);
    const char* Asrc = IS_G1 ? (const char*)g_A : (const char*)g_H;
    const size_t rowE = IS_G1 ? FEAT : HID;
    const char* Wsrc = IS_G1 ? (const char*)g_W1 : (const char*)g_W2;

    auto issue = [&](int s, int it) {
        uint32_t base = sb + s * STG;
        #pragma unroll
        for (int i = 0; i < 4; i++) {
            int cid = i * 256 + t;
            int r = cid >> 3, c = cid & 7;
            uint32_t off = (uint32_t)((r * 128 + c * 16) ^ ((r & 7) << 4));
            size_t so = ((size_t)(prow0 + r) * rowE + it * 64 + c * 8) * 2;
            cpa16(base + off, Asrc + so);
        }
        size_t tb0 = ((size_t)((grp * NTB + bnb * 2 + 0) * KTB + it)) << 14;
        size_t tb1 = ((size_t)((grp * NTB + bnb * 2 + 1) * KTB + it)) << 14;
        #pragma unroll
        for (int i = 0; i < 8; i++) {
            int cid = i * 256 + t;
            int ti = cid >> 10, j = cid & 1023;
            const char* sp = Wsrc + (ti ? tb1 : tb0) + (size_t)j * 16;
            cpa16(base + 16384 + ti * 16384 + j * 16, sp);
        }
    };

    const int w = t >> 5, lane = t & 31;
    const int wm = w >> 2, wn = w & 3;
    const int lr = lane & 7, gq = lane >> 3;
    int preA[4], rxA[4], preB[4], rxB[4];
    #pragma unroll
    for (int mf = 0; mf < 4; mf++) {
        int row = wm * 64 + mf * 16 + (gq & 1) * 8 + lr;
        preA[mf] = row * 128 + (gq >> 1) * 16;
        rxA[mf]  = (row & 7) << 4;
    }
    #pragma unroll
    for (int p = 0; p < 4; p++) {
        int n = wn * 64 + p * 16 + (gq >> 1) * 8 + lr;
        preB[p] = ((n >> 7) << 14) + (n & 127) * 128 + (gq & 1) * 16;
        rxB[p]  = (n & 7) << 4;
    }

    float acc[4][8][4];
    #pragma unroll
    for (int i = 0; i < 4; i++)
        #pragma unroll
        for (int j = 0; j < 8; j++)
            #pragma unroll
            for (int e = 0; e < 4; e++) acc[i][j][e] = 0.f;

    issue(0, 0); CPCOMMIT();
    for (int it = 0; it < NIT; it++) {
        int b = it & 1;
        if (it + 1 < NIT) { issue(b ^ 1, it + 1); CPCOMMIT(); CPWAIT1(); }
        else              { CPWAIT0(); }
        __syncthreads();
        uint32_t sA = sb + b * STG, sW = sA + 16384;
        #pragma unroll
        for (int k16 = 0; k16 < 4; k16++) {
            int kb = k16 * 32;
            uint32_t a[4][4], bb[8][2];
            #pragma unroll
            for (int mf = 0; mf < 4; mf++) ldsm4(a[mf], sA + (uint32_t)((preA[mf] + kb) ^ rxA[mf]));
            #pragma unroll
            for (int p = 0; p < 4; p++) {
                uint32_t r[4];
                ldsm4(r, sW + (uint32_t)((preB[p] + kb) ^ rxB[p]));
                bb[2*p][0]=r[0]; bb[2*p][1]=r[1]; bb[2*p+1][0]=r[2]; bb[2*p+1][1]=r[3];
            }
            #pragma unroll
            for (int mf = 0; mf < 4; mf++)
                #pragma unroll
                for (int nf = 0; nf < 8; nf++) mma_h(acc[mf][nf], a[mf], bb[nf]);
        }
        __syncthreads();
    }

    // epilogue
    #pragma unroll
    for (int mf = 0; mf < 4; mf++) {
        #pragma unroll
        for (int half = 0; half < 2; half++) {
            int row = wm * 64 + mf * 16 + (lane >> 2) + half * 8;
            if (IS_G1) {
                size_t base = (size_t)(prow0 + row) * HID + (bnb << 8);
                #pragma unroll
                for (int nf = 0; nf < 8; nf++) {
                    int n = wn * 64 + nf * 8 + (lane & 3) * 2;
                    float v0 = fmaxf(acc[mf][nf][half*2+0] + biasS[n],     0.f);
                    float v1 = fmaxf(acc[mf][nf][half*2+1] + biasS[n + 1], 0.f);
                    __half2 p = __floats2half2_rn(v0, v1);
                    *(uint32_t*)((char*)g_H + (base + n) * 2) = *reinterpret_cast<uint32_t*>(&p);
                }
            } else {
                int orig = rowS[row];
                if (orig >= 0) {
                    float* zp = g_Z + (size_t)orig * PROJ + (bnb << 8);
                    #pragma unroll
                    for (int nf = 0; nf < 8; nf++) {
                        int n = wn * 64 + nf * 8 + (lane & 3) * 2;
                        float2 v;
                        v.x = acc[mf][nf][half*2+0] + biasS[n];
                        v.y = acc[mf][nf][half*2+1] + biasS[n + 1];
                        *(float2*)(zp + n) = v;
                    }
                }
            }
        }
    }
}

// ---------- finalize: warp-per-row norm + logits ----------
__global__ __launch_bounds__(256) void k_final(
    const float* __restrict__ x,
    const float* __restrict__ Wcn, const float* __restrict__ bcn,
    const float* __restrict__ Wco, const float* __restrict__ bco,
    float* __restrict__ out)
{
    const int wid = threadIdx.x >> 5, lane = threadIdx.x & 31;
    const int row = blockIdx.x * 8 + wid;
    const bool nat = __ldg(x + (size_t)row * XLD + FEAT) > 0.5f;
    const float* __restrict__ Wc = nat ? Wcn : Wco;
    const float* __restrict__ bc = nat ? bcn : bco;
    const float* zr = g_Z + (size_t)row * PROJ;

    float4 zv[4];
    float ss = 0.f, l0 = 0.f, l1 = 0.f, l2 = 0.f;
    #pragma unroll
    for (int i = 0; i < 4; i++) {
        const int k = i * 128 + lane * 4;
        float4 z = __ldg((const float4*)(zr + k));
        zv[i] = z;
        ss += z.x*z.x + z.y*z.y + z.z*z.z + z.w*z.w;
        float r0 = fmaxf(z.x, 0.f), r1 = fmaxf(z.y, 0.f);
        float r2 = fmaxf(z.z, 0.f), r3 = fmaxf(z.w, 0.f);
        const float4 w0 = __ldg((const float4*)(Wc + k * 3));
        const float4 w1 = __ldg((const float4*)(Wc + k * 3 + 4));
        const float4 w2 = __ldg((const float4*)(Wc + k * 3 + 8));
        l0 += r0*w0.x + r1*w0.w + r2*w1.z + r3*w2.y;
        l1 += r0*w0.y + r1*w1.x + r2*w1.w + r3*w2.z;
        l2 += r0*w0.z + r1*w1.y + r2*w2.x + r3*w2.w;
    }
    #pragma unroll
    for (int o = 16; o > 0; o >>= 1) {
        ss += __shfl_xor_sync(0xFFFFFFFFu, ss, o);
        l0 += __shfl_xor_sync(0xFFFFFFFFu, l0, o);
        l1 += __shfl_xor_sync(0xFFFFFFFFu, l1, o);
        l2 += __shfl_xor_sync(0xFFFFFFFFu, l2, o);
    }
    if (lane == 0) {
        float* lg = out + (size_t)B_ * PROJ + (size_t)row * NOUT;
        lg[0] = l0 + bc[0]; lg[1] = l1 + bc[1]; lg[2] = l2 + bc[2];
    }
    const float inv = 1.f / fmaxf(sqrtf(ss), 1e-12f);
    float* op = out + (size_t)row * PROJ;
    #pragma unroll
    for (int i = 0; i < 4; i++) {
        float4 z = zv[i];
        z.x *= inv; z.y *= inv; z.z *= inv; z.w *= inv;
        *(float4*)(op + i * 128 + lane * 4) = z;
    }
}

// ---------- launcher ----------
extern "C" void kernel_launch(void* const* d_in, const int* in_sizes, int n_in,
                              void* d_out, int out_size) {
    const float* x   = (const float*)d_in[0];
    const float* W1n = (const float*)d_in[1];
    const float* b1n = (const float*)d_in[2];
    const float* W2n = (const float*)d_in[3];
    const float* b2n = (const float*)d_in[4];
    const float* Wcn = (const float*)d_in[5];
    const float* bcn = (const float*)d_in[6];
    const float* W1o = (const float*)d_in[7];
    const float* b1o = (const float*)d_in[8];
    const float* W2o = (const float*)d_in[9];
    const float* b2o = (const float*)d_in[10];
    const float* Wco = (const float*)d_in[11];
    const float* bco = (const float*)d_in[12];
    float* out = (float*)d_out;

    cudaFuncSetAttribute(gemm_mma<1>, cudaFuncAttributeMaxDynamicSharedMemorySize, 2*49152);
    cudaFuncSetAttribute(gemm_mma<0>, cudaFuncAttributeMaxDynamicSharedMemorySize, 2*49152);

    k_zero<<<1, 1>>>();
    k_count<<<B_ / 256, 256>>>(x);
    k_assign<<<B_ / 256, 256>>>(x);
    k_convA<<<APAD, 256>>>(x);
    prep_w1<<<8192, 256>>>(W1n, W1o);
    prep_w2<<<1024, 256>>>(W2n, W2o);

    gemm_mma<1><<<dim3(8, TILES_M), 256, 2*49152>>>(b1n, b1o);
    gemm_mma<0><<<dim3(2, TILES_M), 256, 2*49152>>>(b2n, b2o);

    k_final<<<B_ / 8, 256>>>(x, Wcn, bcn, Wco, bco, out);
}

// round 9
// speedup vs baseline: 8.7890x; 1.0377x over previous
#include <cuda_runtime.h>
#include <cuda_fp16.h>
#include <cstdint>

#define B_   32768
#define FEAT 4096
#define XLD  4097
#define HID  2048
#define PROJ 512
#define NOUT 3
#define APAD (B_ + 256)
#define TILES_M 258

// ---------- device scratch ----------
__device__ int g_cnt[2];
__device__ int g_cnt2[2];
__device__ int g_pos2row[APAD];
__device__ float g_Z[(size_t)B_ * PROJ];
__device__ __half g_A[(size_t)APAD * FEAT];      // fp16 x features, permuted rows
__device__ __half g_H[(size_t)APAD * HID];       // fp16 hidden
__device__ __half g_W1[(size_t)2 * 16 * 64 * 8192];   // fp16, [N][K] tile-linear SW128
__device__ __half g_W2[(size_t)2 * 4 * 32 * 8192];

// ---------- helpers ----------
__device__ __forceinline__ uint32_t smem_u32(const void* p) {
    uint32_t a;
    asm("{ .reg .u64 t; cvta.to.shared.u64 t, %1; cvt.u32.u64 %0, t; }" : "=r"(a) : "l"(p));
    return a;
}
__device__ __forceinline__ void cpa16(uint32_t d, const void* s) {
    asm volatile("cp.async.cg.shared.global [%0], [%1], 16;" :: "r"(d), "l"(s));
}
#define CPCOMMIT() asm volatile("cp.async.commit_group;" ::: "memory")
#define CPWAIT0()  asm volatile("cp.async.wait_group 0;" ::: "memory")
#define CPWAIT1()  asm volatile("cp.async.wait_group 1;" ::: "memory")
__device__ __forceinline__ void ldsm4(uint32_t* r, uint32_t a) {
    asm volatile("ldmatrix.sync.aligned.m8n8.x4.shared.b16 {%0,%1,%2,%3}, [%4];"
                 : "=r"(r[0]), "=r"(r[1]), "=r"(r[2]), "=r"(r[3]) : "r"(a));
}
__device__ __forceinline__ void mma_h(float* c, const uint32_t* a, const uint32_t* b) {
    asm volatile("mma.sync.aligned.m16n8k16.row.col.f32.f16.f16.f32 "
                 "{%0,%1,%2,%3}, {%4,%5,%6,%7}, {%8,%9}, {%0,%1,%2,%3};"
                 : "+f"(c[0]), "+f"(c[1]), "+f"(c[2]), "+f"(c[3])
                 : "r"(a[0]), "r"(a[1]), "r"(a[2]), "r"(a[3]), "r"(b[0]), "r"(b[1]));
}

// ---------- partition (g_cnt/g_cnt2 reset by k_final for next replay) ----------
__global__ void k_count(const float* __restrict__ x) {
    int r = blockIdx.x * blockDim.x + threadIdx.x;
    if (r < B_) atomicAdd(&g_cnt[(x[(size_t)r*XLD+FEAT] > 0.5f) ? 0 : 1], 1);
}
__global__ void k_assign(const float* __restrict__ x) {
    int r = blockIdx.x * blockDim.x + threadIdx.x;
    if (r < B_) {
        int g = (x[(size_t)r*XLD+FEAT] > 0.5f) ? 0 : 1;
        int idx = atomicAdd(&g_cnt2[g], 1);
        int base_oth = ((g_cnt[0] + 127) >> 7) << 7;
        g_pos2row[g ? (base_oth + idx) : idx] = r;
    }
}

// ---------- A convert: gather + fp32 -> fp16; uniform-branch aligned realign ----------
__global__ __launch_bounds__(256) void k_convA(const float* __restrict__ x) {
    int pos = blockIdx.x;
    int natPad = ((g_cnt[0] + 127) & ~127);
    bool valid = (pos < natPad) ? (pos < g_cnt[0]) : ((pos - natPad) < g_cnt[1]);
    int t = threadIdx.x;
    size_t db = ((size_t)pos * FEAT + t * 16) * 2;   // byte offset (fp16)
    uint4 h0 = {0,0,0,0}, h1 = {0,0,0,0};
    if (valid) {
        int orig = g_pos2row[pos];
        int m = orig & 3;                 // block-uniform misalignment (XLD ≡ 1 mod 4)
        const float* base = x + (size_t)orig * XLD + t * 16 - m;
        float f[20];
        float v[16];
        if (m == 0) {
            #pragma unroll
            for (int q = 0; q < 4; q++) *(float4*)(f + 4*q) = __ldg((const float4*)(base + 4*q));
            #pragma unroll
            for (int j = 0; j < 16; j++) v[j] = f[j];
        } else {
            // 5 aligned float4 cover [base, base+20); select [m, m+16) statically.
            // In-bounds: worst case t=255 on the last row has m=3 (orig=32767), ending exactly at x's end.
            #pragma unroll
            for (int q = 0; q < 5; q++) *(float4*)(f + 4*q) = __ldg((const float4*)(base + 4*q));
            if (m == 1) {
                #pragma unroll
                for (int j = 0; j < 16; j++) v[j] = f[j + 1];
            } else if (m == 2) {
                #pragma unroll
                for (int j = 0; j < 16; j++) v[j] = f[j + 2];
            } else {
                #pragma unroll
                for (int j = 0; j < 16; j++) v[j] = f[j + 3];
            }
        }
        uint32_t* p0 = (uint32_t*)&h0;
        uint32_t* p1 = (uint32_t*)&h1;
        #pragma unroll
        for (int e = 0; e < 4; e++) {
            __half2 a = __floats2half2_rn(v[2*e],   v[2*e+1]);
            __half2 b = __floats2half2_rn(v[8+2*e], v[8+2*e+1]);
            p0[e] = *reinterpret_cast<uint32_t*>(&a);
            p1[e] = *reinterpret_cast<uint32_t*>(&b);
        }
    }
    *(uint4*)((char*)g_A + db)      = h0;
    *(uint4*)((char*)g_A + db + 16) = h1;
}

// ---------- W prepack: fp32 [K][N] -> fp16, [N][K] tile-linear SW128 ----------
__global__ __launch_bounds__(256) void prep_w1(const float* __restrict__ Wn, const float* __restrict__ Wo) {
    int tid = blockIdx.x * 256 + threadIdx.x;      // 2*512*2048
    int n = tid & 2047, rest = tid >> 11;
    int ko = rest & 511, g = rest >> 9;
    const float* src = g ? Wo : Wn;
    uint4 hv;
    uint32_t* hp = (uint32_t*)&hv;
    #pragma unroll
    for (int e = 0; e < 4; e++) {
        __half2 p = __floats2half2_rn(__ldg(src + (size_t)(ko*8 + 2*e) * HID + n),
                                      __ldg(src + (size_t)(ko*8 + 2*e + 1) * HID + n));
        hp[e] = *reinterpret_cast<uint32_t*>(&p);
    }
    int nt = n >> 7, rIn = n & 127, kt = ko >> 3, cb = ko & 7;
    size_t tb = ((size_t)(((g << 4) + nt) * 64 + kt)) << 14;
    uint32_t sw = (uint32_t)(rIn * 128 + (cb << 4)) ^ ((uint32_t)(rIn & 7) << 4);
    *(uint4*)((char*)g_W1 + tb + sw) = hv;
}
__global__ __launch_bounds__(256) void prep_w2(const float* __restrict__ Wn, const float* __restrict__ Wo) {
    int tid = blockIdx.x * 256 + threadIdx.x;      // 2*256*512
    int n = tid & 511, rest = tid >> 9;
    int ko = rest & 255, g = rest >> 8;
    const float* src = g ? Wo : Wn;
    uint4 hv;
    uint32_t* hp = (uint32_t*)&hv;
    #pragma unroll
    for (int e = 0; e < 4; e++) {
        __half2 p = __floats2half2_rn(__ldg(src + (size_t)(ko*8 + 2*e) * PROJ + n),
                                      __ldg(src + (size_t)(ko*8 + 2*e + 1) * PROJ + n));
        hp[e] = *reinterpret_cast<uint32_t*>(&p);
    }
    int nt = n >> 7, rIn = n & 127, kt = ko >> 3, cb = ko & 7;
    size_t tb = ((size_t)(((g << 2) + nt) * 32 + kt)) << 14;
    uint32_t sw = (uint32_t)(rIn * 128 + (cb << 4)) ^ ((uint32_t)(rIn & 7) << 4);
    *(uint4*)((char*)g_W2 + tb + sw) = hv;
}

// ---------- GEMM: M128 x N256 CTA, K-step 64, single fp16 mma ----------
template <int IS_G1>
__global__ __launch_bounds__(256, 1) void gemm_mma(
    const float* __restrict__ bn_, const float* __restrict__ bo_)
{
    extern __shared__ char smc[];
    __shared__ float biasS[256];
    __shared__ int rowS[128];

    constexpr int STG  = 49152;
    constexpr int NTB  = IS_G1 ? 16 : 4;
    constexpr int KTB  = IS_G1 ? 64 : 32;
    constexpr int NIT  = IS_G1 ? (FEAT/64) : (HID/64);
    const int n_nat = g_cnt[0], n_oth = g_cnt[1];
    const int nat_tiles = (n_nat + 127) >> 7;
    const int bm = blockIdx.y, bnb = blockIdx.x;
    int grp, prow0, nrows;
    if (bm < nat_tiles) { grp = 0; prow0 = bm << 7; nrows = min(128, n_nat - prow0); }
    else {
        int bm2 = bm - nat_tiles;
        if ((bm2 << 7) >= n_oth) return;
        grp = 1; prow0 = (nat_tiles + bm2) << 7; nrows = min(128, n_oth - (bm2 << 7));
    }
    const int t = threadIdx.x;
    biasS[t] = (grp ? bo_ : bn_)[(bnb << 8) + t];
    if (t < 128) rowS[t] = (t < nrows) ? g_pos2row[prow0 + t] : -1;
    __syncthreads();

    const uint32_t sb = smem_u32(smc);
    const char* Asrc = IS_G1 ? (const char*)g_A : (const char*)g_H;
    const size_t rowE = IS_G1 ? FEAT : HID;
    const char* Wsrc = IS_G1 ? (const char*)g_W1 : (const char*)g_W2;

    auto issue = [&](int s, int it) {
        uint32_t base = sb + s * STG;
        #pragma unroll
        for (int i = 0; i < 4; i++) {
            int cid = i * 256 + t;
            int r = cid >> 3, c = cid & 7;
            uint32_t off = (uint32_t)((r * 128 + c * 16) ^ ((r & 7) << 4));
            size_t so = ((size_t)(prow0 + r) * rowE + it * 64 + c * 8) * 2;
            cpa16(base + off, Asrc + so);
        }
        size_t tb0 = ((size_t)((grp * NTB + bnb * 2 + 0) * KTB + it)) << 14;
        size_t tb1 = ((size_t)((grp * NTB + bnb * 2 + 1) * KTB + it)) << 14;
        #pragma unroll
        for (int i = 0; i < 8; i++) {
            int cid = i * 256 + t;
            int ti = cid >> 10, j = cid & 1023;
            const char* sp = Wsrc + (ti ? tb1 : tb0) + (size_t)j * 16;
            cpa16(base + 16384 + ti * 16384 + j * 16, sp);
        }
    };

    const int w = t >> 5, lane = t & 31;
    const int wm = w >> 2, wn = w & 3;
    const int lr = lane & 7, gq = lane >> 3;
    int preA[4], rxA[4], preB[4], rxB[4];
    #pragma unroll
    for (int mf = 0; mf < 4; mf++) {
        int row = wm * 64 + mf * 16 + (gq & 1) * 8 + lr;
        preA[mf] = row * 128 + (gq >> 1) * 16;
        rxA[mf]  = (row & 7) << 4;
    }
    #pragma unroll
    for (int p = 0; p < 4; p++) {
        int n = wn * 64 + p * 16 + (gq >> 1) * 8 + lr;
        preB[p] = ((n >> 7) << 14) + (n & 127) * 128 + (gq & 1) * 16;
        rxB[p]  = (n & 7) << 4;
    }

    float acc[4][8][4];
    #pragma unroll
    for (int i = 0; i < 4; i++)
        #pragma unroll
        for (int j = 0; j < 8; j++)
            #pragma unroll
            for (int e = 0; e < 4; e++) acc[i][j][e] = 0.f;

    issue(0, 0); CPCOMMIT();
    for (int it = 0; it < NIT; it++) {
        int b = it & 1;
        if (it + 1 < NIT) { issue(b ^ 1, it + 1); CPCOMMIT(); CPWAIT1(); }
        else              { CPWAIT0(); }
        __syncthreads();
        uint32_t sA = sb + b * STG, sW = sA + 16384;
        #pragma unroll
        for (int k16 = 0; k16 < 4; k16++) {
            int kb = k16 * 32;
            uint32_t a[4][4], bb[8][2];
            #pragma unroll
            for (int mf = 0; mf < 4; mf++) ldsm4(a[mf], sA + (uint32_t)((preA[mf] + kb) ^ rxA[mf]));
            #pragma unroll
            for (int p = 0; p < 4; p++) {
                uint32_t r[4];
                ldsm4(r, sW + (uint32_t)((preB[p] + kb) ^ rxB[p]));
                bb[2*p][0]=r[0]; bb[2*p][1]=r[1]; bb[2*p+1][0]=r[2]; bb[2*p+1][1]=r[3];
            }
            #pragma unroll
            for (int mf = 0; mf < 4; mf++)
                #pragma unroll
                for (int nf = 0; nf < 8; nf++) mma_h(acc[mf][nf], a[mf], bb[nf]);
        }
        __syncthreads();
    }

    // epilogue
    #pragma unroll
    for (int mf = 0; mf < 4; mf++) {
        #pragma unroll
        for (int half = 0; half < 2; half++) {
            int row = wm * 64 + mf * 16 + (lane >> 2) + half * 8;
            if (IS_G1) {
                size_t base = (size_t)(prow0 + row) * HID + (bnb << 8);
                #pragma unroll
                for (int nf = 0; nf < 8; nf++) {
                    int n = wn * 64 + nf * 8 + (lane & 3) * 2;
                    float v0 = fmaxf(acc[mf][nf][half*2+0] + biasS[n],     0.f);
                    float v1 = fmaxf(acc[mf][nf][half*2+1] + biasS[n + 1], 0.f);
                    __half2 p = __floats2half2_rn(v0, v1);
                    *(uint32_t*)((char*)g_H + (base + n) * 2) = *reinterpret_cast<uint32_t*>(&p);
                }
            } else {
                int orig = rowS[row];
                if (orig >= 0) {
                    float* zp = g_Z + (size_t)orig * PROJ + (bnb << 8);
                    #pragma unroll
                    for (int nf = 0; nf < 8; nf++) {
                        int n = wn * 64 + nf * 8 + (lane & 3) * 2;
                        float2 v;
                        v.x = acc[mf][nf][half*2+0] + biasS[n];
                        v.y = acc[mf][nf][half*2+1] + biasS[n + 1];
                        *(float2*)(zp + n) = v;
                    }
                }
            }
        }
    }
}

// ---------- finalize: warp-per-row norm + logits; resets counters for next replay ----------
__global__ __launch_bounds__(256) void k_final(
    const float* __restrict__ x,
    const float* __restrict__ Wcn, const float* __restrict__ bcn,
    const float* __restrict__ Wco, const float* __restrict__ bco,
    float* __restrict__ out)
{
    if (blockIdx.x == 0 && threadIdx.x == 0) {
        g_cnt[0] = 0; g_cnt[1] = 0; g_cnt2[0] = 0; g_cnt2[1] = 0;
    }
    const int wid = threadIdx.x >> 5, lane = threadIdx.x & 31;
    const int row = blockIdx.x * 8 + wid;
    const bool nat = __ldg(x + (size_t)row * XLD + FEAT) > 0.5f;
    const float* __restrict__ Wc = nat ? Wcn : Wco;
    const float* __restrict__ bc = nat ? bcn : bco;
    const float* zr = g_Z + (size_t)row * PROJ;

    float4 zv[4];
    float ss = 0.f, l0 = 0.f, l1 = 0.f, l2 = 0.f;
    #pragma unroll
    for (int i = 0; i < 4; i++) {
        const int k = i * 128 + lane * 4;
        float4 z = __ldg((const float4*)(zr + k));
        zv[i] = z;
        ss += z.x*z.x + z.y*z.y + z.z*z.z + z.w*z.w;
        float r0 = fmaxf(z.x, 0.f), r1 = fmaxf(z.y, 0.f);
        float r2 = fmaxf(z.z, 0.f), r3 = fmaxf(z.w, 0.f);
        const float4 w0 = __ldg((const float4*)(Wc + k * 3));
        const float4 w1 = __ldg((const float4*)(Wc + k * 3 + 4));
        const float4 w2 = __ldg((const float4*)(Wc + k * 3 + 8));
        l0 += r0*w0.x + r1*w0.w + r2*w1.z + r3*w2.y;
        l1 += r0*w0.y + r1*w1.x + r2*w1.w + r3*w2.z;
        l2 += r0*w0.z + r1*w1.y + r2*w2.x + r3*w2.w;
    }
    #pragma unroll
    for (int o = 16; o > 0; o >>= 1) {
        ss += __shfl_xor_sync(0xFFFFFFFFu, ss, o);
        l0 += __shfl_xor_sync(0xFFFFFFFFu, l0, o);
        l1 += __shfl_xor_sync(0xFFFFFFFFu, l1, o);
        l2 += __shfl_xor_sync(0xFFFFFFFFu, l2, o);
    }
    if (lane == 0) {
        float* lg = out + (size_t)B_ * PROJ + (size_t)row * NOUT;
        lg[0] = l0 + bc[0]; lg[1] = l1 + bc[1]; lg[2] = l2 + bc[2];
    }
    const float inv = 1.f / fmaxf(sqrtf(ss), 1e-12f);
    float* op = out + (size_t)row * PROJ;
    #pragma unroll
    for (int i = 0; i < 4; i++) {
        float4 z = zv[i];
        z.x *= inv; z.y *= inv; z.z *= inv; z.w *= inv;
        *(float4*)(op + i * 128 + lane * 4) = z;
    }
}

// ---------- launcher ----------
extern "C" void kernel_launch(void* const* d_in, const int* in_sizes, int n_in,
                              void* d_out, int out_size) {
    const float* x   = (const float*)d_in[0];
    const float* W1n = (const float*)d_in[1];
    const float* b1n = (const float*)d_in[2];
    const float* W2n = (const float*)d_in[3];
    const float* b2n = (const float*)d_in[4];
    const float* Wcn = (const float*)d_in[5];
    const float* bcn = (const float*)d_in[6];
    const float* W1o = (const float*)d_in[7];
    const float* b1o = (const float*)d_in[8];
    const float* W2o = (const float*)d_in[9];
    const float* b2o = (const float*)d_in[10];
    const float* Wco = (const float*)d_in[11];
    const float* bco = (const float*)d_in[12];
    float* out = (float*)d_out;

    cudaFuncSetAttribute(gemm_mma<1>, cudaFuncAttributeMaxDynamicSharedMemorySize, 2*49152);
    cudaFuncSetAttribute(gemm_mma<0>, cudaFuncAttributeMaxDynamicSharedMemorySize, 2*49152);

    k_count<<<B_ / 256, 256>>>(x);
    k_assign<<<B_ / 256, 256>>>(x);
    k_convA<<<APAD, 256>>>(x);
    prep_w1<<<8192, 256>>>(W1n, W1o);
    prep_w2<<<1024, 256>>>(W2n, W2o);

    gemm_mma<1><<<dim3(8, TILES_M), 256, 2*49152>>>(b1n, b1o);
    gemm_mma<0><<<dim3(2, TILES_M), 256, 2*49152>>>(b2n, b2o);

    k_final<<<B_ / 8, 256>>>(x, Wcn, bcn, Wco, bco, out);
}

// round 10
// speedup vs baseline: 8.8902x; 1.0115x over previous
#include <cuda_runtime.h>
#include <cuda_fp16.h>
#include <cstdint>

#define B_   32768
#define FEAT 4096
#define XLD  4097
#define HID  2048
#define PROJ 512
#define NOUT 3
#define APAD (B_ + 256)
#define TILES_M 258

// ---------- device scratch ----------
__device__ int g_cnt2[2];
__device__ int g_pos2row[APAD];
__device__ float g_Z[(size_t)B_ * PROJ];
__device__ __half g_A[(size_t)APAD * FEAT];      // fp16 x features, permuted rows
__device__ __half g_H[(size_t)APAD * HID];       // fp16 hidden
__device__ __half g_W1[(size_t)2 * 16 * 64 * 8192];   // fp16, [N][K] tile-linear SW128
__device__ __half g_W2[(size_t)2 * 4 * 32 * 8192];

// ---------- helpers ----------
__device__ __forceinline__ uint32_t smem_u32(const void* p) {
    uint32_t a;
    asm("{ .reg .u64 t; cvta.to.shared.u64 t, %1; cvt.u32.u64 %0, t; }" : "=r"(a) : "l"(p));
    return a;
}
__device__ __forceinline__ void cpa16(uint32_t d, const void* s) {
    asm volatile("cp.async.cg.shared.global [%0], [%1], 16;" :: "r"(d), "l"(s));
}
#define CPCOMMIT() asm volatile("cp.async.commit_group;" ::: "memory")
#define CPWAIT0()  asm volatile("cp.async.wait_group 0;" ::: "memory")
#define CPWAIT1()  asm volatile("cp.async.wait_group 1;" ::: "memory")
__device__ __forceinline__ void ldsm4(uint32_t* r, uint32_t a) {
    asm volatile("ldmatrix.sync.aligned.m8n8.x4.shared.b16 {%0,%1,%2,%3}, [%4];"
                 : "=r"(r[0]), "=r"(r[1]), "=r"(r[2]), "=r"(r[3]) : "r"(a));
}
__device__ __forceinline__ void mma_h(float* c, const uint32_t* a, const uint32_t* b) {
    asm volatile("mma.sync.aligned.m16n8k16.row.col.f32.f16.f16.f32 "
                 "{%0,%1,%2,%3}, {%4,%5,%6,%7}, {%8,%9}, {%0,%1,%2,%3};"
                 : "+f"(c[0]), "+f"(c[1]), "+f"(c[2]), "+f"(c[3])
                 : "r"(a[0]), "r"(a[1]), "r"(a[2]), "r"(a[3]), "r"(b[0]), "r"(b[1]));
}

// ---------- partition: two-ended, single pass (counters reset by k_final) ----------
__global__ void k_assign(const float* __restrict__ x) {
    int r = blockIdx.x * blockDim.x + threadIdx.x;
    if (r < B_) {
        if (x[(size_t)r*XLD+FEAT] > 0.5f) {
            int idx = atomicAdd(&g_cnt2[0], 1);
            g_pos2row[idx] = r;                    // nat: from front
        } else {
            int idx = atomicAdd(&g_cnt2[1], 1);
            g_pos2row[APAD - 1 - idx] = r;         // oth: from back
        }
    }
}

// ---------- A convert: gather + fp32 -> fp16; uniform-branch aligned realign ----------
__global__ __launch_bounds__(256) void k_convA(const float* __restrict__ x) {
    int pos = blockIdx.x;
    bool valid = (pos < g_cnt2[0]) || (pos >= APAD - g_cnt2[1]);
    int t = threadIdx.x;
    size_t db = ((size_t)pos * FEAT + t * 16) * 2;   // byte offset (fp16)
    uint4 h0 = {0,0,0,0}, h1 = {0,0,0,0};
    if (valid) {
        int orig = g_pos2row[pos];
        int m = orig & 3;                 // block-uniform misalignment (XLD ≡ 1 mod 4)
        const float* base = x + (size_t)orig * XLD + t * 16 - m;
        float f[20];
        float v[16];
        if (m == 0) {
            #pragma unroll
            for (int q = 0; q < 4; q++) *(float4*)(f + 4*q) = __ldg((const float4*)(base + 4*q));
            #pragma unroll
            for (int j = 0; j < 16; j++) v[j] = f[j];
        } else {
            // 5 aligned float4 cover [base, base+20); select [m, m+16) statically.
            #pragma unroll
            for (int q = 0; q < 5; q++) *(float4*)(f + 4*q) = __ldg((const float4*)(base + 4*q));
            if (m == 1) {
                #pragma unroll
                for (int j = 0; j < 16; j++) v[j] = f[j + 1];
            } else if (m == 2) {
                #pragma unroll
                for (int j = 0; j < 16; j++) v[j] = f[j + 2];
            } else {
                #pragma unroll
                for (int j = 0; j < 16; j++) v[j] = f[j + 3];
            }
        }
        uint32_t* p0 = (uint32_t*)&h0;
        uint32_t* p1 = (uint32_t*)&h1;
        #pragma unroll
        for (int e = 0; e < 4; e++) {
            __half2 a = __floats2half2_rn(v[2*e],   v[2*e+1]);
            __half2 b = __floats2half2_rn(v[8+2*e], v[8+2*e+1]);
            p0[e] = *reinterpret_cast<uint32_t*>(&a);
            p1[e] = *reinterpret_cast<uint32_t*>(&b);
        }
    }
    *(uint4*)((char*)g_A + db)      = h0;
    *(uint4*)((char*)g_A + db + 16) = h1;
}

// ---------- merged W prepack: fp32 [K][N] -> fp16, [N][K] tile-linear SW128 ----------
// blocks [0,2048): W1 (4n x 8k per thread); blocks [2048,2304): W2.
__global__ __launch_bounds__(256) void prep_w(
    const float* __restrict__ W1n, const float* __restrict__ W1o,
    const float* __restrict__ W2n, const float* __restrict__ W2o)
{
    int b = blockIdx.x, t = threadIdx.x;
    float rv[8][4];
    if (b < 2048) {
        int tid = b * 256 + t;                 // [0, 524288)
        int n = (tid & 511) * 4;               // 0..2044
        int rest = tid >> 9;
        int ko = rest & 511, g = rest >> 9;
        const float* src = (g ? W1o : W1n) + (size_t)(ko * 8) * HID + n;
        #pragma unroll
        for (int j = 0; j < 8; j++)
            *(float4*)rv[j] = __ldg((const float4*)(src + (size_t)j * HID));
        int kt = ko >> 3, cb = ko & 7;
        int nt = n >> 7;
        size_t tb = ((size_t)(((g << 4) + nt) * 64 + kt)) << 14;
        #pragma unroll
        for (int c = 0; c < 4; c++) {
            uint4 hv;
            uint32_t* hp = (uint32_t*)&hv;
            #pragma unroll
            for (int e = 0; e < 4; e++) {
                __half2 p = __floats2half2_rn(rv[2*e][c], rv[2*e+1][c]);
                hp[e] = *reinterpret_cast<uint32_t*>(&p);
            }
            int rIn = (n + c) & 127;
            uint32_t sw = (uint32_t)(rIn * 128 + (cb << 4)) ^ ((uint32_t)(rIn & 7) << 4);
            *(uint4*)((char*)g_W1 + tb + sw) = hv;
        }
    } else {
        int tid = (b - 2048) * 256 + t;        // [0, 65536)
        int n = (tid & 127) * 4;               // 0..508
        int rest = tid >> 7;
        int ko = rest & 255, g = rest >> 8;
        const float* src = (g ? W2o : W2n) + (size_t)(ko * 8) * PROJ + n;
        #pragma unroll
        for (int j = 0; j < 8; j++)
            *(float4*)rv[j] = __ldg((const float4*)(src + (size_t)j * PROJ));
        int kt = ko >> 3, cb = ko & 7;
        int nt = n >> 7;
        size_t tb = ((size_t)(((g << 2) + nt) * 32 + kt)) << 14;
        #pragma unroll
        for (int c = 0; c < 4; c++) {
            uint4 hv;
            uint32_t* hp = (uint32_t*)&hv;
            #pragma unroll
            for (int e = 0; e < 4; e++) {
                __half2 p = __floats2half2_rn(rv[2*e][c], rv[2*e+1][c]);
                hp[e] = *reinterpret_cast<uint32_t*>(&p);
            }
            int rIn = (n + c) & 127;
            uint32_t sw = (uint32_t)(rIn * 128 + (cb << 4)) ^ ((uint32_t)(rIn & 7) << 4);
            *(uint4*)((char*)g_W2 + tb + sw) = hv;
        }
    }
}

// ---------- GEMM: M128 x N256 CTA, K-step 64, single fp16 mma ----------
template <int IS_G1>
__global__ __launch_bounds__(256, 1) void gemm_mma(
    const float* __restrict__ bn_, const float* __restrict__ bo_)
{
    extern __shared__ char smc[];
    __shared__ float biasS[256];
    __shared__ int rowS[128];

    constexpr int STG  = 49152;
    constexpr int NTB  = IS_G1 ? 16 : 4;
    constexpr int KTB  = IS_G1 ? 64 : 32;
    constexpr int NIT  = IS_G1 ? (FEAT/64) : (HID/64);
    const int n_nat = g_cnt2[0], n_oth = g_cnt2[1];
    const int nat_tiles = (n_nat + 127) >> 7;
    const int oth_start = (APAD - n_oth) >> 7;     // floor: first tile containing oth rows
    const int bm = blockIdx.y, bnb = blockIdx.x;
    int grp;
    if (bm < nat_tiles)      grp = 0;
    else if (bm >= oth_start) grp = 1;
    else return;
    const int prow0 = bm << 7;
    const int lo = grp ? (APAD - n_oth) : 0;       // valid pos range per group
    const int hi = grp ? APAD : n_nat;

    const int t = threadIdx.x;
    biasS[t] = (grp ? bo_ : bn_)[(bnb << 8) + t];
    if (t < 128) {
        int pos = prow0 + t;
        rowS[t] = (pos >= lo && pos < hi) ? g_pos2row[pos] : -1;
    }
    __syncthreads();

    const uint32_t sb = smem_u32(smc);
    const char* Asrc = IS_G1 ? (const char*)g_A : (const char*)g_H;
    const size_t rowE = IS_G1 ? FEAT : HID;
    const char* Wsrc = IS_G1 ? (const char*)g_W1 : (const char*)g_W2;

    auto issue = [&](int s, int it) {
        uint32_t base = sb + s * STG;
        #pragma unroll
        for (int i = 0; i < 4; i++) {
            int cid = i * 256 + t;
            int r = cid >> 3, c = cid & 7;
            uint32_t off = (uint32_t)((r * 128 + c * 16) ^ ((r & 7) << 4));
            size_t so = ((size_t)(prow0 + r) * rowE + it * 64 + c * 8) * 2;
            cpa16(base + off, Asrc + so);
        }
        size_t tb0 = ((size_t)((grp * NTB + bnb * 2 + 0) * KTB + it)) << 14;
        size_t tb1 = ((size_t)((grp * NTB + bnb * 2 + 1) * KTB + it)) << 14;
        #pragma unroll
        for (int i = 0; i < 8; i++) {
            int cid = i * 256 + t;
            int ti = cid >> 10, j = cid & 1023;
            const char* sp = Wsrc + (ti ? tb1 : tb0) + (size_t)j * 16;
            cpa16(base + 16384 + ti * 16384 + j * 16, sp);
        }
    };

    const int w = t >> 5, lane = t & 31;
    const int wm = w >> 2, wn = w & 3;
    const int lr = lane & 7, gq = lane >> 3;
    int preA[4], rxA[4], preB[4], rxB[4];
    #pragma unroll
    for (int mf = 0; mf < 4; mf++) {
        int row = wm * 64 + mf * 16 + (gq & 1) * 8 + lr;
        preA[mf] = row * 128 + (gq >> 1) * 16;
        rxA[mf]  = (row & 7) << 4;
    }
    #pragma unroll
    for (int p = 0; p < 4; p++) {
        int n = wn * 64 + p * 16 + (gq >> 1) * 8 + lr;
        preB[p] = ((n >> 7) << 14) + (n & 127) * 128 + (gq & 1) * 16;
        rxB[p]  = (n & 7) << 4;
    }

    float acc[4][8][4];
    #pragma unroll
    for (int i = 0; i < 4; i++)
        #pragma unroll
        for (int j = 0; j < 8; j++)
            #pragma unroll
            for (int e = 0; e < 4; e++) acc[i][j][e] = 0.f;

    issue(0, 0); CPCOMMIT();
    for (int it = 0; it < NIT; it++) {
        int b = it & 1;
        if (it + 1 < NIT) { issue(b ^ 1, it + 1); CPCOMMIT(); CPWAIT1(); }
        else              { CPWAIT0(); }
        __syncthreads();
        uint32_t sA = sb + b * STG, sW = sA + 16384;
        #pragma unroll
        for (int k16 = 0; k16 < 4; k16++) {
            int kb = k16 * 32;
            uint32_t a[4][4], bb[8][2];
            #pragma unroll
            for (int mf = 0; mf < 4; mf++) ldsm4(a[mf], sA + (uint32_t)((preA[mf] + kb) ^ rxA[mf]));
            #pragma unroll
            for (int p = 0; p < 4; p++) {
                uint32_t r[4];
                ldsm4(r, sW + (uint32_t)((preB[p] + kb) ^ rxB[p]));
                bb[2*p][0]=r[0]; bb[2*p][1]=r[1]; bb[2*p+1][0]=r[2]; bb[2*p+1][1]=r[3];
            }
            #pragma unroll
            for (int mf = 0; mf < 4; mf++)
                #pragma unroll
                for (int nf = 0; nf < 8; nf++) mma_h(acc[mf][nf], a[mf], bb[nf]);
        }
        __syncthreads();
    }

    // epilogue
    #pragma unroll
    for (int mf = 0; mf < 4; mf++) {
        #pragma unroll
        for (int half = 0; half < 2; half++) {
            int row = wm * 64 + mf * 16 + (lane >> 2) + half * 8;
            if (IS_G1) {
                size_t base = (size_t)(prow0 + row) * HID + (bnb << 8);
                #pragma unroll
                for (int nf = 0; nf < 8; nf++) {
                    int n = wn * 64 + nf * 8 + (lane & 3) * 2;
                    float v0 = fmaxf(acc[mf][nf][half*2+0] + biasS[n],     0.f);
                    float v1 = fmaxf(acc[mf][nf][half*2+1] + biasS[n + 1], 0.f);
                    __half2 p = __floats2half2_rn(v0, v1);
                    *(uint32_t*)((char*)g_H + (base + n) * 2) = *reinterpret_cast<uint32_t*>(&p);
                }
            } else {
                int orig = rowS[row];
                if (orig >= 0) {
                    float* zp = g_Z + (size_t)orig * PROJ + (bnb << 8);
                    #pragma unroll
                    for (int nf = 0; nf < 8; nf++) {
                        int n = wn * 64 + nf * 8 + (lane & 3) * 2;
                        float2 v;
                        v.x = acc[mf][nf][half*2+0] + biasS[n];
                        v.y = acc[mf][nf][half*2+1] + biasS[n + 1];
                        *(float2*)(zp + n) = v;
                    }
                }
            }
        }
    }
}

// ---------- finalize: warp-per-row norm + logits; resets counters for next replay ----------
__global__ __launch_bounds__(256) void k_final(
    const float* __restrict__ x,
    const float* __restrict__ Wcn, const float* __restrict__ bcn,
    const float* __restrict__ Wco, const float* __restrict__ bco,
    float* __restrict__ out)
{
    if (blockIdx.x == 0 && threadIdx.x == 0) {
        g_cnt2[0] = 0; g_cnt2[1] = 0;
    }
    const int wid = threadIdx.x >> 5, lane = threadIdx.x & 31;
    const int row = blockIdx.x * 8 + wid;
    const bool nat = __ldg(x + (size_t)row * XLD + FEAT) > 0.5f;
    const float* __restrict__ Wc = nat ? Wcn : Wco;
    const float* __restrict__ bc = nat ? bcn : bco;
    const float* zr = g_Z + (size_t)row * PROJ;

    float4 zv[4];
    float ss = 0.f, l0 = 0.f, l1 = 0.f, l2 = 0.f;
    #pragma unroll
    for (int i = 0; i < 4; i++) {
        const int k = i * 128 + lane * 4;
        float4 z = __ldg((const float4*)(zr + k));
        zv[i] = z;
        ss += z.x*z.x + z.y*z.y + z.z*z.z + z.w*z.w;
        float r0 = fmaxf(z.x, 0.f), r1 = fmaxf(z.y, 0.f);
        float r2 = fmaxf(z.z, 0.f), r3 = fmaxf(z.w, 0.f);
        const float4 w0 = __ldg((const float4*)(Wc + k * 3));
        const float4 w1 = __ldg((const float4*)(Wc + k * 3 + 4));
        const float4 w2 = __ldg((const float4*)(Wc + k * 3 + 8));
        l0 += r0*w0.x + r1*w0.w + r2*w1.z + r3*w2.y;
        l1 += r0*w0.y + r1*w1.x + r2*w1.w + r3*w2.z;
        l2 += r0*w0.z + r1*w1.y + r2*w2.x + r3*w2.w;
    }
    #pragma unroll
    for (int o = 16; o > 0; o >>= 1) {
        ss += __shfl_xor_sync(0xFFFFFFFFu, ss, o);
        l0 += __shfl_xor_sync(0xFFFFFFFFu, l0, o);
        l1 += __shfl_xor_sync(0xFFFFFFFFu, l1, o);
        l2 += __shfl_xor_sync(0xFFFFFFFFu, l2, o);
    }
    if (lane == 0) {
        float* lg = out + (size_t)B_ * PROJ + (size_t)row * NOUT;
        lg[0] = l0 + bc[0]; lg[1] = l1 + bc[1]; lg[2] = l2 + bc[2];
    }
    const float inv = 1.f / fmaxf(sqrtf(ss), 1e-12f);
    float* op = out + (size_t)row * PROJ;
    #pragma unroll
    for (int i = 0; i < 4; i++) {
        float4 z = zv[i];
        z.x *= inv; z.y *= inv; z.z *= inv; z.w *= inv;
        *(float4*)(op + i * 128 + lane * 4) = z;
    }
}

// ---------- launcher ----------
extern "C" void kernel_launch(void* const* d_in, const int* in_sizes, int n_in,
                              void* d_out, int out_size) {
    const float* x   = (const float*)d_in[0];
    const float* W1n = (const float*)d_in[1];
    const float* b1n = (const float*)d_in[2];
    const float* W2n = (const float*)d_in[3];
    const float* b2n = (const float*)d_in[4];
    const float* Wcn = (const float*)d_in[5];
    const float* bcn = (const float*)d_in[6];
    const float* W1o = (const float*)d_in[7];
    const float* b1o = (const float*)d_in[8];
    const float* W2o = (const float*)d_in[9];
    const float* b2o = (const float*)d_in[10];
    const float* Wco = (const float*)d_in[11];
    const float* bco = (const float*)d_in[12];
    float* out = (float*)d_out;

    cudaFuncSetAttribute(gemm_mma<1>, cudaFuncAttributeMaxDynamicSharedMemorySize, 2*49152);
    cudaFuncSetAttribute(gemm_mma<0>, cudaFuncAttributeMaxDynamicSharedMemorySize, 2*49152);

    k_assign<<<B_ / 256, 256>>>(x);
    k_convA<<<APAD, 256>>>(x);
    prep_w<<<2304, 256>>>(W1n, W1o, W2n, W2o);

    gemm_mma<1><<<dim3(8, TILES_M), 256, 2*49152>>>(b1n, b1o);
    gemm_mma<0><<<dim3(2, TILES_M), 256, 2*49152>>>(b2n, b2o);

    k_final<<<B_ / 8, 256>>>(x, Wcn, bcn, Wco, bco, out);
}

// round 11
// speedup vs baseline: 9.6558x; 1.0861x over previous
#include <cuda_runtime.h>
#include <cuda_fp16.h>
#include <cstdint>

#define B_   32768
#define FEAT 4096
#define XLD  4097
#define HID  2048
#define PROJ 512
#define NOUT 3
#define APAD (B_ + 256)
#define TILES_M 258

// ---------- device scratch ----------
__device__ int g_cnt2[2];
__device__ int g_pos2row[APAD];
__device__ float g_Z[(size_t)B_ * PROJ];
__device__ __half g_A[(size_t)APAD * FEAT];      // fp16 x features, permuted rows
__device__ __half g_H[(size_t)APAD * HID];       // fp16 hidden
__device__ __half g_W1[(size_t)2 * 16 * 64 * 8192];   // fp16, [N][K] tile-linear SW128 (16KB tiles)
__device__ __half g_W2[(size_t)2 * 4 * 32 * 8192];

// ---------- helpers ----------
__device__ __forceinline__ uint32_t smem_u32(const void* p) {
    uint32_t a;
    asm("{ .reg .u64 t; cvta.to.shared.u64 t, %1; cvt.u32.u64 %0, t; }" : "=r"(a) : "l"(p));
    return a;
}
__device__ __forceinline__ void cpa16(uint32_t d, const void* s) {
    asm volatile("cp.async.cg.shared.global [%0], [%1], 16;" :: "r"(d), "l"(s));
}
#define CPCOMMIT() asm volatile("cp.async.commit_group;" ::: "memory")
#define CPWAIT0()  asm volatile("cp.async.wait_group 0;" ::: "memory")
#define CPWAIT1()  asm volatile("cp.async.wait_group 1;" ::: "memory")
__device__ __forceinline__ void ldsm4(uint32_t* r, uint32_t a) {
    asm volatile("ldmatrix.sync.aligned.m8n8.x4.shared.b16 {%0,%1,%2,%3}, [%4];"
                 : "=r"(r[0]), "=r"(r[1]), "=r"(r[2]), "=r"(r[3]) : "r"(a));
}
__device__ __forceinline__ void mma_h(float* c, const uint32_t* a, const uint32_t* b) {
    asm volatile("mma.sync.aligned.m16n8k16.row.col.f32.f16.f16.f32 "
                 "{%0,%1,%2,%3}, {%4,%5,%6,%7}, {%8,%9}, {%0,%1,%2,%3};"
                 : "+f"(c[0]), "+f"(c[1]), "+f"(c[2]), "+f"(c[3])
                 : "r"(a[0]), "r"(a[1]), "r"(a[2]), "r"(a[3]), "r"(b[0]), "r"(b[1]));
}

// ---------- partition: two-ended, single pass (counters reset by k_final) ----------
__global__ void k_assign(const float* __restrict__ x) {
    int r = blockIdx.x * blockDim.x + threadIdx.x;
    if (r < B_) {
        if (x[(size_t)r*XLD+FEAT] > 0.5f) {
            int idx = atomicAdd(&g_cnt2[0], 1);
            g_pos2row[idx] = r;                    // nat: from front
        } else {
            int idx = atomicAdd(&g_cnt2[1], 1);
            g_pos2row[APAD - 1 - idx] = r;         // oth: from back
        }
    }
}

// ---------- A convert: gather + fp32 -> fp16; uniform-branch aligned realign ----------
__global__ __launch_bounds__(256) void k_convA(const float* __restrict__ x) {
    int pos = blockIdx.x;
    bool valid = (pos < g_cnt2[0]) || (pos >= APAD - g_cnt2[1]);
    int t = threadIdx.x;
    size_t db = ((size_t)pos * FEAT + t * 16) * 2;
    uint4 h0 = {0,0,0,0}, h1 = {0,0,0,0};
    if (valid) {
        int orig = g_pos2row[pos];
        int m = orig & 3;
        const float* base = x + (size_t)orig * XLD + t * 16 - m;
        float f[20];
        float v[16];
        if (m == 0) {
            #pragma unroll
            for (int q = 0; q < 4; q++) *(float4*)(f + 4*q) = __ldg((const float4*)(base + 4*q));
            #pragma unroll
            for (int j = 0; j < 16; j++) v[j] = f[j];
        } else {
            #pragma unroll
            for (int q = 0; q < 5; q++) *(float4*)(f + 4*q) = __ldg((const float4*)(base + 4*q));
            if (m == 1) {
                #pragma unroll
                for (int j = 0; j < 16; j++) v[j] = f[j + 1];
            } else if (m == 2) {
                #pragma unroll
                for (int j = 0; j < 16; j++) v[j] = f[j + 2];
            } else {
                #pragma unroll
                for (int j = 0; j < 16; j++) v[j] = f[j + 3];
            }
        }
        uint32_t* p0 = (uint32_t*)&h0;
        uint32_t* p1 = (uint32_t*)&h1;
        #pragma unroll
        for (int e = 0; e < 4; e++) {
            __half2 a = __floats2half2_rn(v[2*e],   v[2*e+1]);
            __half2 b = __floats2half2_rn(v[8+2*e], v[8+2*e+1]);
            p0[e] = *reinterpret_cast<uint32_t*>(&a);
            p1[e] = *reinterpret_cast<uint32_t*>(&b);
        }
    }
    *(uint4*)((char*)g_A + db)      = h0;
    *(uint4*)((char*)g_A + db + 16) = h1;
}

// ---------- merged W prepack: fp32 [K][N] -> fp16, [N][K] tile-linear SW128 ----------
__global__ __launch_bounds__(256) void prep_w(
    const float* __restrict__ W1n, const float* __restrict__ W1o,
    const float* __restrict__ W2n, const float* __restrict__ W2o)
{
    int b = blockIdx.x, t = threadIdx.x;
    float rv[8][4];
    if (b < 2048) {
        int tid = b * 256 + t;
        int n = (tid & 511) * 4;
        int rest = tid >> 9;
        int ko = rest & 511, g = rest >> 9;
        const float* src = (g ? W1o : W1n) + (size_t)(ko * 8) * HID + n;
        #pragma unroll
        for (int j = 0; j < 8; j++)
            *(float4*)rv[j] = __ldg((const float4*)(src + (size_t)j * HID));
        int kt = ko >> 3, cb = ko & 7;
        int nt = n >> 7;
        size_t tb = ((size_t)(((g << 4) + nt) * 64 + kt)) << 14;
        #pragma unroll
        for (int c = 0; c < 4; c++) {
            uint4 hv;
            uint32_t* hp = (uint32_t*)&hv;
            #pragma unroll
            for (int e = 0; e < 4; e++) {
                __half2 p = __floats2half2_rn(rv[2*e][c], rv[2*e+1][c]);
                hp[e] = *reinterpret_cast<uint32_t*>(&p);
            }
            int rIn = (n + c) & 127;
            uint32_t sw = (uint32_t)(rIn * 128 + (cb << 4)) ^ ((uint32_t)(rIn & 7) << 4);
            *(uint4*)((char*)g_W1 + tb + sw) = hv;
        }
    } else {
        int tid = (b - 2048) * 256 + t;
        int n = (tid & 127) * 4;
        int rest = tid >> 7;
        int ko = rest & 255, g = rest >> 8;
        const float* src = (g ? W2o : W2n) + (size_t)(ko * 8) * PROJ + n;
        #pragma unroll
        for (int j = 0; j < 8; j++)
            *(float4*)rv[j] = __ldg((const float4*)(src + (size_t)j * PROJ));
        int kt = ko >> 3, cb = ko & 7;
        int nt = n >> 7;
        size_t tb = ((size_t)(((g << 2) + nt) * 32 + kt)) << 14;
        #pragma unroll
        for (int c = 0; c < 4; c++) {
            uint4 hv;
            uint32_t* hp = (uint32_t*)&hv;
            #pragma unroll
            for (int e = 0; e < 4; e++) {
                __half2 p = __floats2half2_rn(rv[2*e][c], rv[2*e+1][c]);
                hp[e] = *reinterpret_cast<uint32_t*>(&p);
            }
            int rIn = (n + c) & 127;
            uint32_t sw = (uint32_t)(rIn * 128 + (cb << 4)) ^ ((uint32_t)(rIn & 7) << 4);
            *(uint4*)((char*)g_W2 + tb + sw) = hv;
        }
    }
}

// ---------- GEMM: M128 x N128 CTA, warp tile 64x32, K-step 64, 2 CTAs/SM ----------
template <int IS_G1>
__global__ __launch_bounds__(256, 2) void gemm_mma(
    const float* __restrict__ bn_, const float* __restrict__ bo_)
{
    extern __shared__ char smc[];
    __shared__ float biasS[128];
    __shared__ int rowS[128];

    constexpr int STG  = 32768;                 // A 16K + W 16K
    constexpr int NTB  = IS_G1 ? 16 : 4;        // 128-col W tiles
    constexpr int KTB  = IS_G1 ? 64 : 32;
    constexpr int NIT  = IS_G1 ? (FEAT/64) : (HID/64);
    const int n_nat = g_cnt2[0], n_oth = g_cnt2[1];
    const int nat_tiles = (n_nat + 127) >> 7;
    const int oth_start = (APAD - n_oth) >> 7;
    const int bm = blockIdx.y, bnb = blockIdx.x;
    int grp;
    if (bm < nat_tiles)       grp = 0;
    else if (bm >= oth_start) grp = 1;
    else return;
    const int prow0 = bm << 7;
    const int lo = grp ? (APAD - n_oth) : 0;
    const int hi = grp ? APAD : n_nat;

    const int t = threadIdx.x;
    if (t < 128) {
        biasS[t] = (grp ? bo_ : bn_)[(bnb << 7) + t];
        int pos = prow0 + t;
        rowS[t] = (pos >= lo && pos < hi) ? g_pos2row[pos] : -1;
    }
    __syncthreads();

    const uint32_t sb = smem_u32(smc);
    const char* Asrc = IS_G1 ? (const char*)g_A : (const char*)g_H;
    const size_t rowE = IS_G1 ? FEAT : HID;
    const char* Wsrc = IS_G1 ? (const char*)g_W1 : (const char*)g_W2;

    auto issue = [&](int s, int it) {
        uint32_t base = sb + s * STG;
        #pragma unroll
        for (int i = 0; i < 4; i++) {
            int cid = i * 256 + t;
            int r = cid >> 3, c = cid & 7;
            uint32_t off = (uint32_t)((r * 128 + c * 16) ^ ((r & 7) << 4));
            size_t so = ((size_t)(prow0 + r) * rowE + it * 64 + c * 8) * 2;
            cpa16(base + off, Asrc + so);
        }
        size_t tb0 = ((size_t)((grp * NTB + bnb) * KTB + it)) << 14;
        #pragma unroll
        for (int i = 0; i < 4; i++) {
            int j = i * 256 + t;                 // 0..1023
            cpa16(base + 16384 + j * 16, Wsrc + tb0 + (size_t)j * 16);
        }
    };

    const int w = t >> 5, lane = t & 31;
    const int wm = w >> 2, wn = w & 3;           // 2m x 4n warp grid
    const int lr = lane & 7, gq = lane >> 3;
    int preA[4], rxA[4], preB[2], rxB[2];
    #pragma unroll
    for (int mf = 0; mf < 4; mf++) {
        int row = wm * 64 + mf * 16 + (gq & 1) * 8 + lr;
        preA[mf] = row * 128 + (gq >> 1) * 16;
        rxA[mf]  = (row & 7) << 4;
    }
    #pragma unroll
    for (int p = 0; p < 2; p++) {
        int n = wn * 32 + p * 16 + (gq >> 1) * 8 + lr;
        preB[p] = (n & 127) * 128 + (gq & 1) * 16;
        rxB[p]  = (n & 7) << 4;
    }

    float acc[4][4][4];
    #pragma unroll
    for (int i = 0; i < 4; i++)
        #pragma unroll
        for (int j = 0; j < 4; j++)
            #pragma unroll
            for (int e = 0; e < 4; e++) acc[i][j][e] = 0.f;

    issue(0, 0); CPCOMMIT();
    for (int it = 0; it < NIT; it++) {
        int b = it & 1;
        if (it + 1 < NIT) { issue(b ^ 1, it + 1); CPCOMMIT(); CPWAIT1(); }
        else              { CPWAIT0(); }
        __syncthreads();
        uint32_t sA = sb + b * STG, sW = sA + 16384;
        #pragma unroll
        for (int k16 = 0; k16 < 4; k16++) {
            int kb = k16 * 32;
            uint32_t a[4][4], bb[4][2];
            #pragma unroll
            for (int mf = 0; mf < 4; mf++) ldsm4(a[mf], sA + (uint32_t)((preA[mf] + kb) ^ rxA[mf]));
            #pragma unroll
            for (int p = 0; p < 2; p++) {
                uint32_t r[4];
                ldsm4(r, sW + (uint32_t)((preB[p] + kb) ^ rxB[p]));
                bb[2*p][0]=r[0]; bb[2*p][1]=r[1]; bb[2*p+1][0]=r[2]; bb[2*p+1][1]=r[3];
            }
            #pragma unroll
            for (int mf = 0; mf < 4; mf++)
                #pragma unroll
                for (int nf = 0; nf < 4; nf++) mma_h(acc[mf][nf], a[mf], bb[nf]);
        }
        __syncthreads();
    }

    // epilogue: warp covers 64 rows x 32 cols
    #pragma unroll
    for (int mf = 0; mf < 4; mf++) {
        #pragma unroll
        for (int half = 0; half < 2; half++) {
            int row = wm * 64 + mf * 16 + (lane >> 2) + half * 8;
            if (IS_G1) {
                size_t base = (size_t)(prow0 + row) * HID + (bnb << 7);
                #pragma unroll
                for (int nf = 0; nf < 4; nf++) {
                    int n = wn * 32 + nf * 8 + (lane & 3) * 2;
                    float v0 = fmaxf(acc[mf][nf][half*2+0] + biasS[n],     0.f);
                    float v1 = fmaxf(acc[mf][nf][half*2+1] + biasS[n + 1], 0.f);
                    __half2 p = __floats2half2_rn(v0, v1);
                    *(uint32_t*)((char*)g_H + (base + n) * 2) = *reinterpret_cast<uint32_t*>(&p);
                }
            } else {
                int orig = rowS[row];
                if (orig >= 0) {
                    float* zp = g_Z + (size_t)orig * PROJ + (bnb << 7);
                    #pragma unroll
                    for (int nf = 0; nf < 4; nf++) {
                        int n = wn * 32 + nf * 8 + (lane & 3) * 2;
                        float2 v;
                        v.x = acc[mf][nf][half*2+0] + biasS[n];
                        v.y = acc[mf][nf][half*2+1] + biasS[n + 1];
                        *(float2*)(zp + n) = v;
                    }
                }
            }
        }
    }
}

// ---------- finalize: warp-per-row norm + logits; resets counters for next replay ----------
__global__ __launch_bounds__(256) void k_final(
    const float* __restrict__ x,
    const float* __restrict__ Wcn, const float* __restrict__ bcn,
    const float* __restrict__ Wco, const float* __restrict__ bco,
    float* __restrict__ out)
{
    if (blockIdx.x == 0 && threadIdx.x == 0) {
        g_cnt2[0] = 0; g_cnt2[1] = 0;
    }
    const int wid = threadIdx.x >> 5, lane = threadIdx.x & 31;
    const int row = blockIdx.x * 8 + wid;
    const bool nat = __ldg(x + (size_t)row * XLD + FEAT) > 0.5f;
    const float* __restrict__ Wc = nat ? Wcn : Wco;
    const float* __restrict__ bc = nat ? bcn : bco;
    const float* zr = g_Z + (size_t)row * PROJ;

    float4 zv[4];
    float ss = 0.f, l0 = 0.f, l1 = 0.f, l2 = 0.f;
    #pragma unroll
    for (int i = 0; i < 4; i++) {
        const int k = i * 128 + lane * 4;
        float4 z = __ldg((const float4*)(zr + k));
        zv[i] = z;
        ss += z.x*z.x + z.y*z.y + z.z*z.z + z.w*z.w;
        float r0 = fmaxf(z.x, 0.f), r1 = fmaxf(z.y, 0.f);
        float r2 = fmaxf(z.z, 0.f), r3 = fmaxf(z.w, 0.f);
        const float4 w0 = __ldg((const float4*)(Wc + k * 3));
        const float4 w1 = __ldg((const float4*)(Wc + k * 3 + 4));
        const float4 w2 = __ldg((const float4*)(Wc + k * 3 + 8));
        l0 += r0*w0.x + r1*w0.w + r2*w1.z + r3*w2.y;
        l1 += r0*w0.y + r1*w1.x + r2*w1.w + r3*w2.z;
        l2 += r0*w0.z + r1*w1.y + r2*w2.x + r3*w2.w;
    }
    #pragma unroll
    for (int o = 16; o > 0; o >>= 1) {
        ss += __shfl_xor_sync(0xFFFFFFFFu, ss, o);
        l0 += __shfl_xor_sync(0xFFFFFFFFu, l0, o);
        l1 += __shfl_xor_sync(0xFFFFFFFFu, l1, o);
        l2 += __shfl_xor_sync(0xFFFFFFFFu, l2, o);
    }
    if (lane == 0) {
        float* lg = out + (size_t)B_ * PROJ + (size_t)row * NOUT;
        lg[0] = l0 + bc[0]; lg[1] = l1 + bc[1]; lg[2] = l2 + bc[2];
    }
    const float inv = 1.f / fmaxf(sqrtf(ss), 1e-12f);
    float* op = out + (size_t)row * PROJ;
    #pragma unroll
    for (int i = 0; i < 4; i++) {
        float4 z = zv[i];
        z.x *= inv; z.y *= inv; z.z *= inv; z.w *= inv;
        *(float4*)(op + i * 128 + lane * 4) = z;
    }
}

// ---------- launcher ----------
extern "C" void kernel_launch(void* const* d_in, const int* in_sizes, int n_in,
                              void* d_out, int out_size) {
    const float* x   = (const float*)d_in[0];
    const float* W1n = (const float*)d_in[1];
    const float* b1n = (const float*)d_in[2];
    const float* W2n = (const float*)d_in[3];
    const float* b2n = (const float*)d_in[4];
    const float* Wcn = (const float*)d_in[5];
    const float* bcn = (const float*)d_in[6];
    const float* W1o = (const float*)d_in[7];
    const float* b1o = (const float*)d_in[8];
    const float* W2o = (const float*)d_in[9];
    const float* b2o = (const float*)d_in[10];
    const float* Wco = (const float*)d_in[11];
    const float* bco = (const float*)d_in[12];
    float* out = (float*)d_out;

    cudaFuncSetAttribute(gemm_mma<1>, cudaFuncAttributeMaxDynamicSharedMemorySize, 2*32768);
    cudaFuncSetAttribute(gemm_mma<0>, cudaFuncAttributeMaxDynamicSharedMemorySize, 2*32768);

    k_assign<<<B_ / 256, 256>>>(x);
    k_convA<<<APAD, 256>>>(x);
    prep_w<<<2304, 256>>>(W1n, W1o, W2n, W2o);

    gemm_mma<1><<<dim3(16, TILES_M), 256, 2*32768>>>(b1n, b1o);
    gemm_mma<0><<<dim3(4, TILES_M), 256, 2*32768>>>(b2n, b2o);

    k_final<<<B_ / 8, 256>>>(x, Wcn, bcn, Wco, bco, out);
}

// round 12
// speedup vs baseline: 9.7219x; 1.0068x over previous
#include <cuda_runtime.h>
#include <cuda_fp16.h>
#include <cstdint>

#define B_   32768
#define FEAT 4096
#define XLD  4097
#define HID  2048
#define PROJ 512
#define NOUT 3
#define APAD (B_ + 256)
#define TILES_M 258

// ---------- device scratch ----------
__device__ int g_cnt2[2];
__device__ int g_pos2row[APAD];
__device__ float g_Z[(size_t)B_ * PROJ];
__device__ __half g_A[(size_t)APAD * FEAT];      // fp16 x features, permuted rows
__device__ __half g_H[(size_t)APAD * HID];       // fp16 hidden
__device__ __half g_W1[(size_t)2 * 16 * 64 * 8192];   // fp16, [N][K] tile-linear SW128 (16KB tiles)
__device__ __half g_W2[(size_t)2 * 4 * 32 * 8192];

// ---------- helpers ----------
__device__ __forceinline__ uint32_t smem_u32(const void* p) {
    uint32_t a;
    asm("{ .reg .u64 t; cvta.to.shared.u64 t, %1; cvt.u32.u64 %0, t; }" : "=r"(a) : "l"(p));
    return a;
}
__device__ __forceinline__ void cpa16(uint32_t d, const void* s) {
    asm volatile("cp.async.cg.shared.global [%0], [%1], 16;" :: "r"(d), "l"(s));
}
#define CPCOMMIT() asm volatile("cp.async.commit_group;" ::: "memory")
#define CPWAIT0()  asm volatile("cp.async.wait_group 0;" ::: "memory")
#define CPWAIT1()  asm volatile("cp.async.wait_group 1;" ::: "memory")
__device__ __forceinline__ void ldsm4(uint32_t* r, uint32_t a) {
    asm volatile("ldmatrix.sync.aligned.m8n8.x4.shared.b16 {%0,%1,%2,%3}, [%4];"
                 : "=r"(r[0]), "=r"(r[1]), "=r"(r[2]), "=r"(r[3]) : "r"(a));
}
__device__ __forceinline__ void mma_h(float* c, const uint32_t* a, const uint32_t* b) {
    asm volatile("mma.sync.aligned.m16n8k16.row.col.f32.f16.f16.f32 "
                 "{%0,%1,%2,%3}, {%4,%5,%6,%7}, {%8,%9}, {%0,%1,%2,%3};"
                 : "+f"(c[0]), "+f"(c[1]), "+f"(c[2]), "+f"(c[3])
                 : "r"(a[0]), "r"(a[1]), "r"(a[2]), "r"(a[3]), "r"(b[0]), "r"(b[1]));
}

// ---------- partition: two-ended, single pass (counters reset by k_final) ----------
__global__ void k_assign(const float* __restrict__ x) {
    int r = blockIdx.x * blockDim.x + threadIdx.x;
    if (r < B_) {
        if (x[(size_t)r*XLD+FEAT] > 0.5f) {
            int idx = atomicAdd(&g_cnt2[0], 1);
            g_pos2row[idx] = r;                    // nat: from front
        } else {
            int idx = atomicAdd(&g_cnt2[1], 1);
            g_pos2row[APAD - 1 - idx] = r;         // oth: from back
        }
    }
}

// ---------- A convert: gather + fp32 -> fp16; uniform-branch aligned realign ----------
__global__ __launch_bounds__(256) void k_convA(const float* __restrict__ x) {
    int pos = blockIdx.x;
    bool valid = (pos < g_cnt2[0]) || (pos >= APAD - g_cnt2[1]);
    int t = threadIdx.x;
    size_t db = ((size_t)pos * FEAT + t * 16) * 2;
    uint4 h0 = {0,0,0,0}, h1 = {0,0,0,0};
    if (valid) {
        int orig = g_pos2row[pos];
        int m = orig & 3;
        const float* base = x + (size_t)orig * XLD + t * 16 - m;
        float f[20];
        float v[16];
        if (m == 0) {
            #pragma unroll
            for (int q = 0; q < 4; q++) *(float4*)(f + 4*q) = __ldg((const float4*)(base + 4*q));
            #pragma unroll
            for (int j = 0; j < 16; j++) v[j] = f[j];
        } else {
            #pragma unroll
            for (int q = 0; q < 5; q++) *(float4*)(f + 4*q) = __ldg((const float4*)(base + 4*q));
            if (m == 1) {
                #pragma unroll
                for (int j = 0; j < 16; j++) v[j] = f[j + 1];
            } else if (m == 2) {
                #pragma unroll
                for (int j = 0; j < 16; j++) v[j] = f[j + 2];
            } else {
                #pragma unroll
                for (int j = 0; j < 16; j++) v[j] = f[j + 3];
            }
        }
        uint32_t* p0 = (uint32_t*)&h0;
        uint32_t* p1 = (uint32_t*)&h1;
        #pragma unroll
        for (int e = 0; e < 4; e++) {
            __half2 a = __floats2half2_rn(v[2*e],   v[2*e+1]);
            __half2 b = __floats2half2_rn(v[8+2*e], v[8+2*e+1]);
            p0[e] = *reinterpret_cast<uint32_t*>(&a);
            p1[e] = *reinterpret_cast<uint32_t*>(&b);
        }
    }
    *(uint4*)((char*)g_A + db)      = h0;
    *(uint4*)((char*)g_A + db + 16) = h1;
}

// ---------- merged W prepack: fp32 [K][N] -> fp16, [N][K] tile-linear SW128 ----------
__global__ __launch_bounds__(256) void prep_w(
    const float* __restrict__ W1n, const float* __restrict__ W1o,
    const float* __restrict__ W2n, const float* __restrict__ W2o)
{
    int b = blockIdx.x, t = threadIdx.x;
    float rv[8][4];
    if (b < 2048) {
        int tid = b * 256 + t;
        int n = (tid & 511) * 4;
        int rest = tid >> 9;
        int ko = rest & 511, g = rest >> 9;
        const float* src = (g ? W1o : W1n) + (size_t)(ko * 8) * HID + n;
        #pragma unroll
        for (int j = 0; j < 8; j++)
            *(float4*)rv[j] = __ldg((const float4*)(src + (size_t)j * HID));
        int kt = ko >> 3, cb = ko & 7;
        int nt = n >> 7;
        size_t tb = ((size_t)(((g << 4) + nt) * 64 + kt)) << 14;
        #pragma unroll
        for (int c = 0; c < 4; c++) {
            uint4 hv;
            uint32_t* hp = (uint32_t*)&hv;
            #pragma unroll
            for (int e = 0; e < 4; e++) {
                __half2 p = __floats2half2_rn(rv[2*e][c], rv[2*e+1][c]);
                hp[e] = *reinterpret_cast<uint32_t*>(&p);
            }
            int rIn = (n + c) & 127;
            uint32_t sw = (uint32_t)(rIn * 128 + (cb << 4)) ^ ((uint32_t)(rIn & 7) << 4);
            *(uint4*)((char*)g_W1 + tb + sw) = hv;
        }
    } else {
        int tid = (b - 2048) * 256 + t;
        int n = (tid & 127) * 4;
        int rest = tid >> 7;
        int ko = rest & 255, g = rest >> 8;
        const float* src = (g ? W2o : W2n) + (size_t)(ko * 8) * PROJ + n;
        #pragma unroll
        for (int j = 0; j < 8; j++)
            *(float4*)rv[j] = __ldg((const float4*)(src + (size_t)j * PROJ));
        int kt = ko >> 3, cb = ko & 7;
        int nt = n >> 7;
        size_t tb = ((size_t)(((g << 2) + nt) * 32 + kt)) << 14;
        #pragma unroll
        for (int c = 0; c < 4; c++) {
            uint4 hv;
            uint32_t* hp = (uint32_t*)&hv;
            #pragma unroll
            for (int e = 0; e < 4; e++) {
                __half2 p = __floats2half2_rn(rv[2*e][c], rv[2*e+1][c]);
                hp[e] = *reinterpret_cast<uint32_t*>(&p);
            }
            int rIn = (n + c) & 127;
            uint32_t sw = (uint32_t)(rIn * 128 + (cb << 4)) ^ ((uint32_t)(rIn & 7) << 4);
            *(uint4*)((char*)g_W2 + tb + sw) = hv;
        }
    }
}

// ---------- GEMM: M128 x N128 CTA, warp tile 64x32, K-step 64, 3-stage pipeline, 2 CTAs/SM ----------
template <int IS_G1>
__global__ __launch_bounds__(256, 2) void gemm_mma(
    const float* __restrict__ bn_, const float* __restrict__ bo_)
{
    extern __shared__ char smc[];
    __shared__ float biasS[128];
    __shared__ int rowS[128];

    constexpr int STG  = 32768;                 // A 16K + W 16K per stage; 3 stages
    constexpr int NTB  = IS_G1 ? 16 : 4;
    constexpr int KTB  = IS_G1 ? 64 : 32;
    constexpr int NIT  = IS_G1 ? (FEAT/64) : (HID/64);
    const int n_nat = g_cnt2[0], n_oth = g_cnt2[1];
    const int nat_tiles = (n_nat + 127) >> 7;
    const int oth_start = (APAD - n_oth) >> 7;
    const int bm = blockIdx.y, bnb = blockIdx.x;
    int grp;
    if (bm < nat_tiles)       grp = 0;
    else if (bm >= oth_start) grp = 1;
    else return;
    const int prow0 = bm << 7;
    const int lo = grp ? (APAD - n_oth) : 0;
    const int hi = grp ? APAD : n_nat;

    const int t = threadIdx.x;
    if (t < 128) {
        biasS[t] = (grp ? bo_ : bn_)[(bnb << 7) + t];
        int pos = prow0 + t;
        rowS[t] = (pos >= lo && pos < hi) ? g_pos2row[pos] : -1;
    }
    __syncthreads();

    const uint32_t sb = smem_u32(smc);
    const char* Asrc = IS_G1 ? (const char*)g_A : (const char*)g_H;
    const size_t rowE = IS_G1 ? FEAT : HID;
    const char* Wsrc = IS_G1 ? (const char*)g_W1 : (const char*)g_W2;

    auto issue = [&](int s, int it) {
        uint32_t base = sb + s * STG;
        #pragma unroll
        for (int i = 0; i < 4; i++) {
            int cid = i * 256 + t;
            int r = cid >> 3, c = cid & 7;
            uint32_t off = (uint32_t)((r * 128 + c * 16) ^ ((r & 7) << 4));
            size_t so = ((size_t)(prow0 + r) * rowE + it * 64 + c * 8) * 2;
            cpa16(base + off, Asrc + so);
        }
        size_t tb0 = ((size_t)((grp * NTB + bnb) * KTB + it)) << 14;
        #pragma unroll
        for (int i = 0; i < 4; i++) {
            int j = i * 256 + t;
            cpa16(base + 16384 + j * 16, Wsrc + tb0 + (size_t)j * 16);
        }
    };

    const int w = t >> 5, lane = t & 31;
    const int wm = w >> 2, wn = w & 3;
    const int lr = lane & 7, gq = lane >> 3;
    int preA[4], rxA[4], preB[2], rxB[2];
    #pragma unroll
    for (int mf = 0; mf < 4; mf++) {
        int row = wm * 64 + mf * 16 + (gq & 1) * 8 + lr;
        preA[mf] = row * 128 + (gq >> 1) * 16;
        rxA[mf]  = (row & 7) << 4;
    }
    #pragma unroll
    for (int p = 0; p < 2; p++) {
        int n = wn * 32 + p * 16 + (gq >> 1) * 8 + lr;
        preB[p] = (n & 127) * 128 + (gq & 1) * 16;
        rxB[p]  = (n & 7) << 4;
    }

    float acc[4][4][4];
    #pragma unroll
    for (int i = 0; i < 4; i++)
        #pragma unroll
        for (int j = 0; j < 4; j++)
            #pragma unroll
            for (int e = 0; e < 4; e++) acc[i][j][e] = 0.f;

    // 3-stage prologue: 2 groups in flight
    issue(0, 0); CPCOMMIT();
    issue(1, 1); CPCOMMIT();
    int buf = 0, nbuf = 2;
    for (int it = 0; it < NIT; it++) {
        if (it + 1 < NIT) { CPWAIT1(); }     // stage it complete (≤1 newer pending)
        else              { CPWAIT0(); }
        __syncthreads();                      // all warps done computing stage it-1; stage it visible
        if (it + 2 < NIT) { issue(nbuf, it + 2); CPCOMMIT(); }
        uint32_t sA = sb + buf * STG, sW = sA + 16384;
        #pragma unroll
        for (int k16 = 0; k16 < 4; k16++) {
            int kb = k16 * 32;
            uint32_t a[4][4], bb[4][2];
            #pragma unroll
            for (int mf = 0; mf < 4; mf++) ldsm4(a[mf], sA + (uint32_t)((preA[mf] + kb) ^ rxA[mf]));
            #pragma unroll
            for (int p = 0; p < 2; p++) {
                uint32_t r[4];
                ldsm4(r, sW + (uint32_t)((preB[p] + kb) ^ rxB[p]));
                bb[2*p][0]=r[0]; bb[2*p][1]=r[1]; bb[2*p+1][0]=r[2]; bb[2*p+1][1]=r[3];
            }
            #pragma unroll
            for (int mf = 0; mf < 4; mf++)
                #pragma unroll
                for (int nf = 0; nf < 4; nf++) mma_h(acc[mf][nf], a[mf], bb[nf]);
        }
        buf = (buf == 2) ? 0 : buf + 1;
        nbuf = (nbuf == 2) ? 0 : nbuf + 1;
    }

    // epilogue: warp covers 64 rows x 32 cols
    #pragma unroll
    for (int mf = 0; mf < 4; mf++) {
        #pragma unroll
        for (int half = 0; half < 2; half++) {
            int row = wm * 64 + mf * 16 + (lane >> 2) + half * 8;
            if (IS_G1) {
                size_t base = (size_t)(prow0 + row) * HID + (bnb << 7);
                #pragma unroll
                for (int nf = 0; nf < 4; nf++) {
                    int n = wn * 32 + nf * 8 + (lane & 3) * 2;
                    float v0 = fmaxf(acc[mf][nf][half*2+0] + biasS[n],     0.f);
                    float v1 = fmaxf(acc[mf][nf][half*2+1] + biasS[n + 1], 0.f);
                    __half2 p = __floats2half2_rn(v0, v1);
                    *(uint32_t*)((char*)g_H + (base + n) * 2) = *reinterpret_cast<uint32_t*>(&p);
                }
            } else {
                int orig = rowS[row];
                if (orig >= 0) {
                    float* zp = g_Z + (size_t)orig * PROJ + (bnb << 7);
                    #pragma unroll
                    for (int nf = 0; nf < 4; nf++) {
                        int n = wn * 32 + nf * 8 + (lane & 3) * 2;
                        float2 v;
                        v.x = acc[mf][nf][half*2+0] + biasS[n];
                        v.y = acc[mf][nf][half*2+1] + biasS[n + 1];
                        *(float2*)(zp + n) = v;
                    }
                }
            }
        }
    }
}

// ---------- finalize: warp-per-row norm + logits; resets counters for next replay ----------
__global__ __launch_bounds__(256) void k_final(
    const float* __restrict__ x,
    const float* __restrict__ Wcn, const float* __restrict__ bcn,
    const float* __restrict__ Wco, const float* __restrict__ bco,
    float* __restrict__ out)
{
    if (blockIdx.x == 0 && threadIdx.x == 0) {
        g_cnt2[0] = 0; g_cnt2[1] = 0;
    }
    const int wid = threadIdx.x >> 5, lane = threadIdx.x & 31;
    const int row = blockIdx.x * 8 + wid;
    const bool nat = __ldg(x + (size_t)row * XLD + FEAT) > 0.5f;
    const float* __restrict__ Wc = nat ? Wcn : Wco;
    const float* __restrict__ bc = nat ? bcn : bco;
    const float* zr = g_Z + (size_t)row * PROJ;

    float4 zv[4];
    float ss = 0.f, l0 = 0.f, l1 = 0.f, l2 = 0.f;
    #pragma unroll
    for (int i = 0; i < 4; i++) {
        const int k = i * 128 + lane * 4;
        float4 z = __ldg((const float4*)(zr + k));
        zv[i] = z;
        ss += z.x*z.x + z.y*z.y + z.z*z.z + z.w*z.w;
        float r0 = fmaxf(z.x, 0.f), r1 = fmaxf(z.y, 0.f);
        float r2 = fmaxf(z.z, 0.f), r3 = fmaxf(z.w, 0.f);
        const float4 w0 = __ldg((const float4*)(Wc + k * 3));
        const float4 w1 = __ldg((const float4*)(Wc + k * 3 + 4));
        const float4 w2 = __ldg((const float4*)(Wc + k * 3 + 8));
        l0 += r0*w0.x + r1*w0.w + r2*w1.z + r3*w2.y;
        l1 += r0*w0.y + r1*w1.x + r2*w1.w + r3*w2.z;
        l2 += r0*w0.z + r1*w1.y + r2*w2.x + r3*w2.w;
    }
    #pragma unroll
    for (int o = 16; o > 0; o >>= 1) {
        ss += __shfl_xor_sync(0xFFFFFFFFu, ss, o);
        l0 += __shfl_xor_sync(0xFFFFFFFFu, l0, o);
        l1 += __shfl_xor_sync(0xFFFFFFFFu, l1, o);
        l2 += __shfl_xor_sync(0xFFFFFFFFu, l2, o);
    }
    if (lane == 0) {
        float* lg = out + (size_t)B_ * PROJ + (size_t)row * NOUT;
        lg[0] = l0 + bc[0]; lg[1] = l1 + bc[1]; lg[2] = l2 + bc[2];
    }
    const float inv = 1.f / fmaxf(sqrtf(ss), 1e-12f);
    float* op = out + (size_t)row * PROJ;
    #pragma unroll
    for (int i = 0; i < 4; i++) {
        float4 z = zv[i];
        z.x *= inv; z.y *= inv; z.z *= inv; z.w *= inv;
        *(float4*)(op + i * 128 + lane * 4) = z;
    }
}

// ---------- launcher ----------
extern "C" void kernel_launch(void* const* d_in, const int* in_sizes, int n_in,
                              void* d_out, int out_size) {
    const float* x   = (const float*)d_in[0];
    const float* W1n = (const float*)d_in[1];
    const float* b1n = (const float*)d_in[2];
    const float* W2n = (const float*)d_in[3];
    const float* b2n = (const float*)d_in[4];
    const float* Wcn = (const float*)d_in[5];
    const float* bcn = (const float*)d_in[6];
    const float* W1o = (const float*)d_in[7];
    const float* b1o = (const float*)d_in[8];
    const float* W2o = (const float*)d_in[9];
    const float* b2o = (const float*)d_in[10];
    const float* Wco = (const float*)d_in[11];
    const float* bco = (const float*)d_in[12];
    float* out = (float*)d_out;

    cudaFuncSetAttribute(gemm_mma<1>, cudaFuncAttributeMaxDynamicSharedMemorySize, 3*32768);
    cudaFuncSetAttribute(gemm_mma<0>, cudaFuncAttributeMaxDynamicSharedMemorySize, 3*32768);

    k_assign<<<B_ / 256, 256>>>(x);
    k_convA<<<APAD, 256>>>(x);
    prep_w<<<2304, 256>>>(W1n, W1o, W2n, W2o);

    gemm_mma<1><<<dim3(16, TILES_M), 256, 3*32768>>>(b1n, b1o);
    gemm_mma<0><<<dim3(4, TILES_M), 256, 3*32768>>>(b2n, b2o);

    k_final<<<B_ / 8, 256>>>(x, Wcn, bcn, Wco, bco, out);
}

// round 13
// speedup vs baseline: 9.8038x; 1.0084x over previous
#include <cuda_runtime.h>
#include <cuda_fp16.h>
#include <cstdint>

#define B_   32768
#define FEAT 4096
#define XLD  4097
#define HID  2048
#define PROJ 512
#define NOUT 3
#define APAD (B_ + 256)
#define TILES_M 258

// ---------- device scratch ----------
__device__ int g_cnt2[2];
__device__ int g_pos2row[APAD];
__device__ float g_Z[(size_t)B_ * PROJ];
__device__ __half g_A[(size_t)APAD * FEAT];      // fp16 x features, permuted rows (pad rows stay 0)
__device__ __half g_H[(size_t)APAD * HID];       // fp16 hidden
__device__ __half g_W1[(size_t)2 * 16 * 64 * 8192];   // fp16, [N][K] tile-linear SW128 (16KB tiles)
__device__ __half g_W2[(size_t)2 * 4 * 32 * 8192];

// ---------- helpers ----------
__device__ __forceinline__ uint32_t smem_u32(const void* p) {
    uint32_t a;
    asm("{ .reg .u64 t; cvta.to.shared.u64 t, %1; cvt.u32.u64 %0, t; }" : "=r"(a) : "l"(p));
    return a;
}
__device__ __forceinline__ void cpa16(uint32_t d, const void* s) {
    asm volatile("cp.async.cg.shared.global [%0], [%1], 16;" :: "r"(d), "l"(s));
}
#define CPCOMMIT() asm volatile("cp.async.commit_group;" ::: "memory")
#define CPWAIT0()  asm volatile("cp.async.wait_group 0;" ::: "memory")
#define CPWAIT1()  asm volatile("cp.async.wait_group 1;" ::: "memory")
__device__ __forceinline__ void ldsm4(uint32_t* r, uint32_t a) {
    asm volatile("ldmatrix.sync.aligned.m8n8.x4.shared.b16 {%0,%1,%2,%3}, [%4];"
                 : "=r"(r[0]), "=r"(r[1]), "=r"(r[2]), "=r"(r[3]) : "r"(a));
}
__device__ __forceinline__ void mma_h(float* c, const uint32_t* a, const uint32_t* b) {
    asm volatile("mma.sync.aligned.m16n8k16.row.col.f32.f16.f16.f32 "
                 "{%0,%1,%2,%3}, {%4,%5,%6,%7}, {%8,%9}, {%0,%1,%2,%3};"
                 : "+f"(c[0]), "+f"(c[1]), "+f"(c[2]), "+f"(c[3])
                 : "r"(a[0]), "r"(a[1]), "r"(a[2]), "r"(a[3]), "r"(b[0]), "r"(b[1]));
}

// ---------- fused partition + A convert: one block per original row ----------
// Thread 0: one atomic per row -> pos; all threads convert the row into g_A[pos].
// Pad positions are never written (zero since module load) -> GEMM sees zeros.
__global__ __launch_bounds__(256) void k_ac(const float* __restrict__ x) {
    const int r = blockIdx.x;
    const int t = threadIdx.x;
    __shared__ int sPos;

    // load features first (independent of pos; overlaps the atomic)
    const int m = r & 3;                        // row-uniform misalignment (XLD ≡ 1 mod 4)
    const float* base = x + (size_t)r * XLD + t * 16 - m;
    float f[20];
    float v[16];
    if (m == 0) {
        #pragma unroll
        for (int q = 0; q < 4; q++) *(float4*)(f + 4*q) = __ldg((const float4*)(base + 4*q));
        #pragma unroll
        for (int j = 0; j < 16; j++) v[j] = f[j];
    } else {
        // 5 aligned float4 cover [base, base+20); worst case (r=B_-1, t=255, m=3) ends exactly at x's end.
        #pragma unroll
        for (int q = 0; q < 5; q++) *(float4*)(f + 4*q) = __ldg((const float4*)(base + 4*q));
        if (m == 1) {
            #pragma unroll
            for (int j = 0; j < 16; j++) v[j] = f[j + 1];
        } else if (m == 2) {
            #pragma unroll
            for (int j = 0; j < 16; j++) v[j] = f[j + 2];
        } else {
            #pragma unroll
            for (int j = 0; j < 16; j++) v[j] = f[j + 3];
        }
    }

    if (t == 0) {
        bool nat = x[(size_t)r * XLD + FEAT] > 0.5f;
        int idx = atomicAdd(&g_cnt2[nat ? 0 : 1], 1);
        int pos = nat ? idx : (APAD - 1 - idx);
        g_pos2row[pos] = r;
        sPos = pos;
    }

    uint4 h0, h1;
    uint32_t* p0 = (uint32_t*)&h0;
    uint32_t* p1 = (uint32_t*)&h1;
    #pragma unroll
    for (int e = 0; e < 4; e++) {
        __half2 a = __floats2half2_rn(v[2*e],   v[2*e+1]);
        __half2 b = __floats2half2_rn(v[8+2*e], v[8+2*e+1]);
        p0[e] = *reinterpret_cast<uint32_t*>(&a);
        p1[e] = *reinterpret_cast<uint32_t*>(&b);
    }
    __syncthreads();
    size_t db = ((size_t)sPos * FEAT + t * 16) * 2;
    *(uint4*)((char*)g_A + db)      = h0;
    *(uint4*)((char*)g_A + db + 16) = h1;
}

// ---------- merged W prepack: fp32 [K][N] -> fp16, [N][K] tile-linear SW128 ----------
__global__ __launch_bounds__(256) void prep_w(
    const float* __restrict__ W1n, const float* __restrict__ W1o,
    const float* __restrict__ W2n, const float* __restrict__ W2o)
{
    int b = blockIdx.x, t = threadIdx.x;
    float rv[8][4];
    if (b < 2048) {
        int tid = b * 256 + t;
        int n = (tid & 511) * 4;
        int rest = tid >> 9;
        int ko = rest & 511, g = rest >> 9;
        const float* src = (g ? W1o : W1n) + (size_t)(ko * 8) * HID + n;
        #pragma unroll
        for (int j = 0; j < 8; j++)
            *(float4*)rv[j] = __ldg((const float4*)(src + (size_t)j * HID));
        int kt = ko >> 3, cb = ko & 7;
        int nt = n >> 7;
        size_t tb = ((size_t)(((g << 4) + nt) * 64 + kt)) << 14;
        #pragma unroll
        for (int c = 0; c < 4; c++) {
            uint4 hv;
            uint32_t* hp = (uint32_t*)&hv;
            #pragma unroll
            for (int e = 0; e < 4; e++) {
                __half2 p = __floats2half2_rn(rv[2*e][c], rv[2*e+1][c]);
                hp[e] = *reinterpret_cast<uint32_t*>(&p);
            }
            int rIn = (n + c) & 127;
            uint32_t sw = (uint32_t)(rIn * 128 + (cb << 4)) ^ ((uint32_t)(rIn & 7) << 4);
            *(uint4*)((char*)g_W1 + tb + sw) = hv;
        }
    } else {
        int tid = (b - 2048) * 256 + t;
        int n = (tid & 127) * 4;
        int rest = tid >> 7;
        int ko = rest & 255, g = rest >> 8;
        const float* src = (g ? W2o : W2n) + (size_t)(ko * 8) * PROJ + n;
        #pragma unroll
        for (int j = 0; j < 8; j++)
            *(float4*)rv[j] = __ldg((const float4*)(src + (size_t)j * PROJ));
        int kt = ko >> 3, cb = ko & 7;
        int nt = n >> 7;
        size_t tb = ((size_t)(((g << 2) + nt) * 32 + kt)) << 14;
        #pragma unroll
        for (int c = 0; c < 4; c++) {
            uint4 hv;
            uint32_t* hp = (uint32_t*)&hv;
            #pragma unroll
            for (int e = 0; e < 4; e++) {
                __half2 p = __floats2half2_rn(rv[2*e][c], rv[2*e+1][c]);
                hp[e] = *reinterpret_cast<uint32_t*>(&p);
            }
            int rIn = (n + c) & 127;
            uint32_t sw = (uint32_t)(rIn * 128 + (cb << 4)) ^ ((uint32_t)(rIn & 7) << 4);
            *(uint4*)((char*)g_W2 + tb + sw) = hv;
        }
    }
}

// ---------- GEMM: M128 x N128 CTA, warp tile 64x32, K-step 64, 3-stage pipeline, 2 CTAs/SM ----------
template <int IS_G1>
__global__ __launch_bounds__(256, 2) void gemm_mma(
    const float* __restrict__ bn_, const float* __restrict__ bo_)
{
    extern __shared__ char smc[];
    __shared__ float biasS[128];
    __shared__ int rowS[128];

    constexpr int STG  = 32768;                 // A 16K + W 16K per stage; 3 stages
    constexpr int NTB  = IS_G1 ? 16 : 4;
    constexpr int KTB  = IS_G1 ? 64 : 32;
    constexpr int NIT  = IS_G1 ? (FEAT/64) : (HID/64);
    const int n_nat = g_cnt2[0], n_oth = g_cnt2[1];
    const int nat_tiles = (n_nat + 127) >> 7;
    const int oth_start = (APAD - n_oth) >> 7;
    const int bm = blockIdx.y, bnb = blockIdx.x;
    int grp;
    if (bm < nat_tiles)       grp = 0;
    else if (bm >= oth_start) grp = 1;
    else return;
    const int prow0 = bm << 7;
    const int lo = grp ? (APAD - n_oth) : 0;
    const int hi = grp ? APAD : n_nat;

    const int t = threadIdx.x;
    const uint32_t sb = smem_u32(smc);
    const char* Asrc = IS_G1 ? (const char*)g_A : (const char*)g_H;
    const size_t rowE = IS_G1 ? FEAT : HID;
    const char* Wsrc = IS_G1 ? (const char*)g_W1 : (const char*)g_W2;

    auto issue = [&](int s, int it) {
        uint32_t base = sb + s * STG;
        #pragma unroll
        for (int i = 0; i < 4; i++) {
            int cid = i * 256 + t;
            int r = cid >> 3, c = cid & 7;
            uint32_t off = (uint32_t)((r * 128 + c * 16) ^ ((r & 7) << 4));
            size_t so = ((size_t)(prow0 + r) * rowE + it * 64 + c * 8) * 2;
            cpa16(base + off, Asrc + so);
        }
        size_t tb0 = ((size_t)((grp * NTB + bnb) * KTB + it)) << 14;
        #pragma unroll
        for (int i = 0; i < 4; i++) {
            int j = i * 256 + t;
            cpa16(base + 16384 + j * 16, Wsrc + tb0 + (size_t)j * 16);
        }
    };

    // prologue loads first (don't depend on biasS/rowS)
    issue(0, 0); CPCOMMIT();
    issue(1, 1); CPCOMMIT();

    if (t < 128) {
        biasS[t] = (grp ? bo_ : bn_)[(bnb << 7) + t];
        int pos = prow0 + t;
        rowS[t] = (pos >= lo && pos < hi) ? g_pos2row[pos] : -1;
    }
    // (first in-loop __syncthreads guards biasS/rowS)

    const int w = t >> 5, lane = t & 31;
    const int wm = w >> 2, wn = w & 3;
    const int lr = lane & 7, gq = lane >> 3;
    int preA[4], rxA[4], preB[2], rxB[2];
    #pragma unroll
    for (int mf = 0; mf < 4; mf++) {
        int row = wm * 64 + mf * 16 + (gq & 1) * 8 + lr;
        preA[mf] = row * 128 + (gq >> 1) * 16;
        rxA[mf]  = (row & 7) << 4;
    }
    #pragma unroll
    for (int p = 0; p < 2; p++) {
        int n = wn * 32 + p * 16 + (gq >> 1) * 8 + lr;
        preB[p] = (n & 127) * 128 + (gq & 1) * 16;
        rxB[p]  = (n & 7) << 4;
    }

    float acc[4][4][4];
    #pragma unroll
    for (int i = 0; i < 4; i++)
        #pragma unroll
        for (int j = 0; j < 4; j++)
            #pragma unroll
            for (int e = 0; e < 4; e++) acc[i][j][e] = 0.f;

    int buf = 0, nbuf = 2;
    for (int it = 0; it < NIT; it++) {
        if (it + 1 < NIT) { CPWAIT1(); }
        else              { CPWAIT0(); }
        __syncthreads();
        uint32_t sA = sb + buf * STG, sW = sA + 16384;

        // k16 = 0 first, then issue next stage (de-clusters cp.async from the ldsm burst)
        #pragma unroll
        for (int k16 = 0; k16 < 4; k16++) {
            int kb = k16 * 32;
            uint32_t a[4][4], bb[4][2];
            #pragma unroll
            for (int mf = 0; mf < 4; mf++) ldsm4(a[mf], sA + (uint32_t)((preA[mf] + kb) ^ rxA[mf]));
            #pragma unroll
            for (int p = 0; p < 2; p++) {
                uint32_t r[4];
                ldsm4(r, sW + (uint32_t)((preB[p] + kb) ^ rxB[p]));
                bb[2*p][0]=r[0]; bb[2*p][1]=r[1]; bb[2*p+1][0]=r[2]; bb[2*p+1][1]=r[3];
            }
            #pragma unroll
            for (int mf = 0; mf < 4; mf++)
                #pragma unroll
                for (int nf = 0; nf < 4; nf++) mma_h(acc[mf][nf], a[mf], bb[nf]);
            if (k16 == 0 && it + 2 < NIT) { issue(nbuf, it + 2); CPCOMMIT(); }
        }
        buf = (buf == 2) ? 0 : buf + 1;
        nbuf = (nbuf == 2) ? 0 : nbuf + 1;
    }

    // epilogue: warp covers 64 rows x 32 cols
    #pragma unroll
    for (int mf = 0; mf < 4; mf++) {
        #pragma unroll
        for (int half = 0; half < 2; half++) {
            int row = wm * 64 + mf * 16 + (lane >> 2) + half * 8;
            if (IS_G1) {
                size_t base = (size_t)(prow0 + row) * HID + (bnb << 7);
                #pragma unroll
                for (int nf = 0; nf < 4; nf++) {
                    int n = wn * 32 + nf * 8 + (lane & 3) * 2;
                    float v0 = fmaxf(acc[mf][nf][half*2+0] + biasS[n],     0.f);
                    float v1 = fmaxf(acc[mf][nf][half*2+1] + biasS[n + 1], 0.f);
                    __half2 p = __floats2half2_rn(v0, v1);
                    *(uint32_t*)((char*)g_H + (base + n) * 2) = *reinterpret_cast<uint32_t*>(&p);
                }
            } else {
                int orig = rowS[row];
                if (orig >= 0) {
                    float* zp = g_Z + (size_t)orig * PROJ + (bnb << 7);
                    #pragma unroll
                    for (int nf = 0; nf < 4; nf++) {
                        int n = wn * 32 + nf * 8 + (lane & 3) * 2;
                        float2 v;
                        v.x = acc[mf][nf][half*2+0] + biasS[n];
                        v.y = acc[mf][nf][half*2+1] + biasS[n + 1];
                        *(float2*)(zp + n) = v;
                    }
                }
            }
        }
    }
}

// ---------- finalize: warp-per-row norm + logits; resets counters for next replay ----------
__global__ __launch_bounds__(256) void k_final(
    const float* __restrict__ x,
    const float* __restrict__ Wcn, const float* __restrict__ bcn,
    const float* __restrict__ Wco, const float* __restrict__ bco,
    float* __restrict__ out)
{
    if (blockIdx.x == 0 && threadIdx.x == 0) {
        g_cnt2[0] = 0; g_cnt2[1] = 0;
    }
    const int wid = threadIdx.x >> 5, lane = threadIdx.x & 31;
    const int row = blockIdx.x * 8 + wid;
    const bool nat = __ldg(x + (size_t)row * XLD + FEAT) > 0.5f;
    const float* __restrict__ Wc = nat ? Wcn : Wco;
    const float* __restrict__ bc = nat ? bcn : bco;
    const float* zr = g_Z + (size_t)row * PROJ;

    float4 zv[4];
    float ss = 0.f, l0 = 0.f, l1 = 0.f, l2 = 0.f;
    #pragma unroll
    for (int i = 0; i < 4; i++) {
        const int k = i * 128 + lane * 4;
        float4 z = __ldg((const float4*)(zr + k));
        zv[i] = z;
        ss += z.x*z.x + z.y*z.y + z.z*z.z + z.w*z.w;
        float r0 = fmaxf(z.x, 0.f), r1 = fmaxf(z.y, 0.f);
        float r2 = fmaxf(z.z, 0.f), r3 = fmaxf(z.w, 0.f);
        const float4 w0 = __ldg((const float4*)(Wc + k * 3));
        const float4 w1 = __ldg((const float4*)(Wc + k * 3 + 4));
        const float4 w2 = __ldg((const float4*)(Wc + k * 3 + 8));
        l0 += r0*w0.x + r1*w0.w + r2*w1.z + r3*w2.y;
        l1 += r0*w0.y + r1*w1.x + r2*w1.w + r3*w2.z;
        l2 += r0*w0.z + r1*w1.y + r2*w2.x + r3*w2.w;
    }
    #pragma unroll
    for (int o = 16; o > 0; o >>= 1) {
        ss += __shfl_xor_sync(0xFFFFFFFFu, ss, o);
        l0 += __shfl_xor_sync(0xFFFFFFFFu, l0, o);
        l1 += __shfl_xor_sync(0xFFFFFFFFu, l1, o);
        l2 += __shfl_xor_sync(0xFFFFFFFFu, l2, o);
    }
    if (lane == 0) {
        float* lg = out + (size_t)B_ * PROJ + (size_t)row * NOUT;
        lg[0] = l0 + bc[0]; lg[1] = l1 + bc[1]; lg[2] = l2 + bc[2];
    }
    const float inv = 1.f / fmaxf(sqrtf(ss), 1e-12f);
    float* op = out + (size_t)row * PROJ;
    #pragma unroll
    for (int i = 0; i < 4; i++) {
        float4 z = zv[i];
        z.x *= inv; z.y *= inv; z.z *= inv; z.w *= inv;
        *(float4*)(op + i * 128 + lane * 4) = z;
    }
}

// ---------- launcher ----------
extern "C" void kernel_launch(void* const* d_in, const int* in_sizes, int n_in,
                              void* d_out, int out_size) {
    const float* x   = (const float*)d_in[0];
    const float* W1n = (const float*)d_in[1];
    const float* b1n = (const float*)d_in[2];
    const float* W2n = (const float*)d_in[3];
    const float* b2n = (const float*)d_in[4];
    const float* Wcn = (const float*)d_in[5];
    const float* bcn = (const float*)d_in[6];
    const float* W1o = (const float*)d_in[7];
    const float* b1o = (const float*)d_in[8];
    const float* W2o = (const float*)d_in[9];
    const float* b2o = (const float*)d_in[10];
    const float* Wco = (const float*)d_in[11];
    const float* bco = (const float*)d_in[12];
    float* out = (float*)d_out;

    cudaFuncSetAttribute(gemm_mma<1>, cudaFuncAttributeMaxDynamicSharedMemorySize, 3*32768);
    cudaFuncSetAttribute(gemm_mma<0>, cudaFuncAttributeMaxDynamicSharedMemorySize, 3*32768);

    k_ac<<<B_, 256>>>(x);
    prep_w<<<2304, 256>>>(W1n, W1o, W2n, W2o);

    gemm_mma<1><<<dim3(16, TILES_M), 256, 3*32768>>>(b1n, b1o);
    gemm_mma<0><<<dim3(4, TILES_M), 256, 3*32768>>>(b2n, b2o);

    k_final<<<B_ / 8, 256>>>(x, Wcn, bcn, Wco, bco, out);
}